// round 5
// baseline (speedup 1.0000x reference)
#include <cuda_runtime.h>
#include <cuda_bf16.h>
#include <stdint.h>

// ---------------- problem constants ----------------
#define NN   84
#define PP   3486
#define HSZ  2048
#define H2   1024
#define G3H  6144

// ---------------- device scratch ----------------
__device__ float g_gi[NN * G3H];
__device__ float g_gh[PP * G3H];      // GEMM outputs; reused as t / t2 later
__device__ float g_h [PP * HSZ];
__device__ float g_y [PP * HSZ];
__device__ double g_acc[6];
__device__ int   g_iu[PP];
__device__ int   g_ju[PP];
__device__ __nv_bfloat16 g_ahi[PP * HSZ];   // activation bf16 hi
__device__ __nv_bfloat16 g_alo[PP * HSZ];   // activation bf16 lo
__device__ __nv_bfloat16 g_bhi[G3H * HSZ];  // weight bf16 hi
__device__ __nv_bfloat16 g_blo[G3H * HSZ];  // weight bf16 lo

__device__ __forceinline__ float sigm(float x) { return 1.0f / (1.0f + expf(-x)); }

__device__ __forceinline__ void split_bf(float x, __nv_bfloat16& h, __nv_bfloat16& l) {
    h = __float2bfloat16(x);
    l = __float2bfloat16(x - __bfloat162float(h));
}

__device__ __forceinline__ uint32_t s2u(const void* p) {
    uint32_t a;
    asm("{ .reg .u64 t; cvta.to.shared.u64 t, %1; cvt.u32.u64 %0, t; }" : "=r"(a) : "l"(p));
    return a;
}

// ---------------- packed f32x2 helpers (for small f32 GEMM) ----------------
__device__ __forceinline__ unsigned long long pk2(float lo, float hi) {
    unsigned long long r;
    asm("mov.b64 %0, {%1, %2};" : "=l"(r) : "f"(lo), "f"(hi));
    return r;
}
__device__ __forceinline__ void fma2(unsigned long long& d,
                                     unsigned long long a, unsigned long long b) {
    asm("fma.rn.f32x2 %0, %1, %2, %0;" : "+l"(d) : "l"(a), "l"(b));
}
__device__ __forceinline__ float2 unpk2(unsigned long long v) {
    float lo, hi;
    asm("mov.b64 {%0, %1}, %2;" : "=f"(lo), "=f"(hi) : "l"(v));
    return make_float2(lo, hi);
}

// ---------------- init ----------------
__global__ void k_init() {
    int t = blockIdx.x * blockDim.x + threadIdx.x;
    if (t < 6) g_acc[t] = 0.0;
    if (t < NN * NN) {
        int i = t / NN, j = t % NN;
        if (j > i) {
            int p = i * (NN - 1) - i * (i - 1) / 2 + (j - i - 1);
            g_iu[p] = i;
            g_ju[p] = j;
        }
    }
}

// ---------------- f32 -> bf16 hi/lo convert ----------------
__global__ void k_conv(const float* __restrict__ in, __nv_bfloat16* __restrict__ hi,
                       __nv_bfloat16* __restrict__ lo, int n) {
    int i = blockIdx.x * blockDim.x + threadIdx.x;
    if (i < n) {
        __nv_bfloat16 h, l;
        split_bf(in[i], h, l);
        hi[i] = h;
        lo[i] = l;
    }
}

// ================= bf16x3 mma.sync GEMM =================
// C[M,N] = A[M,K] @ B[N,K]^T + bias (A,B given as bf16 hi/lo pairs).
// CTA 128x128, BK=32, 128 threads, warp grid 2(M) x 2(N), warp tile 64x64.
// 3-stage cp.async ring, ONE __syncthreads per K-tile iteration.
// SMEM: 4 matrices (Ahi,Alo,Bhi,Blo) x 128 rows x 80B (32 bf16 + 16B pad).
#define LDB         80
#define MAT_BYTES   (128 * LDB)       // 10240
#define STAGE_BYTES (4 * MAT_BYTES)   // 40960
#define NSTAGE      3
#define GSMEM       (NSTAGE * STAGE_BYTES)   // 122880

#define LDSM4(R, A) \
    asm volatile("ldmatrix.sync.aligned.m8n8.x4.shared.b16 {%0,%1,%2,%3}, [%4];" \
        : "=r"((R)[0]), "=r"((R)[1]), "=r"((R)[2]), "=r"((R)[3]) : "r"(A))
#define LDSM4P(R0, R1, A) \
    asm volatile("ldmatrix.sync.aligned.m8n8.x4.shared.b16 {%0,%1,%2,%3}, [%4];" \
        : "=r"((R0)[0]), "=r"((R0)[1]), "=r"((R1)[0]), "=r"((R1)[1]) : "r"(A))
#define MMA(D, Aa, Bb) \
    asm volatile("mma.sync.aligned.m16n8k16.row.col.f32.bf16.bf16.f32 " \
        "{%0,%1,%2,%3},{%4,%5,%6,%7},{%8,%9},{%0,%1,%2,%3};" \
        : "+f"((D)[0]), "+f"((D)[1]), "+f"((D)[2]), "+f"((D)[3]) \
        : "r"((Aa)[0]), "r"((Aa)[1]), "r"((Aa)[2]), "r"((Aa)[3]), \
          "r"((Bb)[0]), "r"((Bb)[1]))

__device__ __forceinline__ void g_issue(
    uint32_t sbase, int s,
    const __nv_bfloat16* Ahi, const __nv_bfloat16* Alo,
    const __nv_bfloat16* Bhi, const __nv_bfloat16* Blo,
    int m0, int n0, int M, int K, int kt, int tid)
{
    const __nv_bfloat16* bases[4] = {Ahi, Alo, Bhi, Blo};
#pragma unroll
    for (int i = 0; i < 16; i++) {
        int cid = tid + i * 128;       // 0..2047 16B chunks
        int mat = cid >> 9;            // 512 chunks per matrix
        int r   = (cid >> 2) & 127;
        int ch  = cid & 3;
        int row, sz;
        if (mat < 2) {
            row = m0 + r;
            sz  = (row < M) ? 16 : 0;
            if (row >= M) row = M - 1;
        } else {
            row = n0 + r;
            sz  = 16;
        }
        const __nv_bfloat16* gp = bases[mat] + (size_t)row * K + kt * 32 + ch * 8;
        uint32_t sa = sbase + s * STAGE_BYTES + mat * MAT_BYTES + r * LDB + ch * 16;
        asm volatile("cp.async.cg.shared.global [%0], [%1], 16, %2;"
                     :: "r"(sa), "l"(gp), "r"(sz));
    }
}

template <bool RELU, int SLOT>
__global__ __launch_bounds__(128)
void k_bgemm(const __nv_bfloat16* __restrict__ Ahi, const __nv_bfloat16* __restrict__ Alo,
             const __nv_bfloat16* __restrict__ Bhi, const __nv_bfloat16* __restrict__ Blo,
             const float* __restrict__ bias, float* __restrict__ C,
             int M, int N, int K)
{
    extern __shared__ char smem[];
    const uint32_t sbase = s2u(smem);
    const int tid  = threadIdx.x;
    const int wid  = tid >> 5;
    const int lane = tid & 31;
    const int m0 = blockIdx.y * 128;
    const int n0 = blockIdx.x * 128;
    const int wm = wid & 1;       // 2 warps in M -> 64 rows each
    const int wn = wid >> 1;      // 2 warps in N -> 64 cols each

    float acc[4][8][4];
#pragma unroll
    for (int a = 0; a < 4; a++)
#pragma unroll
        for (int b = 0; b < 8; b++)
#pragma unroll
            for (int c = 0; c < 4; c++) acc[a][b][c] = 0.f;

    const int NKT = K >> 5;

    // prologue: stages 0,1 <- tiles 0,1
    g_issue(sbase, 0, Ahi, Alo, Bhi, Blo, m0, n0, M, K, 0, tid);
    asm volatile("cp.async.commit_group;" ::: "memory");
    g_issue(sbase, 1, Ahi, Alo, Bhi, Blo, m0, n0, M, K, 1, tid);
    asm volatile("cp.async.commit_group;" ::: "memory");

    // ldmatrix lane addresses (within one matrix)
    const uint32_t a_lane = (uint32_t)((wm * 64 + (lane & 15)) * LDB + (lane >> 4) * 16);
    const uint32_t b_lane = (uint32_t)((wn * 64 + (lane >> 4) * 8 + (lane & 7)) * LDB
                                       + ((lane >> 3) & 1) * 16);

    for (int kt = 0; kt < NKT; kt++) {
        asm volatile("cp.async.wait_group 1;" ::: "memory");   // tile kt resident
        __syncthreads();                                       // stage (kt-1)%3 free
        const int snext = (kt + 2) % NSTAGE;
        if (kt + 2 < NKT)
            g_issue(sbase, snext, Ahi, Alo, Bhi, Blo, m0, n0, M, K, kt + 2, tid);
        asm volatile("cp.async.commit_group;" ::: "memory");

        const uint32_t sb = sbase + (kt % NSTAGE) * STAGE_BYTES;
#pragma unroll
        for (int k16 = 0; k16 < 2; k16++) {
            uint32_t ah[4][4], al[4][4];
#pragma unroll
            for (int mt = 0; mt < 4; mt++) {
                uint32_t aadr = sb + a_lane + mt * (16 * LDB) + k16 * 32;
                LDSM4(ah[mt], aadr);
                LDSM4(al[mt], aadr + MAT_BYTES);
            }
            uint32_t bh[8][2], bl[8][2];
#pragma unroll
            for (int ntb = 0; ntb < 8; ntb += 2) {
                uint32_t badr = sb + 2 * MAT_BYTES + b_lane + ntb * (8 * LDB) + k16 * 32;
                LDSM4P(bh[ntb], bh[ntb + 1], badr);
                LDSM4P(bl[ntb], bl[ntb + 1], badr + MAT_BYTES);
            }
#pragma unroll
            for (int mt = 0; mt < 4; mt++)
#pragma unroll
                for (int nt = 0; nt < 8; nt++) {
                    MMA(acc[mt][nt], ah[mt], bh[nt]);   // hi * hi
                    MMA(acc[mt][nt], ah[mt], bl[nt]);   // hi * lo
                    MMA(acc[mt][nt], al[mt], bh[nt]);   // lo * hi
                }
        }
    }

    // ---------------- epilogue ----------------
    double lsum = 0.0, lsq = 0.0;
    const int rb = m0 + wm * 64 + (lane >> 2);
    const int cb = n0 + wn * 64 + (lane & 3) * 2;
#pragma unroll
    for (int mt = 0; mt < 4; mt++) {
#pragma unroll
        for (int half = 0; half < 2; half++) {
            int r = rb + mt * 16 + half * 8;
            if (r < M) {
                float* crow = C + (size_t)r * N;
#pragma unroll
                for (int nt = 0; nt < 8; nt++) {
                    int c = cb + nt * 8;
                    float v0 = acc[mt][nt][half * 2]     + bias[c];
                    float v1 = acc[mt][nt][half * 2 + 1] + bias[c + 1];
                    if (RELU) { v0 = fmaxf(v0, 0.f); v1 = fmaxf(v1, 0.f); }
                    *(float2*)(crow + c) = make_float2(v0, v1);
                    if (SLOT >= 0) {
                        lsum += (double)v0 + (double)v1;
                        lsq  += (double)v0 * v0 + (double)v1 * v1;
                    }
                }
            }
        }
    }
    if (SLOT >= 0) {
#pragma unroll
        for (int off = 16; off; off >>= 1) {
            lsum += __shfl_down_sync(0xffffffffu, lsum, off);
            lsq  += __shfl_down_sync(0xffffffffu, lsq,  off);
        }
        if (lane == 0) {
            atomicAdd(&g_acc[SLOT * 2],     lsum);
            atomicAdd(&g_acc[SLOT * 2 + 1], lsq);
        }
    }
}

// ---------------- f32 SGEMM (small; GEMM1 only) ----------------
template <bool RELU, int SLOT>
__global__ __launch_bounds__(256)
void k_gemm(const float* __restrict__ A, const float* __restrict__ B,
            const float* __restrict__ bias, float* __restrict__ C,
            int M, int N, int K)
{
    __shared__ float As[16][132];
    __shared__ float Bs[16][132];
    const int tid = threadIdx.x;
    const int tx  = tid & 15;
    const int ty  = tid >> 4;
    const int m0  = blockIdx.y * 128;
    const int n0  = blockIdx.x * 128;

    unsigned long long acc[8][4];
#pragma unroll
    for (int i = 0; i < 8; i++)
#pragma unroll
        for (int j = 0; j < 4; j++) acc[i][j] = 0ULL;

    for (int kt = 0; kt < K; kt += 16) {
        __syncthreads();
#pragma unroll
        for (int q = 0; q < 2; q++) {
            int fi  = tid + q * 256;
            int row = fi >> 2;
            int kq  = fi & 3;
            float4 av = make_float4(0.f, 0.f, 0.f, 0.f);
            int gr = m0 + row;
            if (gr < M)
                av = *(const float4*)(A + (size_t)gr * K + kt + kq * 4);
            As[kq * 4 + 0][row] = av.x;
            As[kq * 4 + 1][row] = av.y;
            As[kq * 4 + 2][row] = av.z;
            As[kq * 4 + 3][row] = av.w;
            float4 bv = *(const float4*)(B + (size_t)(n0 + row) * K + kt + kq * 4);
            Bs[kq * 4 + 0][row] = bv.x;
            Bs[kq * 4 + 1][row] = bv.y;
            Bs[kq * 4 + 2][row] = bv.z;
            Bs[kq * 4 + 3][row] = bv.w;
        }
        __syncthreads();
#pragma unroll
        for (int kk = 0; kk < 16; kk++) {
            float4 a0 = *(const float4*)&As[kk][ty * 8];
            float4 a1 = *(const float4*)&As[kk][ty * 8 + 4];
            float4 b0 = *(const float4*)&Bs[kk][tx * 8];
            float4 b1 = *(const float4*)&Bs[kk][tx * 8 + 4];
            unsigned long long bp0 = pk2(b0.x, b0.y);
            unsigned long long bp1 = pk2(b0.z, b0.w);
            unsigned long long bp2 = pk2(b1.x, b1.y);
            unsigned long long bp3 = pk2(b1.z, b1.w);
            float av[8] = {a0.x, a0.y, a0.z, a0.w, a1.x, a1.y, a1.z, a1.w};
#pragma unroll
            for (int i = 0; i < 8; i++) {
                unsigned long long ap = pk2(av[i], av[i]);
                fma2(acc[i][0], ap, bp0);
                fma2(acc[i][1], ap, bp1);
                fma2(acc[i][2], ap, bp2);
                fma2(acc[i][3], ap, bp3);
            }
        }
    }
#pragma unroll
    for (int i = 0; i < 8; i++) {
        int r = m0 + ty * 8 + i;
        if (r < M) {
            float* crow = C + (size_t)r * N + n0 + tx * 8;
            const float* brow = bias + n0 + tx * 8;
#pragma unroll
            for (int j2 = 0; j2 < 4; j2++) {
                float2 v = unpk2(acc[i][j2]);
                float c0 = v.x + brow[j2 * 2];
                float c1 = v.y + brow[j2 * 2 + 1];
                if (RELU) { c0 = fmaxf(c0, 0.f); c1 = fmaxf(c1, 0.f); }
                crow[j2 * 2]     = c0;
                crow[j2 * 2 + 1] = c1;
            }
        }
    }
}

// ---------------- GRU elementwise combine (+ fused bf16 split) ----------------
template <int STEP, bool WF32>
__global__ void k_gru(const float* __restrict__ hin, float* __restrict__ hout,
                      __nv_bfloat16* __restrict__ ohi, __nv_bfloat16* __restrict__ olo)
{
    int idx = blockIdx.x * blockDim.x + threadIdx.x;
    if (idx >= PP * HSZ) return;
    int p = idx / HSZ;
    int j = idx - p * HSZ;
    int node = (STEP == 0) ? g_iu[p] : g_ju[p];
    const float* gi = g_gi + (size_t)node * G3H;
    const float* gh = g_gh + (size_t)p * G3H;
    float r = sigm(gi[j]            + gh[j]);
    float z = sigm(gi[j + HSZ]      + gh[j + HSZ]);
    float n = tanhf(gi[j + 2 * HSZ] + r * gh[j + 2 * HSZ]);
    float v = (1.0f - z) * n + z * hin[idx];
    if (WF32) hout[idx] = v;
    __nv_bfloat16 h, l;
    split_bf(v, h, l);
    ohi[idx] = h;
    olo[idx] = l;
}

// ---------------- full-tensor LayerNorm apply (+ fused bf16 split) ----------------
template <bool CONV>
__global__ void k_norm(float* __restrict__ buf, const float* __restrict__ w,
                       const float* __restrict__ b, int count, int slot,
                       __nv_bfloat16* __restrict__ ohi, __nv_bfloat16* __restrict__ olo)
{
    double sum = g_acc[slot * 2];
    double sq  = g_acc[slot * 2 + 1];
    double mu  = sum / (double)count;
    double var = sq / (double)count - mu * mu;
    float rs  = rsqrtf((float)var + 1e-5f);
    float fmu = (float)mu;
    for (int i = blockIdx.x * blockDim.x + threadIdx.x; i < count;
         i += gridDim.x * blockDim.x) {
        float v = (buf[i] - fmu) * rs * w[i] + b[i];
        if (CONV) {
            __nv_bfloat16 h, l;
            split_bf(v, h, l);
            ohi[i] = h;
            olo[i] = l;
        } else {
            buf[i] = v;
        }
    }
}

// ---------------- final dot + sigmoid + symmetric scatter ----------------
__global__ void k_out(const float* __restrict__ h3, const float* __restrict__ w4,
                      const float* __restrict__ b4, float* __restrict__ out)
{
    int w    = (blockIdx.x * blockDim.x + threadIdx.x) >> 5;
    int lane = threadIdx.x & 31;
    if (w >= NN * NN) return;
    int i = w / NN, j = w % NN;
    if (i == j) { if (lane == 0) out[w] = 0.f; return; }
    int i0 = min(i, j), j0 = max(i, j);
    int p = i0 * (NN - 1) - i0 * (i0 - 1) / 2 + (j0 - i0 - 1);
    const float* hr = h3 + (size_t)p * H2;
    float s = 0.f;
    for (int t = lane; t < H2; t += 32) s += hr[t] * w4[t];
#pragma unroll
    for (int off = 16; off; off >>= 1) s += __shfl_down_sync(0xffffffffu, s, off);
    if (lane == 0) out[w] = 1.0f / (1.0f + expf(-(s + b4[0])));
}

// ---------------- host launch ----------------
extern "C" void kernel_launch(void* const* d_in, const int* in_sizes, int n_in,
                              void* d_out, int out_size)
{
    const float* x    = (const float*)d_in[0];
    const float* hid  = (const float*)d_in[1];
    const float* Wih  = (const float*)d_in[2];
    const float* Whh  = (const float*)d_in[3];
    const float* bih  = (const float*)d_in[4];
    const float* bhh  = (const float*)d_in[5];
    const float* W1   = (const float*)d_in[6];
    const float* b1   = (const float*)d_in[7];
    const float* ln1w = (const float*)d_in[8];
    const float* ln1b = (const float*)d_in[9];
    const float* W2   = (const float*)d_in[10];
    const float* b2   = (const float*)d_in[11];
    const float* ln2w = (const float*)d_in[12];
    const float* ln2b = (const float*)d_in[13];
    const float* W3   = (const float*)d_in[14];
    const float* b3   = (const float*)d_in[15];
    const float* ln3w = (const float*)d_in[16];
    const float* ln3b = (const float*)d_in[17];
    const float* W4   = (const float*)d_in[18];
    const float* b4   = (const float*)d_in[19];
    float* out = (float*)d_out;

    float *p_gi, *p_gh, *p_h, *p_y;
    __nv_bfloat16 *p_ahi, *p_alo, *p_bhi, *p_blo;
    cudaGetSymbolAddress((void**)&p_gi,  g_gi);
    cudaGetSymbolAddress((void**)&p_gh,  g_gh);
    cudaGetSymbolAddress((void**)&p_h,   g_h);
    cudaGetSymbolAddress((void**)&p_y,   g_y);
    cudaGetSymbolAddress((void**)&p_ahi, g_ahi);
    cudaGetSymbolAddress((void**)&p_alo, g_alo);
    cudaGetSymbolAddress((void**)&p_bhi, g_bhi);
    cudaGetSymbolAddress((void**)&p_blo, g_blo);
    float* p_t  = p_gh;                    // [PP, H2]
    float* p_t2 = p_gh + (size_t)PP * H2;  // [PP, H2]

    cudaFuncSetAttribute(k_bgemm<false, -1>, cudaFuncAttributeMaxDynamicSharedMemorySize, GSMEM);
    cudaFuncSetAttribute(k_bgemm<true, 0>,   cudaFuncAttributeMaxDynamicSharedMemorySize, GSMEM);
    cudaFuncSetAttribute(k_bgemm<true, 1>,   cudaFuncAttributeMaxDynamicSharedMemorySize, GSMEM);
    cudaFuncSetAttribute(k_bgemm<true, 2>,   cudaFuncAttributeMaxDynamicSharedMemorySize, GSMEM);

    const int MB = (PP + 127) / 128;  // 28

    // 0) init
    k_init<<<(NN * NN + 255) / 256, 256>>>();

    // 1) gi_node = x @ Wih^T + bih  [84, 6144], K=64 (tiny, f32 path)
    k_gemm<false, -1><<<dim3(G3H / 128, 1), 256>>>(x, Wih, bih, p_gi, NN, G3H, 64);

    // 2) GRU step 1: gh = hid @ Whh^T + bhh, combine -> g_h (+ bf16 of h1)
    k_conv<<<(PP * HSZ + 255) / 256, 256>>>(hid, p_ahi, p_alo, PP * HSZ);
    k_conv<<<(G3H * HSZ + 255) / 256, 256>>>(Whh, p_bhi, p_blo, G3H * HSZ);
    k_bgemm<false, -1><<<dim3(G3H / 128, MB), 128, GSMEM>>>(
        p_ahi, p_alo, p_bhi, p_blo, bhh, p_gh, PP, G3H, HSZ);
    k_gru<0, true><<<(PP * HSZ + 255) / 256, 256>>>(hid, p_h, p_ahi, p_alo);

    // 3) GRU step 2: gh = h1 @ Whh^T + bhh, combine -> bf16 of h2
    k_bgemm<false, -1><<<dim3(G3H / 128, MB), 128, GSMEM>>>(
        p_ahi, p_alo, p_bhi, p_blo, bhh, p_gh, PP, G3H, HSZ);
    k_gru<1, false><<<(PP * HSZ + 255) / 256, 256>>>(p_h, p_h, p_ahi, p_alo);

    // 4) layer 1: relu(h2 @ W1^T + b1) -> g_y, LN stats fused; LN emits bf16 of y
    k_conv<<<(HSZ * HSZ + 255) / 256, 256>>>(W1, p_bhi, p_blo, HSZ * HSZ);
    k_bgemm<true, 0><<<dim3(HSZ / 128, MB), 128, GSMEM>>>(
        p_ahi, p_alo, p_bhi, p_blo, b1, p_y, PP, HSZ, HSZ);
    k_norm<true><<<2048, 256>>>(p_y, ln1w, ln1b, PP * HSZ, 0, p_ahi, p_alo);

    // 5) layer 2: relu(y @ W2^T + b2) -> t, LN emits bf16 of t
    k_conv<<<(H2 * HSZ + 255) / 256, 256>>>(W2, p_bhi, p_blo, H2 * HSZ);
    k_bgemm<true, 1><<<dim3(H2 / 128, MB), 128, GSMEM>>>(
        p_ahi, p_alo, p_bhi, p_blo, b2, p_t, PP, H2, HSZ);
    k_norm<true><<<2048, 256>>>(p_t, ln2w, ln2b, PP * H2, 1, p_ahi, p_alo);

    // 6) layer 3: relu(t @ W3^T + b3) -> t2, LN in place (f32 for k_out)
    k_conv<<<(H2 * H2 + 255) / 256, 256>>>(W3, p_bhi, p_blo, H2 * H2);
    k_bgemm<true, 2><<<dim3(H2 / 128, MB), 128, GSMEM>>>(
        p_ahi, p_alo, p_bhi, p_blo, b3, p_t2, PP, H2, H2);
    k_norm<false><<<2048, 256>>>(p_t2, ln3w, ln3b, PP * H2, 2, 0, 0);

    // 7) output
    k_out<<<(NN * NN * 32 + 255) / 256, 256>>>(p_t2, W4, b4, out);
}

// round 6
// speedup vs baseline: 1.0224x; 1.0224x over previous
#include <cuda_runtime.h>
#include <cuda_bf16.h>
#include <stdint.h>

// ---------------- problem constants ----------------
#define NN   84
#define PP   3486
#define HSZ  2048
#define H2   1024
#define G3H  6144

// ---------------- device scratch ----------------
__device__ float g_gi[NN * G3H];
__device__ float g_gh[PP * G3H];      // GEMM outputs; reused as t / t2 later
__device__ float g_h [PP * HSZ];
__device__ float g_y [PP * HSZ];
__device__ double g_acc[6];
__device__ int   g_iu[PP];
__device__ int   g_ju[PP];
__device__ __nv_bfloat16 g_ahi[PP * HSZ];   // activation bf16 hi
__device__ __nv_bfloat16 g_alo[PP * HSZ];   // activation bf16 lo
__device__ __nv_bfloat16 g_bhi[G3H * HSZ];  // weight bf16 hi
__device__ __nv_bfloat16 g_blo[G3H * HSZ];  // weight bf16 lo

__device__ __forceinline__ float sigm(float x) { return 1.0f / (1.0f + expf(-x)); }

__device__ __forceinline__ void split_bf(float x, __nv_bfloat16& h, __nv_bfloat16& l) {
    h = __float2bfloat16(x);
    l = __float2bfloat16(x - __bfloat162float(h));
}

__device__ __forceinline__ uint32_t s2u(const void* p) {
    uint32_t a;
    asm("{ .reg .u64 t; cvta.to.shared.u64 t, %1; cvt.u32.u64 %0, t; }" : "=r"(a) : "l"(p));
    return a;
}

// ---------------- packed f32x2 helpers (for small f32 GEMM) ----------------
__device__ __forceinline__ unsigned long long pk2(float lo, float hi) {
    unsigned long long r;
    asm("mov.b64 %0, {%1, %2};" : "=l"(r) : "f"(lo), "f"(hi));
    return r;
}
__device__ __forceinline__ void fma2(unsigned long long& d,
                                     unsigned long long a, unsigned long long b) {
    asm("fma.rn.f32x2 %0, %1, %2, %0;" : "+l"(d) : "l"(a), "l"(b));
}
__device__ __forceinline__ float2 unpk2(unsigned long long v) {
    float lo, hi;
    asm("mov.b64 {%0, %1}, %2;" : "=f"(lo), "=f"(hi) : "l"(v));
    return make_float2(lo, hi);
}

// ---------------- init ----------------
__global__ void k_init() {
    int t = blockIdx.x * blockDim.x + threadIdx.x;
    if (t < 6) g_acc[t] = 0.0;
    if (t < NN * NN) {
        int i = t / NN, j = t % NN;
        if (j > i) {
            int p = i * (NN - 1) - i * (i - 1) / 2 + (j - i - 1);
            g_iu[p] = i;
            g_ju[p] = j;
        }
    }
}

// ---------------- f32 -> bf16 hi/lo convert ----------------
__global__ void k_conv(const float* __restrict__ in, __nv_bfloat16* __restrict__ hi,
                       __nv_bfloat16* __restrict__ lo, int n) {
    int i = blockIdx.x * blockDim.x + threadIdx.x;
    if (i < n) {
        __nv_bfloat16 h, l;
        split_bf(in[i], h, l);
        hi[i] = h;
        lo[i] = l;
    }
}

// ================= bf16x3 mma.sync GEMM =================
// C[M,N] = A[M,K] @ B[N,K]^T + bias (A,B given as bf16 hi/lo pairs).
// CTA 256(M)x128(N), BK=32, 256 threads, warp grid 4(M) x 2(N), warp tile 64x64.
// 3-stage cp.async ring, ONE __syncthreads per K-tile iteration.
// Per-stage SMEM: Ahi(256x80) Alo(256x80) Bhi(128x80) Blo(128x80) = 61440 B.
#define LDB          80
#define MATA_BYTES   (256 * LDB)      // 20480
#define MATB_BYTES   (128 * LDB)      // 10240
#define OFF_B        (2 * MATA_BYTES) // 40960
#define STAGE_BYTES  (2 * MATA_BYTES + 2 * MATB_BYTES)  // 61440
#define NSTAGE       3
#define GSMEM        (NSTAGE * STAGE_BYTES)             // 184320

#define LDSM4(R, A) \
    asm volatile("ldmatrix.sync.aligned.m8n8.x4.shared.b16 {%0,%1,%2,%3}, [%4];" \
        : "=r"((R)[0]), "=r"((R)[1]), "=r"((R)[2]), "=r"((R)[3]) : "r"(A))
#define LDSM4P(R0, R1, A) \
    asm volatile("ldmatrix.sync.aligned.m8n8.x4.shared.b16 {%0,%1,%2,%3}, [%4];" \
        : "=r"((R0)[0]), "=r"((R0)[1]), "=r"((R1)[0]), "=r"((R1)[1]) : "r"(A))
#define MMA(D, Aa, Bb) \
    asm volatile("mma.sync.aligned.m16n8k16.row.col.f32.bf16.bf16.f32 " \
        "{%0,%1,%2,%3},{%4,%5,%6,%7},{%8,%9},{%0,%1,%2,%3};" \
        : "+f"((D)[0]), "+f"((D)[1]), "+f"((D)[2]), "+f"((D)[3]) \
        : "r"((Aa)[0]), "r"((Aa)[1]), "r"((Aa)[2]), "r"((Aa)[3]), \
          "r"((Bb)[0]), "r"((Bb)[1]))

__device__ __forceinline__ void g_issue(
    uint32_t sbase, int s,
    const __nv_bfloat16* Ahi, const __nv_bfloat16* Alo,
    const __nv_bfloat16* Bhi, const __nv_bfloat16* Blo,
    int m0, int n0, int M, int K, int kt, int tid)
{
    const uint32_t stg = sbase + s * STAGE_BYTES;
    // A matrices: cids 0..2047  (2 mats x 256 rows x 4 chunks)
#pragma unroll
    for (int i = 0; i < 8; i++) {
        int cid = tid + i * 256;
        int mat = cid >> 10;            // 0=Ahi 1=Alo
        int r   = (cid >> 2) & 255;
        int ch  = cid & 3;
        int row = m0 + r;
        int sz  = (row < M) ? 16 : 0;
        if (row >= M) row = M - 1;
        const __nv_bfloat16* gp = (mat ? Alo : Ahi) + (size_t)row * K + kt * 32 + ch * 8;
        uint32_t sa = stg + mat * MATA_BYTES + r * LDB + ch * 16;
        asm volatile("cp.async.cg.shared.global [%0], [%1], 16, %2;"
                     :: "r"(sa), "l"(gp), "r"(sz));
    }
    // B matrices: cids 0..1023  (2 mats x 128 rows x 4 chunks)
#pragma unroll
    for (int i = 0; i < 4; i++) {
        int cid = tid + i * 256;
        int mat = cid >> 9;             // 0=Bhi 1=Blo
        int r   = (cid >> 2) & 127;
        int ch  = cid & 3;
        const __nv_bfloat16* gp = (mat ? Blo : Bhi) + (size_t)(n0 + r) * K + kt * 32 + ch * 8;
        uint32_t sa = stg + OFF_B + mat * MATB_BYTES + r * LDB + ch * 16;
        asm volatile("cp.async.ca.shared.global [%0], [%1], 16;"
                     :: "r"(sa), "l"(gp));
    }
}

template <bool RELU, int SLOT>
__global__ __launch_bounds__(256)
void k_bgemm(const __nv_bfloat16* __restrict__ Ahi, const __nv_bfloat16* __restrict__ Alo,
             const __nv_bfloat16* __restrict__ Bhi, const __nv_bfloat16* __restrict__ Blo,
             const float* __restrict__ bias, float* __restrict__ C,
             int M, int N, int K)
{
    extern __shared__ char smem[];
    const uint32_t sbase = s2u(smem);
    const int tid  = threadIdx.x;
    const int wid  = tid >> 5;
    const int lane = tid & 31;
    const int m0 = blockIdx.y * 256;
    const int n0 = blockIdx.x * 128;
    const int wm = wid & 3;       // 4 warps in M -> 64 rows each
    const int wn = wid >> 2;      // 2 warps in N -> 64 cols each

    float acc[4][8][4];
#pragma unroll
    for (int a = 0; a < 4; a++)
#pragma unroll
        for (int b = 0; b < 8; b++)
#pragma unroll
            for (int c = 0; c < 4; c++) acc[a][b][c] = 0.f;

    const int NKT = K >> 5;

    g_issue(sbase, 0, Ahi, Alo, Bhi, Blo, m0, n0, M, K, 0, tid);
    asm volatile("cp.async.commit_group;" ::: "memory");
    g_issue(sbase, 1, Ahi, Alo, Bhi, Blo, m0, n0, M, K, 1, tid);
    asm volatile("cp.async.commit_group;" ::: "memory");

    const uint32_t a_lane = (uint32_t)((wm * 64 + (lane & 15)) * LDB + (lane >> 4) * 16);
    const uint32_t b_lane = (uint32_t)(OFF_B + (wn * 64 + (lane >> 4) * 8 + (lane & 7)) * LDB
                                       + ((lane >> 3) & 1) * 16);

    for (int kt = 0; kt < NKT; kt++) {
        asm volatile("cp.async.wait_group 1;" ::: "memory");   // tile kt resident
        __syncthreads();                                       // stage (kt-1)%3 free
        const int snext = (kt + 2) % NSTAGE;
        if (kt + 2 < NKT)
            g_issue(sbase, snext, Ahi, Alo, Bhi, Blo, m0, n0, M, K, kt + 2, tid);
        asm volatile("cp.async.commit_group;" ::: "memory");

        const uint32_t sb = sbase + (kt % NSTAGE) * STAGE_BYTES;
#pragma unroll
        for (int k16 = 0; k16 < 2; k16++) {
            uint32_t ah[4][4], al[4][4];
#pragma unroll
            for (int mt = 0; mt < 4; mt++) {
                uint32_t aadr = sb + a_lane + mt * (16 * LDB) + k16 * 32;
                LDSM4(ah[mt], aadr);
                LDSM4(al[mt], aadr + MATA_BYTES);
            }
            uint32_t bh[8][2], bl[8][2];
#pragma unroll
            for (int ntb = 0; ntb < 8; ntb += 2) {
                uint32_t badr = sb + b_lane + ntb * (8 * LDB) + k16 * 32;
                LDSM4P(bh[ntb], bh[ntb + 1], badr);
                LDSM4P(bl[ntb], bl[ntb + 1], badr + MATB_BYTES);
            }
#pragma unroll
            for (int mt = 0; mt < 4; mt++)
#pragma unroll
                for (int nt = 0; nt < 8; nt++) {
                    MMA(acc[mt][nt], ah[mt], bh[nt]);   // hi * hi
                    MMA(acc[mt][nt], ah[mt], bl[nt]);   // hi * lo
                    MMA(acc[mt][nt], al[mt], bh[nt]);   // lo * hi
                }
        }
    }

    // ---------------- epilogue ----------------
    double lsum = 0.0, lsq = 0.0;
    const int rb = m0 + wm * 64 + (lane >> 2);
    const int cb = n0 + wn * 64 + (lane & 3) * 2;
#pragma unroll
    for (int mt = 0; mt < 4; mt++) {
#pragma unroll
        for (int half = 0; half < 2; half++) {
            int r = rb + mt * 16 + half * 8;
            if (r < M) {
                float* crow = C + (size_t)r * N;
#pragma unroll
                for (int nt = 0; nt < 8; nt++) {
                    int c = cb + nt * 8;
                    float v0 = acc[mt][nt][half * 2]     + bias[c];
                    float v1 = acc[mt][nt][half * 2 + 1] + bias[c + 1];
                    if (RELU) { v0 = fmaxf(v0, 0.f); v1 = fmaxf(v1, 0.f); }
                    *(float2*)(crow + c) = make_float2(v0, v1);
                    if (SLOT >= 0) {
                        lsum += (double)v0 + (double)v1;
                        lsq  += (double)v0 * v0 + (double)v1 * v1;
                    }
                }
            }
        }
    }
    if (SLOT >= 0) {
#pragma unroll
        for (int off = 16; off; off >>= 1) {
            lsum += __shfl_down_sync(0xffffffffu, lsum, off);
            lsq  += __shfl_down_sync(0xffffffffu, lsq,  off);
        }
        if (lane == 0) {
            atomicAdd(&g_acc[SLOT * 2],     lsum);
            atomicAdd(&g_acc[SLOT * 2 + 1], lsq);
        }
    }
}

// ---------------- f32 SGEMM (small; GEMM1 only) ----------------
template <bool RELU, int SLOT>
__global__ __launch_bounds__(256)
void k_gemm(const float* __restrict__ A, const float* __restrict__ B,
            const float* __restrict__ bias, float* __restrict__ C,
            int M, int N, int K)
{
    __shared__ float As[16][132];
    __shared__ float Bs[16][132];
    const int tid = threadIdx.x;
    const int tx  = tid & 15;
    const int ty  = tid >> 4;
    const int m0  = blockIdx.y * 128;
    const int n0  = blockIdx.x * 128;

    unsigned long long acc[8][4];
#pragma unroll
    for (int i = 0; i < 8; i++)
#pragma unroll
        for (int j = 0; j < 4; j++) acc[i][j] = 0ULL;

    for (int kt = 0; kt < K; kt += 16) {
        __syncthreads();
#pragma unroll
        for (int q = 0; q < 2; q++) {
            int fi  = tid + q * 256;
            int row = fi >> 2;
            int kq  = fi & 3;
            float4 av = make_float4(0.f, 0.f, 0.f, 0.f);
            int gr = m0 + row;
            if (gr < M)
                av = *(const float4*)(A + (size_t)gr * K + kt + kq * 4);
            As[kq * 4 + 0][row] = av.x;
            As[kq * 4 + 1][row] = av.y;
            As[kq * 4 + 2][row] = av.z;
            As[kq * 4 + 3][row] = av.w;
            float4 bv = *(const float4*)(B + (size_t)(n0 + row) * K + kt + kq * 4);
            Bs[kq * 4 + 0][row] = bv.x;
            Bs[kq * 4 + 1][row] = bv.y;
            Bs[kq * 4 + 2][row] = bv.z;
            Bs[kq * 4 + 3][row] = bv.w;
        }
        __syncthreads();
#pragma unroll
        for (int kk = 0; kk < 16; kk++) {
            float4 a0 = *(const float4*)&As[kk][ty * 8];
            float4 a1 = *(const float4*)&As[kk][ty * 8 + 4];
            float4 b0 = *(const float4*)&Bs[kk][tx * 8];
            float4 b1 = *(const float4*)&Bs[kk][tx * 8 + 4];
            unsigned long long bp0 = pk2(b0.x, b0.y);
            unsigned long long bp1 = pk2(b0.z, b0.w);
            unsigned long long bp2 = pk2(b1.x, b1.y);
            unsigned long long bp3 = pk2(b1.z, b1.w);
            float av[8] = {a0.x, a0.y, a0.z, a0.w, a1.x, a1.y, a1.z, a1.w};
#pragma unroll
            for (int i = 0; i < 8; i++) {
                unsigned long long ap = pk2(av[i], av[i]);
                fma2(acc[i][0], ap, bp0);
                fma2(acc[i][1], ap, bp1);
                fma2(acc[i][2], ap, bp2);
                fma2(acc[i][3], ap, bp3);
            }
        }
    }
#pragma unroll
    for (int i = 0; i < 8; i++) {
        int r = m0 + ty * 8 + i;
        if (r < M) {
            float* crow = C + (size_t)r * N + n0 + tx * 8;
            const float* brow = bias + n0 + tx * 8;
#pragma unroll
            for (int j2 = 0; j2 < 4; j2++) {
                float2 v = unpk2(acc[i][j2]);
                float c0 = v.x + brow[j2 * 2];
                float c1 = v.y + brow[j2 * 2 + 1];
                if (RELU) { c0 = fmaxf(c0, 0.f); c1 = fmaxf(c1, 0.f); }
                crow[j2 * 2]     = c0;
                crow[j2 * 2 + 1] = c1;
            }
        }
    }
}

// ---------------- GRU elementwise combine (+ fused bf16 split) ----------------
template <int STEP, bool WF32>
__global__ void k_gru(const float* __restrict__ hin, float* __restrict__ hout,
                      __nv_bfloat16* __restrict__ ohi, __nv_bfloat16* __restrict__ olo)
{
    int idx = blockIdx.x * blockDim.x + threadIdx.x;
    if (idx >= PP * HSZ) return;
    int p = idx / HSZ;
    int j = idx - p * HSZ;
    int node = (STEP == 0) ? g_iu[p] : g_ju[p];
    const float* gi = g_gi + (size_t)node * G3H;
    const float* gh = g_gh + (size_t)p * G3H;
    float r = sigm(gi[j]            + gh[j]);
    float z = sigm(gi[j + HSZ]      + gh[j + HSZ]);
    float n = tanhf(gi[j + 2 * HSZ] + r * gh[j + 2 * HSZ]);
    float v = (1.0f - z) * n + z * hin[idx];
    if (WF32) hout[idx] = v;
    __nv_bfloat16 h, l;
    split_bf(v, h, l);
    ohi[idx] = h;
    olo[idx] = l;
}

// ---------------- full-tensor LayerNorm apply (+ fused bf16 split) ----------------
template <bool CONV>
__global__ void k_norm(float* __restrict__ buf, const float* __restrict__ w,
                       const float* __restrict__ b, int count, int slot,
                       __nv_bfloat16* __restrict__ ohi, __nv_bfloat16* __restrict__ olo)
{
    double sum = g_acc[slot * 2];
    double sq  = g_acc[slot * 2 + 1];
    double mu  = sum / (double)count;
    double var = sq / (double)count - mu * mu;
    float rs  = rsqrtf((float)var + 1e-5f);
    float fmu = (float)mu;
    for (int i = blockIdx.x * blockDim.x + threadIdx.x; i < count;
         i += gridDim.x * blockDim.x) {
        float v = (buf[i] - fmu) * rs * w[i] + b[i];
        if (CONV) {
            __nv_bfloat16 h, l;
            split_bf(v, h, l);
            ohi[i] = h;
            olo[i] = l;
        } else {
            buf[i] = v;
        }
    }
}

// ---------------- final dot + sigmoid + symmetric scatter ----------------
__global__ void k_out(const float* __restrict__ h3, const float* __restrict__ w4,
                      const float* __restrict__ b4, float* __restrict__ out)
{
    int w    = (blockIdx.x * blockDim.x + threadIdx.x) >> 5;
    int lane = threadIdx.x & 31;
    if (w >= NN * NN) return;
    int i = w / NN, j = w % NN;
    if (i == j) { if (lane == 0) out[w] = 0.f; return; }
    int i0 = min(i, j), j0 = max(i, j);
    int p = i0 * (NN - 1) - i0 * (i0 - 1) / 2 + (j0 - i0 - 1);
    const float* hr = h3 + (size_t)p * H2;
    float s = 0.f;
    for (int t = lane; t < H2; t += 32) s += hr[t] * w4[t];
#pragma unroll
    for (int off = 16; off; off >>= 1) s += __shfl_down_sync(0xffffffffu, s, off);
    if (lane == 0) out[w] = 1.0f / (1.0f + expf(-(s + b4[0])));
}

// ---------------- host launch ----------------
extern "C" void kernel_launch(void* const* d_in, const int* in_sizes, int n_in,
                              void* d_out, int out_size)
{
    const float* x    = (const float*)d_in[0];
    const float* hid  = (const float*)d_in[1];
    const float* Wih  = (const float*)d_in[2];
    const float* Whh  = (const float*)d_in[3];
    const float* bih  = (const float*)d_in[4];
    const float* bhh  = (const float*)d_in[5];
    const float* W1   = (const float*)d_in[6];
    const float* b1   = (const float*)d_in[7];
    const float* ln1w = (const float*)d_in[8];
    const float* ln1b = (const float*)d_in[9];
    const float* W2   = (const float*)d_in[10];
    const float* b2   = (const float*)d_in[11];
    const float* ln2w = (const float*)d_in[12];
    const float* ln2b = (const float*)d_in[13];
    const float* W3   = (const float*)d_in[14];
    const float* b3   = (const float*)d_in[15];
    const float* ln3w = (const float*)d_in[16];
    const float* ln3b = (const float*)d_in[17];
    const float* W4   = (const float*)d_in[18];
    const float* b4   = (const float*)d_in[19];
    float* out = (float*)d_out;

    float *p_gi, *p_gh, *p_h, *p_y;
    __nv_bfloat16 *p_ahi, *p_alo, *p_bhi, *p_blo;
    cudaGetSymbolAddress((void**)&p_gi,  g_gi);
    cudaGetSymbolAddress((void**)&p_gh,  g_gh);
    cudaGetSymbolAddress((void**)&p_h,   g_h);
    cudaGetSymbolAddress((void**)&p_y,   g_y);
    cudaGetSymbolAddress((void**)&p_ahi, g_ahi);
    cudaGetSymbolAddress((void**)&p_alo, g_alo);
    cudaGetSymbolAddress((void**)&p_bhi, g_bhi);
    cudaGetSymbolAddress((void**)&p_blo, g_blo);
    float* p_t  = p_gh;                    // [PP, H2]
    float* p_t2 = p_gh + (size_t)PP * H2;  // [PP, H2]

    cudaFuncSetAttribute(k_bgemm<false, -1>, cudaFuncAttributeMaxDynamicSharedMemorySize, GSMEM);
    cudaFuncSetAttribute(k_bgemm<true, 0>,   cudaFuncAttributeMaxDynamicSharedMemorySize, GSMEM);
    cudaFuncSetAttribute(k_bgemm<true, 1>,   cudaFuncAttributeMaxDynamicSharedMemorySize, GSMEM);
    cudaFuncSetAttribute(k_bgemm<true, 2>,   cudaFuncAttributeMaxDynamicSharedMemorySize, GSMEM);

    const int MB = (PP + 255) / 256;  // 14

    // 0) init
    k_init<<<(NN * NN + 255) / 256, 256>>>();

    // 1) gi_node = x @ Wih^T + bih  [84, 6144], K=64 (tiny, f32 path)
    k_gemm<false, -1><<<dim3(G3H / 128, 1), 256>>>(x, Wih, bih, p_gi, NN, G3H, 64);

    // 2) GRU step 1: gh = hid @ Whh^T + bhh, combine -> g_h (+ bf16 of h1)
    k_conv<<<(PP * HSZ + 255) / 256, 256>>>(hid, p_ahi, p_alo, PP * HSZ);
    k_conv<<<(G3H * HSZ + 255) / 256, 256>>>(Whh, p_bhi, p_blo, G3H * HSZ);
    k_bgemm<false, -1><<<dim3(G3H / 128, MB), 256, GSMEM>>>(
        p_ahi, p_alo, p_bhi, p_blo, bhh, p_gh, PP, G3H, HSZ);
    k_gru<0, true><<<(PP * HSZ + 255) / 256, 256>>>(hid, p_h, p_ahi, p_alo);

    // 3) GRU step 2: gh = h1 @ Whh^T + bhh, combine -> bf16 of h2
    k_bgemm<false, -1><<<dim3(G3H / 128, MB), 256, GSMEM>>>(
        p_ahi, p_alo, p_bhi, p_blo, bhh, p_gh, PP, G3H, HSZ);
    k_gru<1, false><<<(PP * HSZ + 255) / 256, 256>>>(p_h, p_h, p_ahi, p_alo);

    // 4) layer 1: relu(h2 @ W1^T + b1) -> g_y, LN stats fused; LN emits bf16 of y
    k_conv<<<(HSZ * HSZ + 255) / 256, 256>>>(W1, p_bhi, p_blo, HSZ * HSZ);
    k_bgemm<true, 0><<<dim3(HSZ / 128, MB), 256, GSMEM>>>(
        p_ahi, p_alo, p_bhi, p_blo, b1, p_y, PP, HSZ, HSZ);
    k_norm<true><<<2048, 256>>>(p_y, ln1w, ln1b, PP * HSZ, 0, p_ahi, p_alo);

    // 5) layer 2: relu(y @ W2^T + b2) -> t, LN emits bf16 of t
    k_conv<<<(H2 * HSZ + 255) / 256, 256>>>(W2, p_bhi, p_blo, H2 * HSZ);
    k_bgemm<true, 1><<<dim3(H2 / 128, MB), 256, GSMEM>>>(
        p_ahi, p_alo, p_bhi, p_blo, b2, p_t, PP, H2, HSZ);
    k_norm<true><<<2048, 256>>>(p_t, ln2w, ln2b, PP * H2, 1, p_ahi, p_alo);

    // 6) layer 3: relu(t @ W3^T + b3) -> t2, LN in place (f32 for k_out)
    k_conv<<<(H2 * H2 + 255) / 256, 256>>>(W3, p_bhi, p_blo, H2 * H2);
    k_bgemm<true, 2><<<dim3(H2 / 128, MB), 256, GSMEM>>>(
        p_ahi, p_alo, p_bhi, p_blo, b3, p_t2, PP, H2, H2);
    k_norm<false><<<2048, 256>>>(p_t2, ln3w, ln3b, PP * H2, 2, 0, 0);

    // 7) output
    k_out<<<(NN * NN * 32 + 255) / 256, 256>>>(p_t2, W4, b4, out);
}

// round 7
// speedup vs baseline: 1.3381x; 1.3087x over previous
#include <cuda_runtime.h>
#include <cuda_fp16.h>
#include <stdint.h>

// ---------------- problem constants ----------------
#define NN   84
#define PP   3486
#define HSZ  2048
#define H2   1024
#define G3H  6144

// ---------------- device scratch ----------------
__device__ float g_gi[NN * G3H];
__device__ float g_gh[PP * G3H];      // GEMM outputs; reused as t / t2 later
__device__ float g_h [PP * HSZ];
__device__ float g_y [PP * HSZ];
__device__ double g_acc[6];
__device__ int   g_iu[PP];
__device__ int   g_ju[PP];
__device__ __half g_ahi[PP * HSZ];    // activation fp16 (single precision level)
__device__ __half g_bhi[G3H * HSZ];   // weight fp16 hi
__device__ __half g_blo[G3H * HSZ];   // weight fp16 lo (residual)

__device__ __forceinline__ float sigm(float x) { return 1.0f / (1.0f + expf(-x)); }

__device__ __forceinline__ void split_h(float x, __half& h, __half& l) {
    h = __float2half_rn(x);
    l = __float2half_rn(x - __half2float(h));
}

__device__ __forceinline__ uint32_t s2u(const void* p) {
    uint32_t a;
    asm("{ .reg .u64 t; cvta.to.shared.u64 t, %1; cvt.u32.u64 %0, t; }" : "=r"(a) : "l"(p));
    return a;
}

// ---------------- packed f32x2 helpers (for small f32 GEMM) ----------------
__device__ __forceinline__ unsigned long long pk2(float lo, float hi) {
    unsigned long long r;
    asm("mov.b64 %0, {%1, %2};" : "=l"(r) : "f"(lo), "f"(hi));
    return r;
}
__device__ __forceinline__ void fma2(unsigned long long& d,
                                     unsigned long long a, unsigned long long b) {
    asm("fma.rn.f32x2 %0, %1, %2, %0;" : "+l"(d) : "l"(a), "l"(b));
}
__device__ __forceinline__ float2 unpk2(unsigned long long v) {
    float lo, hi;
    asm("mov.b64 {%0, %1}, %2;" : "=f"(lo), "=f"(hi) : "l"(v));
    return make_float2(lo, hi);
}

// ---------------- init ----------------
__global__ void k_init() {
    int t = blockIdx.x * blockDim.x + threadIdx.x;
    if (t < 6) g_acc[t] = 0.0;
    if (t < NN * NN) {
        int i = t / NN, j = t % NN;
        if (j > i) {
            int p = i * (NN - 1) - i * (i - 1) / 2 + (j - i - 1);
            g_iu[p] = i;
            g_ju[p] = j;
        }
    }
}

// ---------------- f32 -> fp16 converts ----------------
__global__ void k_convw(const float* __restrict__ in, __half* __restrict__ hi,
                        __half* __restrict__ lo, int n) {
    int i = blockIdx.x * blockDim.x + threadIdx.x;
    if (i < n) {
        __half h, l;
        split_h(in[i], h, l);
        hi[i] = h;
        lo[i] = l;
    }
}
__global__ void k_conva(const float* __restrict__ in, __half* __restrict__ hi, int n) {
    int i = blockIdx.x * blockDim.x + threadIdx.x;
    if (i < n) hi[i] = __float2half_rn(in[i]);
}

// ================= fp16 2-pass mma.sync GEMM =================
// C[M,N] = A[M,K] @ (Bhi+Blo)[N,K]^T + bias.  A single fp16, B split hi/lo.
// CTA 256(M)x128(N), BK=32, 256 threads, warp grid 4(M) x 2(N), warp tile 64x64.
// 4-stage cp.async ring, ONE __syncthreads per K-tile iteration.
// Per-stage SMEM: A(256x80) Bhi(128x80) Blo(128x80) = 40960 B.
#define LDB          80
#define MATA_BYTES   (256 * LDB)      // 20480
#define MATB_BYTES   (128 * LDB)      // 10240
#define OFF_B        MATA_BYTES       // 20480
#define STAGE_BYTES  (MATA_BYTES + 2 * MATB_BYTES)   // 40960
#define NSTAGE       4
#define GSMEM        (NSTAGE * STAGE_BYTES)          // 163840

#define LDSM4(R, A) \
    asm volatile("ldmatrix.sync.aligned.m8n8.x4.shared.b16 {%0,%1,%2,%3}, [%4];" \
        : "=r"((R)[0]), "=r"((R)[1]), "=r"((R)[2]), "=r"((R)[3]) : "r"(A))
#define LDSM4P(R0, R1, A) \
    asm volatile("ldmatrix.sync.aligned.m8n8.x4.shared.b16 {%0,%1,%2,%3}, [%4];" \
        : "=r"((R0)[0]), "=r"((R0)[1]), "=r"((R1)[0]), "=r"((R1)[1]) : "r"(A))
#define MMA(D, Aa, Bb) \
    asm volatile("mma.sync.aligned.m16n8k16.row.col.f32.f16.f16.f32 " \
        "{%0,%1,%2,%3},{%4,%5,%6,%7},{%8,%9},{%0,%1,%2,%3};" \
        : "+f"((D)[0]), "+f"((D)[1]), "+f"((D)[2]), "+f"((D)[3]) \
        : "r"((Aa)[0]), "r"((Aa)[1]), "r"((Aa)[2]), "r"((Aa)[3]), \
          "r"((Bb)[0]), "r"((Bb)[1]))

__device__ __forceinline__ void g_issue(
    uint32_t sbase, int s,
    const __half* Ahi, const __half* Bhi, const __half* Blo,
    int m0, int n0, int M, int K, int kt, int tid)
{
    const uint32_t stg = sbase + s * STAGE_BYTES;
    // A: 256 rows x 4 chunks = 1024 chunks
#pragma unroll
    for (int i = 0; i < 4; i++) {
        int cid = tid + i * 256;
        int r   = cid >> 2;
        int ch  = cid & 3;
        int row = m0 + r;
        int sz  = (row < M) ? 16 : 0;
        if (row >= M) row = M - 1;
        const __half* gp = Ahi + (size_t)row * K + kt * 32 + ch * 8;
        uint32_t sa = stg + r * LDB + ch * 16;
        asm volatile("cp.async.cg.shared.global [%0], [%1], 16, %2;"
                     :: "r"(sa), "l"(gp), "r"(sz));
    }
    // B: 2 mats x 128 rows x 4 chunks = 1024 chunks
#pragma unroll
    for (int i = 0; i < 4; i++) {
        int cid = tid + i * 256;
        int mat = cid >> 9;
        int r   = (cid >> 2) & 127;
        int ch  = cid & 3;
        const __half* gp = (mat ? Blo : Bhi) + (size_t)(n0 + r) * K + kt * 32 + ch * 8;
        uint32_t sa = stg + OFF_B + mat * MATB_BYTES + r * LDB + ch * 16;
        asm volatile("cp.async.ca.shared.global [%0], [%1], 16;"
                     :: "r"(sa), "l"(gp));
    }
}

template <bool RELU, int SLOT>
__global__ __launch_bounds__(256)
void k_bgemm(const __half* __restrict__ Ahi, const __half* __restrict__ Bhi,
             const __half* __restrict__ Blo,
             const float* __restrict__ bias, float* __restrict__ C,
             int M, int N, int K)
{
    extern __shared__ char smem[];
    const uint32_t sbase = s2u(smem);
    const int tid  = threadIdx.x;
    const int wid  = tid >> 5;
    const int lane = tid & 31;
    const int m0 = blockIdx.y * 256;
    const int n0 = blockIdx.x * 128;
    const int wm = wid & 3;       // 4 warps in M -> 64 rows each
    const int wn = wid >> 2;      // 2 warps in N -> 64 cols each

    float acc[4][8][4];
#pragma unroll
    for (int a = 0; a < 4; a++)
#pragma unroll
        for (int b = 0; b < 8; b++)
#pragma unroll
            for (int c = 0; c < 4; c++) acc[a][b][c] = 0.f;

    const int NKT = K >> 5;

    // prologue: stages 0..2 <- tiles 0..2
    g_issue(sbase, 0, Ahi, Bhi, Blo, m0, n0, M, K, 0, tid);
    asm volatile("cp.async.commit_group;" ::: "memory");
    g_issue(sbase, 1, Ahi, Bhi, Blo, m0, n0, M, K, 1, tid);
    asm volatile("cp.async.commit_group;" ::: "memory");
    g_issue(sbase, 2, Ahi, Bhi, Blo, m0, n0, M, K, 2, tid);
    asm volatile("cp.async.commit_group;" ::: "memory");

    const uint32_t a_lane = (uint32_t)((wm * 64 + (lane & 15)) * LDB + (lane >> 4) * 16);
    const uint32_t b_lane = (uint32_t)(OFF_B + (wn * 64 + (lane >> 4) * 8 + (lane & 7)) * LDB
                                       + ((lane >> 3) & 1) * 16);

    for (int kt = 0; kt < NKT; kt++) {
        asm volatile("cp.async.wait_group 2;" ::: "memory");   // tile kt resident
        __syncthreads();                                       // stage (kt-1)%4 free
        if (kt + 3 < NKT)
            g_issue(sbase, (kt + 3) % NSTAGE, Ahi, Bhi, Blo, m0, n0, M, K, kt + 3, tid);
        asm volatile("cp.async.commit_group;" ::: "memory");

        const uint32_t sb = sbase + (kt % NSTAGE) * STAGE_BYTES;
#pragma unroll
        for (int k16 = 0; k16 < 2; k16++) {
            uint32_t ah[4][4];
#pragma unroll
            for (int mt = 0; mt < 4; mt++) {
                uint32_t aadr = sb + a_lane + mt * (16 * LDB) + k16 * 32;
                LDSM4(ah[mt], aadr);
            }
            uint32_t bh[8][2], bl[8][2];
#pragma unroll
            for (int ntb = 0; ntb < 8; ntb += 2) {
                uint32_t badr = sb + b_lane + ntb * (8 * LDB) + k16 * 32;
                LDSM4P(bh[ntb], bh[ntb + 1], badr);
                LDSM4P(bl[ntb], bl[ntb + 1], badr + MATB_BYTES);
            }
#pragma unroll
            for (int mt = 0; mt < 4; mt++)
#pragma unroll
                for (int nt = 0; nt < 8; nt++) {
                    MMA(acc[mt][nt], ah[mt], bh[nt]);   // A * Bhi
                    MMA(acc[mt][nt], ah[mt], bl[nt]);   // A * Blo
                }
        }
    }

    // ---------------- epilogue ----------------
    double lsum = 0.0, lsq = 0.0;
    const int rb = m0 + wm * 64 + (lane >> 2);
    const int cb = n0 + wn * 64 + (lane & 3) * 2;
#pragma unroll
    for (int mt = 0; mt < 4; mt++) {
#pragma unroll
        for (int half = 0; half < 2; half++) {
            int r = rb + mt * 16 + half * 8;
            if (r < M) {
                float* crow = C + (size_t)r * N;
#pragma unroll
                for (int nt = 0; nt < 8; nt++) {
                    int c = cb + nt * 8;
                    float v0 = acc[mt][nt][half * 2]     + bias[c];
                    float v1 = acc[mt][nt][half * 2 + 1] + bias[c + 1];
                    if (RELU) { v0 = fmaxf(v0, 0.f); v1 = fmaxf(v1, 0.f); }
                    *(float2*)(crow + c) = make_float2(v0, v1);
                    if (SLOT >= 0) {
                        lsum += (double)v0 + (double)v1;
                        lsq  += (double)v0 * v0 + (double)v1 * v1;
                    }
                }
            }
        }
    }
    if (SLOT >= 0) {
#pragma unroll
        for (int off = 16; off; off >>= 1) {
            lsum += __shfl_down_sync(0xffffffffu, lsum, off);
            lsq  += __shfl_down_sync(0xffffffffu, lsq,  off);
        }
        if (lane == 0) {
            atomicAdd(&g_acc[SLOT * 2],     lsum);
            atomicAdd(&g_acc[SLOT * 2 + 1], lsq);
        }
    }
}

// ---------------- f32 SGEMM (small; GEMM1 only) ----------------
template <bool RELU, int SLOT>
__global__ __launch_bounds__(256)
void k_gemm(const float* __restrict__ A, const float* __restrict__ B,
            const float* __restrict__ bias, float* __restrict__ C,
            int M, int N, int K)
{
    __shared__ float As[16][132];
    __shared__ float Bs[16][132];
    const int tid = threadIdx.x;
    const int tx  = tid & 15;
    const int ty  = tid >> 4;
    const int m0  = blockIdx.y * 128;
    const int n0  = blockIdx.x * 128;

    unsigned long long acc[8][4];
#pragma unroll
    for (int i = 0; i < 8; i++)
#pragma unroll
        for (int j = 0; j < 4; j++) acc[i][j] = 0ULL;

    for (int kt = 0; kt < K; kt += 16) {
        __syncthreads();
#pragma unroll
        for (int q = 0; q < 2; q++) {
            int fi  = tid + q * 256;
            int row = fi >> 2;
            int kq  = fi & 3;
            float4 av = make_float4(0.f, 0.f, 0.f, 0.f);
            int gr = m0 + row;
            if (gr < M)
                av = *(const float4*)(A + (size_t)gr * K + kt + kq * 4);
            As[kq * 4 + 0][row] = av.x;
            As[kq * 4 + 1][row] = av.y;
            As[kq * 4 + 2][row] = av.z;
            As[kq * 4 + 3][row] = av.w;
            float4 bv = *(const float4*)(B + (size_t)(n0 + row) * K + kt + kq * 4);
            Bs[kq * 4 + 0][row] = bv.x;
            Bs[kq * 4 + 1][row] = bv.y;
            Bs[kq * 4 + 2][row] = bv.z;
            Bs[kq * 4 + 3][row] = bv.w;
        }
        __syncthreads();
#pragma unroll
        for (int kk = 0; kk < 16; kk++) {
            float4 a0 = *(const float4*)&As[kk][ty * 8];
            float4 a1 = *(const float4*)&As[kk][ty * 8 + 4];
            float4 b0 = *(const float4*)&Bs[kk][tx * 8];
            float4 b1 = *(const float4*)&Bs[kk][tx * 8 + 4];
            unsigned long long bp0 = pk2(b0.x, b0.y);
            unsigned long long bp1 = pk2(b0.z, b0.w);
            unsigned long long bp2 = pk2(b1.x, b1.y);
            unsigned long long bp3 = pk2(b1.z, b1.w);
            float av[8] = {a0.x, a0.y, a0.z, a0.w, a1.x, a1.y, a1.z, a1.w};
#pragma unroll
            for (int i = 0; i < 8; i++) {
                unsigned long long ap = pk2(av[i], av[i]);
                fma2(acc[i][0], ap, bp0);
                fma2(acc[i][1], ap, bp1);
                fma2(acc[i][2], ap, bp2);
                fma2(acc[i][3], ap, bp3);
            }
        }
    }
#pragma unroll
    for (int i = 0; i < 8; i++) {
        int r = m0 + ty * 8 + i;
        if (r < M) {
            float* crow = C + (size_t)r * N + n0 + tx * 8;
            const float* brow = bias + n0 + tx * 8;
#pragma unroll
            for (int j2 = 0; j2 < 4; j2++) {
                float2 v = unpk2(acc[i][j2]);
                float c0 = v.x + brow[j2 * 2];
                float c1 = v.y + brow[j2 * 2 + 1];
                if (RELU) { c0 = fmaxf(c0, 0.f); c1 = fmaxf(c1, 0.f); }
                crow[j2 * 2]     = c0;
                crow[j2 * 2 + 1] = c1;
            }
        }
    }
}

// ---------------- GRU elementwise combine (+ fused fp16 emit) ----------------
template <int STEP, bool WF32>
__global__ void k_gru(const float* __restrict__ hin, float* __restrict__ hout,
                      __half* __restrict__ ohi)
{
    int idx = blockIdx.x * blockDim.x + threadIdx.x;
    if (idx >= PP * HSZ) return;
    int p = idx / HSZ;
    int j = idx - p * HSZ;
    int node = (STEP == 0) ? g_iu[p] : g_ju[p];
    const float* gi = g_gi + (size_t)node * G3H;
    const float* gh = g_gh + (size_t)p * G3H;
    float r = sigm(gi[j]            + gh[j]);
    float z = sigm(gi[j + HSZ]      + gh[j + HSZ]);
    float n = tanhf(gi[j + 2 * HSZ] + r * gh[j + 2 * HSZ]);
    float v = (1.0f - z) * n + z * hin[idx];
    if (WF32) hout[idx] = v;
    ohi[idx] = __float2half_rn(v);
}

// ---------------- full-tensor LayerNorm apply (+ fused fp16 emit) ----------------
template <bool CONV>
__global__ void k_norm(float* __restrict__ buf, const float* __restrict__ w,
                       const float* __restrict__ b, int count, int slot,
                       __half* __restrict__ ohi)
{
    double sum = g_acc[slot * 2];
    double sq  = g_acc[slot * 2 + 1];
    double mu  = sum / (double)count;
    double var = sq / (double)count - mu * mu;
    float rs  = rsqrtf((float)var + 1e-5f);
    float fmu = (float)mu;
    for (int i = blockIdx.x * blockDim.x + threadIdx.x; i < count;
         i += gridDim.x * blockDim.x) {
        float v = (buf[i] - fmu) * rs * w[i] + b[i];
        if (CONV) ohi[i] = __float2half_rn(v);
        else      buf[i] = v;
    }
}

// ---------------- final dot + sigmoid + symmetric scatter ----------------
__global__ void k_out(const float* __restrict__ h3, const float* __restrict__ w4,
                      const float* __restrict__ b4, float* __restrict__ out)
{
    int w    = (blockIdx.x * blockDim.x + threadIdx.x) >> 5;
    int lane = threadIdx.x & 31;
    if (w >= NN * NN) return;
    int i = w / NN, j = w % NN;
    if (i == j) { if (lane == 0) out[w] = 0.f; return; }
    int i0 = min(i, j), j0 = max(i, j);
    int p = i0 * (NN - 1) - i0 * (i0 - 1) / 2 + (j0 - i0 - 1);
    const float* hr = h3 + (size_t)p * H2;
    float s = 0.f;
    for (int t = lane; t < H2; t += 32) s += hr[t] * w4[t];
#pragma unroll
    for (int off = 16; off; off >>= 1) s += __shfl_down_sync(0xffffffffu, s, off);
    if (lane == 0) out[w] = 1.0f / (1.0f + expf(-(s + b4[0])));
}

// ---------------- host launch ----------------
extern "C" void kernel_launch(void* const* d_in, const int* in_sizes, int n_in,
                              void* d_out, int out_size)
{
    const float* x    = (const float*)d_in[0];
    const float* hid  = (const float*)d_in[1];
    const float* Wih  = (const float*)d_in[2];
    const float* Whh  = (const float*)d_in[3];
    const float* bih  = (const float*)d_in[4];
    const float* bhh  = (const float*)d_in[5];
    const float* W1   = (const float*)d_in[6];
    const float* b1   = (const float*)d_in[7];
    const float* ln1w = (const float*)d_in[8];
    const float* ln1b = (const float*)d_in[9];
    const float* W2   = (const float*)d_in[10];
    const float* b2   = (const float*)d_in[11];
    const float* ln2w = (const float*)d_in[12];
    const float* ln2b = (const float*)d_in[13];
    const float* W3   = (const float*)d_in[14];
    const float* b3   = (const float*)d_in[15];
    const float* ln3w = (const float*)d_in[16];
    const float* ln3b = (const float*)d_in[17];
    const float* W4   = (const float*)d_in[18];
    const float* b4   = (const float*)d_in[19];
    float* out = (float*)d_out;

    float *p_gi, *p_gh, *p_h, *p_y;
    __half *p_ahi, *p_bhi, *p_blo;
    cudaGetSymbolAddress((void**)&p_gi,  g_gi);
    cudaGetSymbolAddress((void**)&p_gh,  g_gh);
    cudaGetSymbolAddress((void**)&p_h,   g_h);
    cudaGetSymbolAddress((void**)&p_y,   g_y);
    cudaGetSymbolAddress((void**)&p_ahi, g_ahi);
    cudaGetSymbolAddress((void**)&p_bhi, g_bhi);
    cudaGetSymbolAddress((void**)&p_blo, g_blo);
    float* p_t  = p_gh;                    // [PP, H2]
    float* p_t2 = p_gh + (size_t)PP * H2;  // [PP, H2]

    cudaFuncSetAttribute(k_bgemm<false, -1>, cudaFuncAttributeMaxDynamicSharedMemorySize, GSMEM);
    cudaFuncSetAttribute(k_bgemm<true, 0>,   cudaFuncAttributeMaxDynamicSharedMemorySize, GSMEM);
    cudaFuncSetAttribute(k_bgemm<true, 1>,   cudaFuncAttributeMaxDynamicSharedMemorySize, GSMEM);
    cudaFuncSetAttribute(k_bgemm<true, 2>,   cudaFuncAttributeMaxDynamicSharedMemorySize, GSMEM);

    const int MB = (PP + 255) / 256;  // 14

    // 0) init
    k_init<<<(NN * NN + 255) / 256, 256>>>();

    // 1) gi_node = x @ Wih^T + bih  [84, 6144], K=64 (tiny, f32 path)
    k_gemm<false, -1><<<dim3(G3H / 128, 1), 256>>>(x, Wih, bih, p_gi, NN, G3H, 64);

    // 2) GRU step 1: gh = hid @ Whh^T + bhh, combine -> g_h (+ fp16 of h1)
    k_conva<<<(PP * HSZ + 255) / 256, 256>>>(hid, p_ahi, PP * HSZ);
    k_convw<<<(G3H * HSZ + 255) / 256, 256>>>(Whh, p_bhi, p_blo, G3H * HSZ);
    k_bgemm<false, -1><<<dim3(G3H / 128, MB), 256, GSMEM>>>(
        p_ahi, p_bhi, p_blo, bhh, p_gh, PP, G3H, HSZ);
    k_gru<0, true><<<(PP * HSZ + 255) / 256, 256>>>(hid, p_h, p_ahi);

    // 3) GRU step 2: gh = h1 @ Whh^T + bhh, combine -> fp16 of h2
    k_bgemm<false, -1><<<dim3(G3H / 128, MB), 256, GSMEM>>>(
        p_ahi, p_bhi, p_blo, bhh, p_gh, PP, G3H, HSZ);
    k_gru<1, false><<<(PP * HSZ + 255) / 256, 256>>>(p_h, p_h, p_ahi);

    // 4) layer 1: relu(h2 @ W1^T + b1) -> g_y, LN stats fused; LN emits fp16 of y
    k_convw<<<(HSZ * HSZ + 255) / 256, 256>>>(W1, p_bhi, p_blo, HSZ * HSZ);
    k_bgemm<true, 0><<<dim3(HSZ / 128, MB), 256, GSMEM>>>(
        p_ahi, p_bhi, p_blo, b1, p_y, PP, HSZ, HSZ);
    k_norm<true><<<2048, 256>>>(p_y, ln1w, ln1b, PP * HSZ, 0, p_ahi);

    // 5) layer 2: relu(y @ W2^T + b2) -> t, LN emits fp16 of t
    k_convw<<<(H2 * HSZ + 255) / 256, 256>>>(W2, p_bhi, p_blo, H2 * HSZ);
    k_bgemm<true, 1><<<dim3(H2 / 128, MB), 256, GSMEM>>>(
        p_ahi, p_bhi, p_blo, b2, p_t, PP, H2, HSZ);
    k_norm<true><<<2048, 256>>>(p_t, ln2w, ln2b, PP * H2, 1, p_ahi);

    // 6) layer 3: relu(t @ W3^T + b3) -> t2, LN in place (f32 for k_out)
    k_convw<<<(H2 * H2 + 255) / 256, 256>>>(W3, p_bhi, p_blo, H2 * H2);
    k_bgemm<true, 2><<<dim3(H2 / 128, MB), 256, GSMEM>>>(
        p_ahi, p_bhi, p_blo, b3, p_t2, PP, H2, H2);
    k_norm<false><<<2048, 256>>>(p_t2, ln3w, ln3b, PP * H2, 2, 0);

    // 7) output
    k_out<<<(NN * NN * 32 + 255) / 256, 256>>>(p_t2, W4, b4, out);
}

// round 8
// speedup vs baseline: 1.4204x; 1.0615x over previous
#include <cuda_runtime.h>
#include <cuda_fp16.h>
#include <stdint.h>

// ---------------- problem constants ----------------
#define NN   84
#define PP   3486
#define HSZ  2048
#define H2   1024
#define G3H  6144

// ---------------- device scratch ----------------
__device__ float g_gi[NN * G3H];
__device__ float g_gh[PP * G3H];      // GEMM outputs; reused as t / t2 later
__device__ float g_h [PP * HSZ];
__device__ float g_y [PP * HSZ];
__device__ double g_acc[6];
__device__ int   g_iu[PP];
__device__ int   g_ju[PP];
__device__ __half g_ahi[PP * HSZ];    // activation fp16
__device__ __half g_bhi[G3H * HSZ];   // weight fp16 hi
__device__ __half g_blo[G3H * HSZ];   // weight fp16 lo (residual)

// fast, overflow-safe activations (adds ~1e-5 rel err; budget allows)
__device__ __forceinline__ float sigm_f(float x) {
    return 1.0f / (1.0f + __expf(-x));
}
__device__ __forceinline__ float tanh_f(float x) {
    float e = __expf(-2.0f * fabsf(x));      // in (0,1], no overflow
    float t = (1.0f - e) / (1.0f + e);
    return copysignf(t, x);
}

__device__ __forceinline__ void split_h(float x, __half& h, __half& l) {
    h = __float2half_rn(x);
    l = __float2half_rn(x - __half2float(h));
}

__device__ __forceinline__ uint32_t s2u(const void* p) {
    uint32_t a;
    asm("{ .reg .u64 t; cvta.to.shared.u64 t, %1; cvt.u32.u64 %0, t; }" : "=r"(a) : "l"(p));
    return a;
}

// ---------------- packed f32x2 helpers (for small f32 GEMM) ----------------
__device__ __forceinline__ unsigned long long pk2(float lo, float hi) {
    unsigned long long r;
    asm("mov.b64 %0, {%1, %2};" : "=l"(r) : "f"(lo), "f"(hi));
    return r;
}
__device__ __forceinline__ void fma2(unsigned long long& d,
                                     unsigned long long a, unsigned long long b) {
    asm("fma.rn.f32x2 %0, %1, %2, %0;" : "+l"(d) : "l"(a), "l"(b));
}
__device__ __forceinline__ float2 unpk2(unsigned long long v) {
    float lo, hi;
    asm("mov.b64 {%0, %1}, %2;" : "=f"(lo), "=f"(hi) : "l"(v));
    return make_float2(lo, hi);
}

// ---------------- init ----------------
__global__ void k_init() {
    int t = blockIdx.x * blockDim.x + threadIdx.x;
    if (t < 6) g_acc[t] = 0.0;
    if (t < NN * NN) {
        int i = t / NN, j = t % NN;
        if (j > i) {
            int p = i * (NN - 1) - i * (i - 1) / 2 + (j - i - 1);
            g_iu[p] = i;
            g_ju[p] = j;
        }
    }
}

// ---------------- vectorized f32 -> fp16 converts (4 elems/thread) ----------------
__global__ void k_convw(const float4* __restrict__ in, __half2* __restrict__ hi,
                        __half2* __restrict__ lo, int n4) {
    int i = blockIdx.x * blockDim.x + threadIdx.x;
    if (i >= n4) return;
    float4 v = in[i];
    __half h0, l0, h1, l1, h2, l2, h3, l3;
    split_h(v.x, h0, l0); split_h(v.y, h1, l1);
    split_h(v.z, h2, l2); split_h(v.w, h3, l3);
    hi[i * 2]     = __halves2half2(h0, h1);
    hi[i * 2 + 1] = __halves2half2(h2, h3);
    lo[i * 2]     = __halves2half2(l0, l1);
    lo[i * 2 + 1] = __halves2half2(l2, l3);
}
__global__ void k_conva(const float4* __restrict__ in, __half2* __restrict__ hi, int n4) {
    int i = blockIdx.x * blockDim.x + threadIdx.x;
    if (i >= n4) return;
    float4 v = in[i];
    hi[i * 2]     = __halves2half2(__float2half_rn(v.x), __float2half_rn(v.y));
    hi[i * 2 + 1] = __halves2half2(__float2half_rn(v.z), __float2half_rn(v.w));
}

// ================= fp16 2-pass mma.sync GEMM (unchanged from R6) =================
#define LDB          80
#define MATA_BYTES   (256 * LDB)
#define MATB_BYTES   (128 * LDB)
#define OFF_B        MATA_BYTES
#define STAGE_BYTES  (MATA_BYTES + 2 * MATB_BYTES)   // 40960
#define NSTAGE       4
#define GSMEM        (NSTAGE * STAGE_BYTES)          // 163840

#define LDSM4(R, A) \
    asm volatile("ldmatrix.sync.aligned.m8n8.x4.shared.b16 {%0,%1,%2,%3}, [%4];" \
        : "=r"((R)[0]), "=r"((R)[1]), "=r"((R)[2]), "=r"((R)[3]) : "r"(A))
#define LDSM4P(R0, R1, A) \
    asm volatile("ldmatrix.sync.aligned.m8n8.x4.shared.b16 {%0,%1,%2,%3}, [%4];" \
        : "=r"((R0)[0]), "=r"((R0)[1]), "=r"((R1)[0]), "=r"((R1)[1]) : "r"(A))
#define MMA(D, Aa, Bb) \
    asm volatile("mma.sync.aligned.m16n8k16.row.col.f32.f16.f16.f32 " \
        "{%0,%1,%2,%3},{%4,%5,%6,%7},{%8,%9},{%0,%1,%2,%3};" \
        : "+f"((D)[0]), "+f"((D)[1]), "+f"((D)[2]), "+f"((D)[3]) \
        : "r"((Aa)[0]), "r"((Aa)[1]), "r"((Aa)[2]), "r"((Aa)[3]), \
          "r"((Bb)[0]), "r"((Bb)[1]))

__device__ __forceinline__ void g_issue(
    uint32_t sbase, int s,
    const __half* Ahi, const __half* Bhi, const __half* Blo,
    int m0, int n0, int M, int K, int kt, int tid)
{
    const uint32_t stg = sbase + s * STAGE_BYTES;
#pragma unroll
    for (int i = 0; i < 4; i++) {
        int cid = tid + i * 256;
        int r   = cid >> 2;
        int ch  = cid & 3;
        int row = m0 + r;
        int sz  = (row < M) ? 16 : 0;
        if (row >= M) row = M - 1;
        const __half* gp = Ahi + (size_t)row * K + kt * 32 + ch * 8;
        uint32_t sa = stg + r * LDB + ch * 16;
        asm volatile("cp.async.cg.shared.global [%0], [%1], 16, %2;"
                     :: "r"(sa), "l"(gp), "r"(sz));
    }
#pragma unroll
    for (int i = 0; i < 4; i++) {
        int cid = tid + i * 256;
        int mat = cid >> 9;
        int r   = (cid >> 2) & 127;
        int ch  = cid & 3;
        const __half* gp = (mat ? Blo : Bhi) + (size_t)(n0 + r) * K + kt * 32 + ch * 8;
        uint32_t sa = stg + OFF_B + mat * MATB_BYTES + r * LDB + ch * 16;
        asm volatile("cp.async.ca.shared.global [%0], [%1], 16;"
                     :: "r"(sa), "l"(gp));
    }
}

template <bool RELU, int SLOT>
__global__ __launch_bounds__(256)
void k_bgemm(const __half* __restrict__ Ahi, const __half* __restrict__ Bhi,
             const __half* __restrict__ Blo,
             const float* __restrict__ bias, float* __restrict__ C,
             int M, int N, int K)
{
    extern __shared__ char smem[];
    const uint32_t sbase = s2u(smem);
    const int tid  = threadIdx.x;
    const int wid  = tid >> 5;
    const int lane = tid & 31;
    const int m0 = blockIdx.y * 256;
    const int n0 = blockIdx.x * 128;
    const int wm = wid & 3;
    const int wn = wid >> 2;

    float acc[4][8][4];
#pragma unroll
    for (int a = 0; a < 4; a++)
#pragma unroll
        for (int b = 0; b < 8; b++)
#pragma unroll
            for (int c = 0; c < 4; c++) acc[a][b][c] = 0.f;

    const int NKT = K >> 5;

    g_issue(sbase, 0, Ahi, Bhi, Blo, m0, n0, M, K, 0, tid);
    asm volatile("cp.async.commit_group;" ::: "memory");
    g_issue(sbase, 1, Ahi, Bhi, Blo, m0, n0, M, K, 1, tid);
    asm volatile("cp.async.commit_group;" ::: "memory");
    g_issue(sbase, 2, Ahi, Bhi, Blo, m0, n0, M, K, 2, tid);
    asm volatile("cp.async.commit_group;" ::: "memory");

    const uint32_t a_lane = (uint32_t)((wm * 64 + (lane & 15)) * LDB + (lane >> 4) * 16);
    const uint32_t b_lane = (uint32_t)(OFF_B + (wn * 64 + (lane >> 4) * 8 + (lane & 7)) * LDB
                                       + ((lane >> 3) & 1) * 16);

    for (int kt = 0; kt < NKT; kt++) {
        asm volatile("cp.async.wait_group 2;" ::: "memory");
        __syncthreads();
        if (kt + 3 < NKT)
            g_issue(sbase, (kt + 3) % NSTAGE, Ahi, Bhi, Blo, m0, n0, M, K, kt + 3, tid);
        asm volatile("cp.async.commit_group;" ::: "memory");

        const uint32_t sb = sbase + (kt % NSTAGE) * STAGE_BYTES;
#pragma unroll
        for (int k16 = 0; k16 < 2; k16++) {
            uint32_t ah[4][4];
#pragma unroll
            for (int mt = 0; mt < 4; mt++) {
                uint32_t aadr = sb + a_lane + mt * (16 * LDB) + k16 * 32;
                LDSM4(ah[mt], aadr);
            }
            uint32_t bh[8][2], bl[8][2];
#pragma unroll
            for (int ntb = 0; ntb < 8; ntb += 2) {
                uint32_t badr = sb + b_lane + ntb * (8 * LDB) + k16 * 32;
                LDSM4P(bh[ntb], bh[ntb + 1], badr);
                LDSM4P(bl[ntb], bl[ntb + 1], badr + MATB_BYTES);
            }
#pragma unroll
            for (int mt = 0; mt < 4; mt++)
#pragma unroll
                for (int nt = 0; nt < 8; nt++) {
                    MMA(acc[mt][nt], ah[mt], bh[nt]);
                    MMA(acc[mt][nt], ah[mt], bl[nt]);
                }
        }
    }

    double lsum = 0.0, lsq = 0.0;
    const int rb = m0 + wm * 64 + (lane >> 2);
    const int cb = n0 + wn * 64 + (lane & 3) * 2;
#pragma unroll
    for (int mt = 0; mt < 4; mt++) {
#pragma unroll
        for (int half = 0; half < 2; half++) {
            int r = rb + mt * 16 + half * 8;
            if (r < M) {
                float* crow = C + (size_t)r * N;
#pragma unroll
                for (int nt = 0; nt < 8; nt++) {
                    int c = cb + nt * 8;
                    float v0 = acc[mt][nt][half * 2]     + bias[c];
                    float v1 = acc[mt][nt][half * 2 + 1] + bias[c + 1];
                    if (RELU) { v0 = fmaxf(v0, 0.f); v1 = fmaxf(v1, 0.f); }
                    *(float2*)(crow + c) = make_float2(v0, v1);
                    if (SLOT >= 0) {
                        lsum += (double)v0 + (double)v1;
                        lsq  += (double)v0 * v0 + (double)v1 * v1;
                    }
                }
            }
        }
    }
    if (SLOT >= 0) {
#pragma unroll
        for (int off = 16; off; off >>= 1) {
            lsum += __shfl_down_sync(0xffffffffu, lsum, off);
            lsq  += __shfl_down_sync(0xffffffffu, lsq,  off);
        }
        if (lane == 0) {
            atomicAdd(&g_acc[SLOT * 2],     lsum);
            atomicAdd(&g_acc[SLOT * 2 + 1], lsq);
        }
    }
}

// ---------------- f32 SGEMM (small; GEMM1 only) ----------------
template <bool RELU, int SLOT>
__global__ __launch_bounds__(256)
void k_gemm(const float* __restrict__ A, const float* __restrict__ B,
            const float* __restrict__ bias, float* __restrict__ C,
            int M, int N, int K)
{
    __shared__ float As[16][132];
    __shared__ float Bs[16][132];
    const int tid = threadIdx.x;
    const int tx  = tid & 15;
    const int ty  = tid >> 4;
    const int m0  = blockIdx.y * 128;
    const int n0  = blockIdx.x * 128;

    unsigned long long acc[8][4];
#pragma unroll
    for (int i = 0; i < 8; i++)
#pragma unroll
        for (int j = 0; j < 4; j++) acc[i][j] = 0ULL;

    for (int kt = 0; kt < K; kt += 16) {
        __syncthreads();
#pragma unroll
        for (int q = 0; q < 2; q++) {
            int fi  = tid + q * 256;
            int row = fi >> 2;
            int kq  = fi & 3;
            float4 av = make_float4(0.f, 0.f, 0.f, 0.f);
            int gr = m0 + row;
            if (gr < M)
                av = *(const float4*)(A + (size_t)gr * K + kt + kq * 4);
            As[kq * 4 + 0][row] = av.x;
            As[kq * 4 + 1][row] = av.y;
            As[kq * 4 + 2][row] = av.z;
            As[kq * 4 + 3][row] = av.w;
            float4 bv = *(const float4*)(B + (size_t)(n0 + row) * K + kt + kq * 4);
            Bs[kq * 4 + 0][row] = bv.x;
            Bs[kq * 4 + 1][row] = bv.y;
            Bs[kq * 4 + 2][row] = bv.z;
            Bs[kq * 4 + 3][row] = bv.w;
        }
        __syncthreads();
#pragma unroll
        for (int kk = 0; kk < 16; kk++) {
            float4 a0 = *(const float4*)&As[kk][ty * 8];
            float4 a1 = *(const float4*)&As[kk][ty * 8 + 4];
            float4 b0 = *(const float4*)&Bs[kk][tx * 8];
            float4 b1 = *(const float4*)&Bs[kk][tx * 8 + 4];
            unsigned long long bp0 = pk2(b0.x, b0.y);
            unsigned long long bp1 = pk2(b0.z, b0.w);
            unsigned long long bp2 = pk2(b1.x, b1.y);
            unsigned long long bp3 = pk2(b1.z, b1.w);
            float av[8] = {a0.x, a0.y, a0.z, a0.w, a1.x, a1.y, a1.z, a1.w};
#pragma unroll
            for (int i = 0; i < 8; i++) {
                unsigned long long ap = pk2(av[i], av[i]);
                fma2(acc[i][0], ap, bp0);
                fma2(acc[i][1], ap, bp1);
                fma2(acc[i][2], ap, bp2);
                fma2(acc[i][3], ap, bp3);
            }
        }
    }
#pragma unroll
    for (int i = 0; i < 8; i++) {
        int r = m0 + ty * 8 + i;
        if (r < M) {
            float* crow = C + (size_t)r * N + n0 + tx * 8;
            const float* brow = bias + n0 + tx * 8;
#pragma unroll
            for (int j2 = 0; j2 < 4; j2++) {
                float2 v = unpk2(acc[i][j2]);
                float c0 = v.x + brow[j2 * 2];
                float c1 = v.y + brow[j2 * 2 + 1];
                if (RELU) { c0 = fmaxf(c0, 0.f); c1 = fmaxf(c1, 0.f); }
                crow[j2 * 2]     = c0;
                crow[j2 * 2 + 1] = c1;
            }
        }
    }
}

// ---------------- GRU elementwise combine, vectorized (4 elems/thread) ----------------
template <int STEP, bool WF32>
__global__ void k_gru(const float* __restrict__ hin, float* __restrict__ hout,
                      __half2* __restrict__ ohi)
{
    int idx = blockIdx.x * blockDim.x + threadIdx.x;       // over PP*HSZ/4
    if (idx >= PP * (HSZ / 4)) return;
    int p  = idx >> 9;                 // /(HSZ/4)=512
    int j4 = idx & 511;
    int j  = j4 * 4;
    int node = (STEP == 0) ? g_iu[p] : g_ju[p];
    const float* gi = g_gi + (size_t)node * G3H;
    const float* gh = g_gh + (size_t)p * G3H;

    float4 gir = *(const float4*)(gi + j);
    float4 giz = *(const float4*)(gi + j + HSZ);
    float4 gin = *(const float4*)(gi + j + 2 * HSZ);
    float4 ghr = *(const float4*)(gh + j);
    float4 ghz = *(const float4*)(gh + j + HSZ);
    float4 ghn = *(const float4*)(gh + j + 2 * HSZ);
    float4 hv  = *(const float4*)(hin + (size_t)p * HSZ + j);

    float o[4];
    {
        float r0 = sigm_f(gir.x + ghr.x), z0 = sigm_f(giz.x + ghz.x);
        o[0] = (1.f - z0) * tanh_f(gin.x + r0 * ghn.x) + z0 * hv.x;
        float r1 = sigm_f(gir.y + ghr.y), z1 = sigm_f(giz.y + ghz.y);
        o[1] = (1.f - z1) * tanh_f(gin.y + r1 * ghn.y) + z1 * hv.y;
        float r2 = sigm_f(gir.z + ghr.z), z2 = sigm_f(giz.z + ghz.z);
        o[2] = (1.f - z2) * tanh_f(gin.z + r2 * ghn.z) + z2 * hv.z;
        float r3 = sigm_f(gir.w + ghr.w), z3 = sigm_f(giz.w + ghz.w);
        o[3] = (1.f - z3) * tanh_f(gin.w + r3 * ghn.w) + z3 * hv.w;
    }
    if (WF32)
        *(float4*)(hout + (size_t)p * HSZ + j) = make_float4(o[0], o[1], o[2], o[3]);
    ohi[idx * 2]     = __halves2half2(__float2half_rn(o[0]), __float2half_rn(o[1]));
    ohi[idx * 2 + 1] = __halves2half2(__float2half_rn(o[2]), __float2half_rn(o[3]));
}

// ---------------- full-tensor LayerNorm apply, vectorized ----------------
template <bool CONV>
__global__ void k_norm(float* __restrict__ buf, const float* __restrict__ w,
                       const float* __restrict__ b, int count4, int slot,
                       __half2* __restrict__ ohi)
{
    double sum = g_acc[slot * 2];
    double sq  = g_acc[slot * 2 + 1];
    double cnt = (double)count4 * 4.0;
    double mu  = sum / cnt;
    double var = sq / cnt - mu * mu;
    float rs  = rsqrtf((float)var + 1e-5f);
    float fmu = (float)mu;
    for (int i = blockIdx.x * blockDim.x + threadIdx.x; i < count4;
         i += gridDim.x * blockDim.x) {
        float4 v = *(const float4*)(buf + i * 4);
        float4 ww = *(const float4*)(w + i * 4);
        float4 bb = *(const float4*)(b + i * 4);
        float o0 = (v.x - fmu) * rs * ww.x + bb.x;
        float o1 = (v.y - fmu) * rs * ww.y + bb.y;
        float o2 = (v.z - fmu) * rs * ww.z + bb.z;
        float o3 = (v.w - fmu) * rs * ww.w + bb.w;
        if (CONV) {
            ohi[i * 2]     = __halves2half2(__float2half_rn(o0), __float2half_rn(o1));
            ohi[i * 2 + 1] = __halves2half2(__float2half_rn(o2), __float2half_rn(o3));
        } else {
            *(float4*)(buf + i * 4) = make_float4(o0, o1, o2, o3);
        }
    }
}

// ---------------- final dot + sigmoid + symmetric scatter ----------------
__global__ void k_out(const float* __restrict__ h3, const float* __restrict__ w4,
                      const float* __restrict__ b4, float* __restrict__ out)
{
    int w    = (blockIdx.x * blockDim.x + threadIdx.x) >> 5;
    int lane = threadIdx.x & 31;
    if (w >= NN * NN) return;
    int i = w / NN, j = w % NN;
    if (i == j) { if (lane == 0) out[w] = 0.f; return; }
    int i0 = min(i, j), j0 = max(i, j);
    int p = i0 * (NN - 1) - i0 * (i0 - 1) / 2 + (j0 - i0 - 1);
    const float* hr = h3 + (size_t)p * H2;
    float s = 0.f;
#pragma unroll
    for (int t = 0; t < H2 / 128; t++) {           // 8 float4 per lane
        float4 a = *(const float4*)(hr + (t * 32 + lane) * 4);
        float4 b = *(const float4*)(w4 + (t * 32 + lane) * 4);
        s += a.x * b.x + a.y * b.y + a.z * b.z + a.w * b.w;
    }
#pragma unroll
    for (int off = 16; off; off >>= 1) s += __shfl_down_sync(0xffffffffu, s, off);
    if (lane == 0) out[w] = 1.0f / (1.0f + __expf(-(s + b4[0])));
}

// ---------------- host launch ----------------
extern "C" void kernel_launch(void* const* d_in, const int* in_sizes, int n_in,
                              void* d_out, int out_size)
{
    const float* x    = (const float*)d_in[0];
    const float* hid  = (const float*)d_in[1];
    const float* Wih  = (const float*)d_in[2];
    const float* Whh  = (const float*)d_in[3];
    const float* bih  = (const float*)d_in[4];
    const float* bhh  = (const float*)d_in[5];
    const float* W1   = (const float*)d_in[6];
    const float* b1   = (const float*)d_in[7];
    const float* ln1w = (const float*)d_in[8];
    const float* ln1b = (const float*)d_in[9];
    const float* W2   = (const float*)d_in[10];
    const float* b2   = (const float*)d_in[11];
    const float* ln2w = (const float*)d_in[12];
    const float* ln2b = (const float*)d_in[13];
    const float* W3   = (const float*)d_in[14];
    const float* b3   = (const float*)d_in[15];
    const float* ln3w = (const float*)d_in[16];
    const float* ln3b = (const float*)d_in[17];
    const float* W4   = (const float*)d_in[18];
    const float* b4   = (const float*)d_in[19];
    float* out = (float*)d_out;

    float *p_gi, *p_gh, *p_h, *p_y;
    __half *p_ahi, *p_bhi, *p_blo;
    cudaGetSymbolAddress((void**)&p_gi,  g_gi);
    cudaGetSymbolAddress((void**)&p_gh,  g_gh);
    cudaGetSymbolAddress((void**)&p_h,   g_h);
    cudaGetSymbolAddress((void**)&p_y,   g_y);
    cudaGetSymbolAddress((void**)&p_ahi, g_ahi);
    cudaGetSymbolAddress((void**)&p_bhi, g_bhi);
    cudaGetSymbolAddress((void**)&p_blo, g_blo);
    float* p_t  = p_gh;                    // [PP, H2]
    float* p_t2 = p_gh + (size_t)PP * H2;  // [PP, H2]

    cudaFuncSetAttribute(k_bgemm<false, -1>, cudaFuncAttributeMaxDynamicSharedMemorySize, GSMEM);
    cudaFuncSetAttribute(k_bgemm<true, 0>,   cudaFuncAttributeMaxDynamicSharedMemorySize, GSMEM);
    cudaFuncSetAttribute(k_bgemm<true, 1>,   cudaFuncAttributeMaxDynamicSharedMemorySize, GSMEM);
    cudaFuncSetAttribute(k_bgemm<true, 2>,   cudaFuncAttributeMaxDynamicSharedMemorySize, GSMEM);

    const int MB = (PP + 255) / 256;  // 14
    const int GRU_G = (PP * (HSZ / 4) + 255) / 256;

    // 0) init
    k_init<<<(NN * NN + 255) / 256, 256>>>();

    // 1) gi_node = x @ Wih^T + bih  [84, 6144], K=64 (tiny, f32 path)
    k_gemm<false, -1><<<dim3(G3H / 128, 1), 256>>>(x, Wih, bih, p_gi, NN, G3H, 64);

    // 2) GRU step 1
    k_conva<<<(PP * HSZ / 4 + 255) / 256, 256>>>((const float4*)hid, (__half2*)p_ahi, PP * HSZ / 4);
    k_convw<<<(G3H * HSZ / 4 + 255) / 256, 256>>>((const float4*)Whh, (__half2*)p_bhi,
                                                  (__half2*)p_blo, G3H * HSZ / 4);
    k_bgemm<false, -1><<<dim3(G3H / 128, MB), 256, GSMEM>>>(
        p_ahi, p_bhi, p_blo, bhh, p_gh, PP, G3H, HSZ);
    k_gru<0, true><<<GRU_G, 256>>>(hid, p_h, (__half2*)p_ahi);

    // 3) GRU step 2
    k_bgemm<false, -1><<<dim3(G3H / 128, MB), 256, GSMEM>>>(
        p_ahi, p_bhi, p_blo, bhh, p_gh, PP, G3H, HSZ);
    k_gru<1, false><<<GRU_G, 256>>>(p_h, p_h, (__half2*)p_ahi);

    // 4) layer 1 + LN (stats fused in GEMM epilogue; LN emits fp16)
    k_convw<<<(HSZ * HSZ / 4 + 255) / 256, 256>>>((const float4*)W1, (__half2*)p_bhi,
                                                  (__half2*)p_blo, HSZ * HSZ / 4);
    k_bgemm<true, 0><<<dim3(HSZ / 128, MB), 256, GSMEM>>>(
        p_ahi, p_bhi, p_blo, b1, p_y, PP, HSZ, HSZ);
    k_norm<true><<<2048, 256>>>(p_y, ln1w, ln1b, PP * HSZ / 4, 0, (__half2*)p_ahi);

    // 5) layer 2 + LN
    k_convw<<<(H2 * HSZ / 4 + 255) / 256, 256>>>((const float4*)W2, (__half2*)p_bhi,
                                                 (__half2*)p_blo, H2 * HSZ / 4);
    k_bgemm<true, 1><<<dim3(H2 / 128, MB), 256, GSMEM>>>(
        p_ahi, p_bhi, p_blo, b2, p_t, PP, H2, HSZ);
    k_norm<true><<<2048, 256>>>(p_t, ln2w, ln2b, PP * H2 / 4, 1, (__half2*)p_ahi);

    // 6) layer 3 + LN (in place f32 for k_out)
    k_convw<<<(H2 * H2 / 4 + 255) / 256, 256>>>((const float4*)W3, (__half2*)p_bhi,
                                                (__half2*)p_blo, H2 * H2 / 4);
    k_bgemm<true, 2><<<dim3(H2 / 128, MB), 256, GSMEM>>>(
        p_ahi, p_bhi, p_blo, b3, p_t2, PP, H2, H2);
    k_norm<false><<<2048, 256>>>(p_t2, ln3w, ln3b, PP * H2 / 4, 2, 0);

    // 7) output
    k_out<<<(NN * NN * 32 + 255) / 256, 256>>>(p_t2, W4, b4, out);
}

// round 9
// speedup vs baseline: 1.5230x; 1.0723x over previous
#include <cuda_runtime.h>
#include <cuda_fp16.h>
#include <stdint.h>

// ---------------- problem constants ----------------
#define NN   84
#define PP   3486
#define HSZ  2048
#define H2   1024
#define G3H  6144

// ---------------- device scratch ----------------
__device__ float g_gi[NN * G3H];
__device__ float g_gh[PP * G3H];      // GEMM outputs; reused as t / t2 later
__device__ float g_h [PP * HSZ];
__device__ float g_y [PP * HSZ];
__device__ double g_acc[6];
__device__ int   g_iu[PP];
__device__ int   g_ju[PP];
__device__ __half g_ahi[PP * HSZ];    // activation fp16
__device__ __half g_bhi[G3H * HSZ];   // weight fp16 hi
__device__ __half g_blo[G3H * HSZ];   // weight fp16 lo (residual)

// fast, overflow-safe activations
__device__ __forceinline__ float sigm_f(float x) {
    return 1.0f / (1.0f + __expf(-x));
}
__device__ __forceinline__ float tanh_f(float x) {
    float e = __expf(-2.0f * fabsf(x));
    float t = (1.0f - e) / (1.0f + e);
    return copysignf(t, x);
}

__device__ __forceinline__ void split_h(float x, __half& h, __half& l) {
    h = __float2half_rn(x);
    l = __float2half_rn(x - __half2float(h));
}

__device__ __forceinline__ uint32_t s2u(const void* p) {
    uint32_t a;
    asm("{ .reg .u64 t; cvta.to.shared.u64 t, %1; cvt.u32.u64 %0, t; }" : "=r"(a) : "l"(p));
    return a;
}

// ---------------- packed f32x2 helpers (for small f32 GEMM) ----------------
__device__ __forceinline__ unsigned long long pk2(float lo, float hi) {
    unsigned long long r;
    asm("mov.b64 %0, {%1, %2};" : "=l"(r) : "f"(lo), "f"(hi));
    return r;
}
__device__ __forceinline__ void fma2(unsigned long long& d,
                                     unsigned long long a, unsigned long long b) {
    asm("fma.rn.f32x2 %0, %1, %2, %0;" : "+l"(d) : "l"(a), "l"(b));
}
__device__ __forceinline__ float2 unpk2(unsigned long long v) {
    float lo, hi;
    asm("mov.b64 {%0, %1}, %2;" : "=f"(lo), "=f"(hi) : "l"(v));
    return make_float2(lo, hi);
}

// ---------------- init ----------------
__global__ void k_init() {
    int t = blockIdx.x * blockDim.x + threadIdx.x;
    if (t < 6) g_acc[t] = 0.0;
    if (t < NN * NN) {
        int i = t / NN, j = t % NN;
        if (j > i) {
            int p = i * (NN - 1) - i * (i - 1) / 2 + (j - i - 1);
            g_iu[p] = i;
            g_ju[p] = j;
        }
    }
}

// ---------------- vectorized f32 -> fp16 converts (4 elems/thread) ----------------
__global__ void k_convw(const float4* __restrict__ in, __half2* __restrict__ hi,
                        __half2* __restrict__ lo, int n4) {
    int i = blockIdx.x * blockDim.x + threadIdx.x;
    if (i >= n4) return;
    float4 v = in[i];
    __half h0, l0, h1, l1, h2, l2, h3, l3;
    split_h(v.x, h0, l0); split_h(v.y, h1, l1);
    split_h(v.z, h2, l2); split_h(v.w, h3, l3);
    hi[i * 2]     = __halves2half2(h0, h1);
    hi[i * 2 + 1] = __halves2half2(h2, h3);
    lo[i * 2]     = __halves2half2(l0, l1);
    lo[i * 2 + 1] = __halves2half2(l2, l3);
}
__global__ void k_conva(const float4* __restrict__ in, __half2* __restrict__ hi, int n4) {
    int i = blockIdx.x * blockDim.x + threadIdx.x;
    if (i >= n4) return;
    float4 v = in[i];
    hi[i * 2]     = __halves2half2(__float2half_rn(v.x), __float2half_rn(v.y));
    hi[i * 2 + 1] = __halves2half2(__float2half_rn(v.z), __float2half_rn(v.w));
}

// ================= fp16 2-pass mma.sync GEMM =================
// C[M,N] = A[M,K] @ (Bhi+Blo)[N,K]^T + bias.  A single fp16, B split hi/lo.
// CTA 128(M)x128(N), BK=32, 128 threads, warp grid 2(M) x 2(N), warp tile 64x64.
// 3-stage cp.async ring, ONE __syncthreads per K-tile iteration.
// Per-stage SMEM: A(128x80) Bhi(128x80) Blo(128x80) = 30720 B -> 2 CTAs/SM.
#define LDB          80
#define MAT_BYTES    (128 * LDB)      // 10240
#define OFF_B        MAT_BYTES        // 10240
#define STAGE_BYTES  (3 * MAT_BYTES)  // 30720
#define NSTAGE       3
#define GSMEM        (NSTAGE * STAGE_BYTES)   // 92160

#define LDSM4(R, A) \
    asm volatile("ldmatrix.sync.aligned.m8n8.x4.shared.b16 {%0,%1,%2,%3}, [%4];" \
        : "=r"((R)[0]), "=r"((R)[1]), "=r"((R)[2]), "=r"((R)[3]) : "r"(A))
#define LDSM4P(R0, R1, A) \
    asm volatile("ldmatrix.sync.aligned.m8n8.x4.shared.b16 {%0,%1,%2,%3}, [%4];" \
        : "=r"((R0)[0]), "=r"((R0)[1]), "=r"((R1)[0]), "=r"((R1)[1]) : "r"(A))
#define MMA(D, Aa, Bb) \
    asm volatile("mma.sync.aligned.m16n8k16.row.col.f32.f16.f16.f32 " \
        "{%0,%1,%2,%3},{%4,%5,%6,%7},{%8,%9},{%0,%1,%2,%3};" \
        : "+f"((D)[0]), "+f"((D)[1]), "+f"((D)[2]), "+f"((D)[3]) \
        : "r"((Aa)[0]), "r"((Aa)[1]), "r"((Aa)[2]), "r"((Aa)[3]), \
          "r"((Bb)[0]), "r"((Bb)[1]))

__device__ __forceinline__ void g_issue(
    uint32_t sbase, int s,
    const __half* Ahi, const __half* Bhi, const __half* Blo,
    int m0, int n0, int M, int K, int kt, int tid)
{
    const uint32_t stg = sbase + s * STAGE_BYTES;
    // A: 128 rows x 4 chunks = 512 chunks
#pragma unroll
    for (int i = 0; i < 4; i++) {
        int cid = tid + i * 128;
        int r   = cid >> 2;
        int ch  = cid & 3;
        int row = m0 + r;
        int sz  = (row < M) ? 16 : 0;
        if (row >= M) row = M - 1;
        const __half* gp = Ahi + (size_t)row * K + kt * 32 + ch * 8;
        uint32_t sa = stg + r * LDB + ch * 16;
        asm volatile("cp.async.cg.shared.global [%0], [%1], 16, %2;"
                     :: "r"(sa), "l"(gp), "r"(sz));
    }
    // B: 2 mats x 128 rows x 4 chunks = 1024 chunks
#pragma unroll
    for (int i = 0; i < 8; i++) {
        int cid = tid + i * 128;
        int mat = cid >> 9;
        int r   = (cid >> 2) & 127;
        int ch  = cid & 3;
        const __half* gp = (mat ? Blo : Bhi) + (size_t)(n0 + r) * K + kt * 32 + ch * 8;
        uint32_t sa = stg + OFF_B + mat * MAT_BYTES + r * LDB + ch * 16;
        asm volatile("cp.async.ca.shared.global [%0], [%1], 16;"
                     :: "r"(sa), "l"(gp));
    }
}

template <bool RELU, int SLOT>
__global__ __launch_bounds__(128)
void k_bgemm(const __half* __restrict__ Ahi, const __half* __restrict__ Bhi,
             const __half* __restrict__ Blo,
             const float* __restrict__ bias, float* __restrict__ C,
             int M, int N, int K)
{
    extern __shared__ char smem[];
    const uint32_t sbase = s2u(smem);
    const int tid  = threadIdx.x;
    const int wid  = tid >> 5;
    const int lane = tid & 31;
    const int m0 = blockIdx.y * 128;
    const int n0 = blockIdx.x * 128;
    const int wm = wid & 1;       // 2 warps in M -> 64 rows each
    const int wn = wid >> 1;      // 2 warps in N -> 64 cols each

    float acc[4][8][4];
#pragma unroll
    for (int a = 0; a < 4; a++)
#pragma unroll
        for (int b = 0; b < 8; b++)
#pragma unroll
            for (int c = 0; c < 4; c++) acc[a][b][c] = 0.f;

    const int NKT = K >> 5;

    // prologue: stages 0,1 <- tiles 0,1
    g_issue(sbase, 0, Ahi, Bhi, Blo, m0, n0, M, K, 0, tid);
    asm volatile("cp.async.commit_group;" ::: "memory");
    g_issue(sbase, 1, Ahi, Bhi, Blo, m0, n0, M, K, 1, tid);
    asm volatile("cp.async.commit_group;" ::: "memory");

    const uint32_t a_lane = (uint32_t)((wm * 64 + (lane & 15)) * LDB + (lane >> 4) * 16);
    const uint32_t b_lane = (uint32_t)(OFF_B + (wn * 64 + (lane >> 4) * 8 + (lane & 7)) * LDB
                                       + ((lane >> 3) & 1) * 16);

    for (int kt = 0; kt < NKT; kt++) {
        asm volatile("cp.async.wait_group 1;" ::: "memory");   // tile kt resident
        __syncthreads();                                       // stage (kt-1)%3 free
        if (kt + 2 < NKT)
            g_issue(sbase, (kt + 2) % NSTAGE, Ahi, Bhi, Blo, m0, n0, M, K, kt + 2, tid);
        asm volatile("cp.async.commit_group;" ::: "memory");

        const uint32_t sb = sbase + (kt % NSTAGE) * STAGE_BYTES;
#pragma unroll
        for (int k16 = 0; k16 < 2; k16++) {
            uint32_t ah[4][4];
#pragma unroll
            for (int mt = 0; mt < 4; mt++) {
                uint32_t aadr = sb + a_lane + mt * (16 * LDB) + k16 * 32;
                LDSM4(ah[mt], aadr);
            }
            uint32_t bh[8][2], bl[8][2];
#pragma unroll
            for (int ntb = 0; ntb < 8; ntb += 2) {
                uint32_t badr = sb + b_lane + ntb * (8 * LDB) + k16 * 32;
                LDSM4P(bh[ntb], bh[ntb + 1], badr);
                LDSM4P(bl[ntb], bl[ntb + 1], badr + MAT_BYTES);
            }
#pragma unroll
            for (int mt = 0; mt < 4; mt++)
#pragma unroll
                for (int nt = 0; nt < 8; nt++) {
                    MMA(acc[mt][nt], ah[mt], bh[nt]);   // A * Bhi
                    MMA(acc[mt][nt], ah[mt], bl[nt]);   // A * Blo
                }
        }
    }

    // ---------------- epilogue ----------------
    double lsum = 0.0, lsq = 0.0;
    const int rb = m0 + wm * 64 + (lane >> 2);
    const int cb = n0 + wn * 64 + (lane & 3) * 2;
#pragma unroll
    for (int mt = 0; mt < 4; mt++) {
#pragma unroll
        for (int half = 0; half < 2; half++) {
            int r = rb + mt * 16 + half * 8;
            if (r < M) {
                float* crow = C + (size_t)r * N;
#pragma unroll
                for (int nt = 0; nt < 8; nt++) {
                    int c = cb + nt * 8;
                    float v0 = acc[mt][nt][half * 2]     + bias[c];
                    float v1 = acc[mt][nt][half * 2 + 1] + bias[c + 1];
                    if (RELU) { v0 = fmaxf(v0, 0.f); v1 = fmaxf(v1, 0.f); }
                    *(float2*)(crow + c) = make_float2(v0, v1);
                    if (SLOT >= 0) {
                        lsum += (double)v0 + (double)v1;
                        lsq  += (double)v0 * v0 + (double)v1 * v1;
                    }
                }
            }
        }
    }
    if (SLOT >= 0) {
#pragma unroll
        for (int off = 16; off; off >>= 1) {
            lsum += __shfl_down_sync(0xffffffffu, lsum, off);
            lsq  += __shfl_down_sync(0xffffffffu, lsq,  off);
        }
        if (lane == 0) {
            atomicAdd(&g_acc[SLOT * 2],     lsum);
            atomicAdd(&g_acc[SLOT * 2 + 1], lsq);
        }
    }
}

// ---------------- f32 SGEMM (small; GEMM1 only) ----------------
template <bool RELU, int SLOT>
__global__ __launch_bounds__(256)
void k_gemm(const float* __restrict__ A, const float* __restrict__ B,
            const float* __restrict__ bias, float* __restrict__ C,
            int M, int N, int K)
{
    __shared__ float As[16][132];
    __shared__ float Bs[16][132];
    const int tid = threadIdx.x;
    const int tx  = tid & 15;
    const int ty  = tid >> 4;
    const int m0  = blockIdx.y * 128;
    const int n0  = blockIdx.x * 128;

    unsigned long long acc[8][4];
#pragma unroll
    for (int i = 0; i < 8; i++)
#pragma unroll
        for (int j = 0; j < 4; j++) acc[i][j] = 0ULL;

    for (int kt = 0; kt < K; kt += 16) {
        __syncthreads();
#pragma unroll
        for (int q = 0; q < 2; q++) {
            int fi  = tid + q * 256;
            int row = fi >> 2;
            int kq  = fi & 3;
            float4 av = make_float4(0.f, 0.f, 0.f, 0.f);
            int gr = m0 + row;
            if (gr < M)
                av = *(const float4*)(A + (size_t)gr * K + kt + kq * 4);
            As[kq * 4 + 0][row] = av.x;
            As[kq * 4 + 1][row] = av.y;
            As[kq * 4 + 2][row] = av.z;
            As[kq * 4 + 3][row] = av.w;
            float4 bv = *(const float4*)(B + (size_t)(n0 + row) * K + kt + kq * 4);
            Bs[kq * 4 + 0][row] = bv.x;
            Bs[kq * 4 + 1][row] = bv.y;
            Bs[kq * 4 + 2][row] = bv.z;
            Bs[kq * 4 + 3][row] = bv.w;
        }
        __syncthreads();
#pragma unroll
        for (int kk = 0; kk < 16; kk++) {
            float4 a0 = *(const float4*)&As[kk][ty * 8];
            float4 a1 = *(const float4*)&As[kk][ty * 8 + 4];
            float4 b0 = *(const float4*)&Bs[kk][tx * 8];
            float4 b1 = *(const float4*)&Bs[kk][tx * 8 + 4];
            unsigned long long bp0 = pk2(b0.x, b0.y);
            unsigned long long bp1 = pk2(b0.z, b0.w);
            unsigned long long bp2 = pk2(b1.x, b1.y);
            unsigned long long bp3 = pk2(b1.z, b1.w);
            float av[8] = {a0.x, a0.y, a0.z, a0.w, a1.x, a1.y, a1.z, a1.w};
#pragma unroll
            for (int i = 0; i < 8; i++) {
                unsigned long long ap = pk2(av[i], av[i]);
                fma2(acc[i][0], ap, bp0);
                fma2(acc[i][1], ap, bp1);
                fma2(acc[i][2], ap, bp2);
                fma2(acc[i][3], ap, bp3);
            }
        }
    }
#pragma unroll
    for (int i = 0; i < 8; i++) {
        int r = m0 + ty * 8 + i;
        if (r < M) {
            float* crow = C + (size_t)r * N + n0 + tx * 8;
            const float* brow = bias + n0 + tx * 8;
#pragma unroll
            for (int j2 = 0; j2 < 4; j2++) {
                float2 v = unpk2(acc[i][j2]);
                float c0 = v.x + brow[j2 * 2];
                float c1 = v.y + brow[j2 * 2 + 1];
                if (RELU) { c0 = fmaxf(c0, 0.f); c1 = fmaxf(c1, 0.f); }
                crow[j2 * 2]     = c0;
                crow[j2 * 2 + 1] = c1;
            }
        }
    }
}

// ---------------- GRU elementwise combine, vectorized (4 elems/thread) ----------------
template <int STEP, bool WF32>
__global__ void k_gru(const float* __restrict__ hin, float* __restrict__ hout,
                      __half2* __restrict__ ohi)
{
    int idx = blockIdx.x * blockDim.x + threadIdx.x;       // over PP*HSZ/4
    if (idx >= PP * (HSZ / 4)) return;
    int p  = idx >> 9;
    int j4 = idx & 511;
    int j  = j4 * 4;
    int node = (STEP == 0) ? g_iu[p] : g_ju[p];
    const float* gi = g_gi + (size_t)node * G3H;
    const float* gh = g_gh + (size_t)p * G3H;

    float4 gir = *(const float4*)(gi + j);
    float4 giz = *(const float4*)(gi + j + HSZ);
    float4 gin = *(const float4*)(gi + j + 2 * HSZ);
    float4 ghr = *(const float4*)(gh + j);
    float4 ghz = *(const float4*)(gh + j + HSZ);
    float4 ghn = *(const float4*)(gh + j + 2 * HSZ);
    float4 hv  = *(const float4*)(hin + (size_t)p * HSZ + j);

    float o[4];
    {
        float r0 = sigm_f(gir.x + ghr.x), z0 = sigm_f(giz.x + ghz.x);
        o[0] = (1.f - z0) * tanh_f(gin.x + r0 * ghn.x) + z0 * hv.x;
        float r1 = sigm_f(gir.y + ghr.y), z1 = sigm_f(giz.y + ghz.y);
        o[1] = (1.f - z1) * tanh_f(gin.y + r1 * ghn.y) + z1 * hv.y;
        float r2 = sigm_f(gir.z + ghr.z), z2 = sigm_f(giz.z + ghz.z);
        o[2] = (1.f - z2) * tanh_f(gin.z + r2 * ghn.z) + z2 * hv.z;
        float r3 = sigm_f(gir.w + ghr.w), z3 = sigm_f(giz.w + ghz.w);
        o[3] = (1.f - z3) * tanh_f(gin.w + r3 * ghn.w) + z3 * hv.w;
    }
    if (WF32)
        *(float4*)(hout + (size_t)p * HSZ + j) = make_float4(o[0], o[1], o[2], o[3]);
    ohi[idx * 2]     = __halves2half2(__float2half_rn(o[0]), __float2half_rn(o[1]));
    ohi[idx * 2 + 1] = __halves2half2(__float2half_rn(o[2]), __float2half_rn(o[3]));
}

// ---------------- full-tensor LayerNorm apply, vectorized ----------------
template <bool CONV>
__global__ void k_norm(float* __restrict__ buf, const float* __restrict__ w,
                       const float* __restrict__ b, int count4, int slot,
                       __half2* __restrict__ ohi)
{
    double sum = g_acc[slot * 2];
    double sq  = g_acc[slot * 2 + 1];
    double cnt = (double)count4 * 4.0;
    double mu  = sum / cnt;
    double var = sq / cnt - mu * mu;
    float rs  = rsqrtf((float)var + 1e-5f);
    float fmu = (float)mu;
    for (int i = blockIdx.x * blockDim.x + threadIdx.x; i < count4;
         i += gridDim.x * blockDim.x) {
        float4 v = *(const float4*)(buf + i * 4);
        float4 ww = *(const float4*)(w + i * 4);
        float4 bb = *(const float4*)(b + i * 4);
        float o0 = (v.x - fmu) * rs * ww.x + bb.x;
        float o1 = (v.y - fmu) * rs * ww.y + bb.y;
        float o2 = (v.z - fmu) * rs * ww.z + bb.z;
        float o3 = (v.w - fmu) * rs * ww.w + bb.w;
        if (CONV) {
            ohi[i * 2]     = __halves2half2(__float2half_rn(o0), __float2half_rn(o1));
            ohi[i * 2 + 1] = __halves2half2(__float2half_rn(o2), __float2half_rn(o3));
        } else {
            *(float4*)(buf + i * 4) = make_float4(o0, o1, o2, o3);
        }
    }
}

// ---------------- final dot + sigmoid + symmetric scatter ----------------
__global__ void k_out(const float* __restrict__ h3, const float* __restrict__ w4,
                      const float* __restrict__ b4, float* __restrict__ out)
{
    int w    = (blockIdx.x * blockDim.x + threadIdx.x) >> 5;
    int lane = threadIdx.x & 31;
    if (w >= NN * NN) return;
    int i = w / NN, j = w % NN;
    if (i == j) { if (lane == 0) out[w] = 0.f; return; }
    int i0 = min(i, j), j0 = max(i, j);
    int p = i0 * (NN - 1) - i0 * (i0 - 1) / 2 + (j0 - i0 - 1);
    const float* hr = h3 + (size_t)p * H2;
    float s = 0.f;
#pragma unroll
    for (int t = 0; t < H2 / 128; t++) {
        float4 a = *(const float4*)(hr + (t * 32 + lane) * 4);
        float4 b = *(const float4*)(w4 + (t * 32 + lane) * 4);
        s += a.x * b.x + a.y * b.y + a.z * b.z + a.w * b.w;
    }
#pragma unroll
    for (int off = 16; off; off >>= 1) s += __shfl_down_sync(0xffffffffu, s, off);
    if (lane == 0) out[w] = 1.0f / (1.0f + __expf(-(s + b4[0])));
}

// ---------------- host launch ----------------
extern "C" void kernel_launch(void* const* d_in, const int* in_sizes, int n_in,
                              void* d_out, int out_size)
{
    const float* x    = (const float*)d_in[0];
    const float* hid  = (const float*)d_in[1];
    const float* Wih  = (const float*)d_in[2];
    const float* Whh  = (const float*)d_in[3];
    const float* bih  = (const float*)d_in[4];
    const float* bhh  = (const float*)d_in[5];
    const float* W1   = (const float*)d_in[6];
    const float* b1   = (const float*)d_in[7];
    const float* ln1w = (const float*)d_in[8];
    const float* ln1b = (const float*)d_in[9];
    const float* W2   = (const float*)d_in[10];
    const float* b2   = (const float*)d_in[11];
    const float* ln2w = (const float*)d_in[12];
    const float* ln2b = (const float*)d_in[13];
    const float* W3   = (const float*)d_in[14];
    const float* b3   = (const float*)d_in[15];
    const float* ln3w = (const float*)d_in[16];
    const float* ln3b = (const float*)d_in[17];
    const float* W4   = (const float*)d_in[18];
    const float* b4   = (const float*)d_in[19];
    float* out = (float*)d_out;

    float *p_gi, *p_gh, *p_h, *p_y;
    __half *p_ahi, *p_bhi, *p_blo;
    cudaGetSymbolAddress((void**)&p_gi,  g_gi);
    cudaGetSymbolAddress((void**)&p_gh,  g_gh);
    cudaGetSymbolAddress((void**)&p_h,   g_h);
    cudaGetSymbolAddress((void**)&p_y,   g_y);
    cudaGetSymbolAddress((void**)&p_ahi, g_ahi);
    cudaGetSymbolAddress((void**)&p_bhi, g_bhi);
    cudaGetSymbolAddress((void**)&p_blo, g_blo);
    float* p_t  = p_gh;                    // [PP, H2]
    float* p_t2 = p_gh + (size_t)PP * H2;  // [PP, H2]

    cudaFuncSetAttribute(k_bgemm<false, -1>, cudaFuncAttributeMaxDynamicSharedMemorySize, GSMEM);
    cudaFuncSetAttribute(k_bgemm<true, 0>,   cudaFuncAttributeMaxDynamicSharedMemorySize, GSMEM);
    cudaFuncSetAttribute(k_bgemm<true, 1>,   cudaFuncAttributeMaxDynamicSharedMemorySize, GSMEM);
    cudaFuncSetAttribute(k_bgemm<true, 2>,   cudaFuncAttributeMaxDynamicSharedMemorySize, GSMEM);

    const int MB = (PP + 127) / 128;  // 28
    const int GRU_G = (PP * (HSZ / 4) + 255) / 256;

    // 0) init
    k_init<<<(NN * NN + 255) / 256, 256>>>();

    // 1) gi_node = x @ Wih^T + bih  [84, 6144], K=64 (tiny, f32 path)
    k_gemm<false, -1><<<dim3(G3H / 128, 1), 256>>>(x, Wih, bih, p_gi, NN, G3H, 64);

    // 2) GRU step 1
    k_conva<<<(PP * HSZ / 4 + 255) / 256, 256>>>((const float4*)hid, (__half2*)p_ahi, PP * HSZ / 4);
    k_convw<<<(G3H * HSZ / 4 + 255) / 256, 256>>>((const float4*)Whh, (__half2*)p_bhi,
                                                  (__half2*)p_blo, G3H * HSZ / 4);
    k_bgemm<false, -1><<<dim3(G3H / 128, MB), 128, GSMEM>>>(
        p_ahi, p_bhi, p_blo, bhh, p_gh, PP, G3H, HSZ);
    k_gru<0, true><<<GRU_G, 256>>>(hid, p_h, (__half2*)p_ahi);

    // 3) GRU step 2
    k_bgemm<false, -1><<<dim3(G3H / 128, MB), 128, GSMEM>>>(
        p_ahi, p_bhi, p_blo, bhh, p_gh, PP, G3H, HSZ);
    k_gru<1, false><<<GRU_G, 256>>>(p_h, p_h, (__half2*)p_ahi);

    // 4) layer 1 + LN (stats fused in GEMM epilogue; LN emits fp16)
    k_convw<<<(HSZ * HSZ / 4 + 255) / 256, 256>>>((const float4*)W1, (__half2*)p_bhi,
                                                  (__half2*)p_blo, HSZ * HSZ / 4);
    k_bgemm<true, 0><<<dim3(HSZ / 128, MB), 128, GSMEM>>>(
        p_ahi, p_bhi, p_blo, b1, p_y, PP, HSZ, HSZ);
    k_norm<true><<<2048, 256>>>(p_y, ln1w, ln1b, PP * HSZ / 4, 0, (__half2*)p_ahi);

    // 5) layer 2 + LN
    k_convw<<<(H2 * HSZ / 4 + 255) / 256, 256>>>((const float4*)W2, (__half2*)p_bhi,
                                                 (__half2*)p_blo, H2 * HSZ / 4);
    k_bgemm<true, 1><<<dim3(H2 / 128, MB), 128, GSMEM>>>(
        p_ahi, p_bhi, p_blo, b2, p_t, PP, H2, HSZ);
    k_norm<true><<<2048, 256>>>(p_t, ln2w, ln2b, PP * H2 / 4, 1, (__half2*)p_ahi);

    // 6) layer 3 + LN (in place f32 for k_out)
    k_convw<<<(H2 * H2 / 4 + 255) / 256, 256>>>((const float4*)W3, (__half2*)p_bhi,
                                                (__half2*)p_blo, H2 * H2 / 4);
    k_bgemm<true, 2><<<dim3(H2 / 128, MB), 128, GSMEM>>>(
        p_ahi, p_bhi, p_blo, b3, p_t2, PP, H2, H2);
    k_norm<false><<<2048, 256>>>(p_t2, ln3w, ln3b, PP * H2 / 4, 2, 0);

    // 7) output
    k_out<<<(NN * NN * 32 + 255) / 256, 256>>>(p_t2, W4, b4, out);
}

// round 10
// speedup vs baseline: 2.2161x; 1.4550x over previous
#include <cuda_runtime.h>
#include <cuda_fp16.h>
#include <stdint.h>

// ---------------- problem constants ----------------
#define NN   84
#define PP   3486
#define HSZ  2048
#define H2   1024
#define G3H  6144

// ---------------- device scratch ----------------
__device__ float g_gi[NN * G3H];
__device__ float g_gh[PP * G3H];      // GEMM outputs; reused as t / t2 later
__device__ float g_h [PP * HSZ];
__device__ float g_y [PP * HSZ];
__device__ double g_acc[6];
__device__ int   g_iu[PP];
__device__ int   g_ju[PP];
__device__ __half g_ahi[PP * HSZ];    // activation fp16
__device__ __half g_bhi[G3H * HSZ];   // weight fp16 hi
__device__ __half g_blo[G3H * HSZ];   // weight fp16 lo (residual; MLP layers only)

// fast, overflow-safe activations
__device__ __forceinline__ float sigm_f(float x) {
    return 1.0f / (1.0f + __expf(-x));
}
__device__ __forceinline__ float tanh_f(float x) {
    float e = __expf(-2.0f * fabsf(x));
    float t = (1.0f - e) / (1.0f + e);
    return copysignf(t, x);
}

__device__ __forceinline__ void split_h(float x, __half& h, __half& l) {
    h = __float2half_rn(x);
    l = __float2half_rn(x - __half2float(h));
}

__device__ __forceinline__ uint32_t s2u(const void* p) {
    uint32_t a;
    asm("{ .reg .u64 t; cvta.to.shared.u64 t, %1; cvt.u32.u64 %0, t; }" : "=r"(a) : "l"(p));
    return a;
}

// ---------------- packed f32x2 helpers (for small f32 GEMM) ----------------
__device__ __forceinline__ unsigned long long pk2(float lo, float hi) {
    unsigned long long r;
    asm("mov.b64 %0, {%1, %2};" : "=l"(r) : "f"(lo), "f"(hi));
    return r;
}
__device__ __forceinline__ void fma2(unsigned long long& d,
                                     unsigned long long a, unsigned long long b) {
    asm("fma.rn.f32x2 %0, %1, %2, %0;" : "+l"(d) : "l"(a), "l"(b));
}
__device__ __forceinline__ float2 unpk2(unsigned long long v) {
    float lo, hi;
    asm("mov.b64 {%0, %1}, %2;" : "=f"(lo), "=f"(hi) : "l"(v));
    return make_float2(lo, hi);
}

// ---------------- init ----------------
__global__ void k_init() {
    int t = blockIdx.x * blockDim.x + threadIdx.x;
    if (t < 6) g_acc[t] = 0.0;
    if (t < NN * NN) {
        int i = t / NN, j = t % NN;
        if (j > i) {
            int p = i * (NN - 1) - i * (i - 1) / 2 + (j - i - 1);
            g_iu[p] = i;
            g_ju[p] = j;
        }
    }
}

// ---------------- vectorized f32 -> fp16 converts (4 elems/thread) ----------------
__global__ void k_convw(const float4* __restrict__ in, __half2* __restrict__ hi,
                        __half2* __restrict__ lo, int n4) {
    int i = blockIdx.x * blockDim.x + threadIdx.x;
    if (i >= n4) return;
    float4 v = in[i];
    __half h0, l0, h1, l1, h2, l2, h3, l3;
    split_h(v.x, h0, l0); split_h(v.y, h1, l1);
    split_h(v.z, h2, l2); split_h(v.w, h3, l3);
    hi[i * 2]     = __halves2half2(h0, h1);
    hi[i * 2 + 1] = __halves2half2(h2, h3);
    lo[i * 2]     = __halves2half2(l0, l1);
    lo[i * 2 + 1] = __halves2half2(l2, l3);
}
__global__ void k_conva(const float4* __restrict__ in, __half2* __restrict__ hi, int n4) {
    int i = blockIdx.x * blockDim.x + threadIdx.x;
    if (i >= n4) return;
    float4 v = in[i];
    hi[i * 2]     = __halves2half2(__float2half_rn(v.x), __float2half_rn(v.y));
    hi[i * 2 + 1] = __halves2half2(__float2half_rn(v.z), __float2half_rn(v.w));
}

// ================= fp16 mma.sync GEMM (1- or 2-pass on B) =================
// C[M,N] = A[M,K] @ (Bhi[+Blo])[N,K]^T + bias.
// CTA 128(M)x128(N), BK=32, 128 threads, warp grid 2(M) x 2(N), warp tile 64x64.
// 3-stage cp.async ring, ONE __syncthreads per K-tile iteration. 2 CTAs/SM.
#define LDB          80
#define MAT_BYTES    (128 * LDB)      // 10240
#define OFF_B        MAT_BYTES        // 10240
#define STAGE_BYTES  (3 * MAT_BYTES)  // 30720
#define NSTAGE       3
#define GSMEM        (NSTAGE * STAGE_BYTES)   // 92160

#define LDSM4(R, A) \
    asm volatile("ldmatrix.sync.aligned.m8n8.x4.shared.b16 {%0,%1,%2,%3}, [%4];" \
        : "=r"((R)[0]), "=r"((R)[1]), "=r"((R)[2]), "=r"((R)[3]) : "r"(A))
#define LDSM4P(R0, R1, A) \
    asm volatile("ldmatrix.sync.aligned.m8n8.x4.shared.b16 {%0,%1,%2,%3}, [%4];" \
        : "=r"((R0)[0]), "=r"((R0)[1]), "=r"((R1)[0]), "=r"((R1)[1]) : "r"(A))
#define MMA(D, Aa, Bb) \
    asm volatile("mma.sync.aligned.m16n8k16.row.col.f32.f16.f16.f32 " \
        "{%0,%1,%2,%3},{%4,%5,%6,%7},{%8,%9},{%0,%1,%2,%3};" \
        : "+f"((D)[0]), "+f"((D)[1]), "+f"((D)[2]), "+f"((D)[3]) \
        : "r"((Aa)[0]), "r"((Aa)[1]), "r"((Aa)[2]), "r"((Aa)[3]), \
          "r"((Bb)[0]), "r"((Bb)[1]))

template <bool TP>
__device__ __forceinline__ void g_issue(
    uint32_t sbase, int s,
    const __half* Ahi, const __half* Bhi, const __half* Blo,
    int m0, int n0, int M, int K, int kt, int tid)
{
    const uint32_t stg = sbase + s * STAGE_BYTES;
    // A: 128 rows x 4 chunks = 512 chunks
#pragma unroll
    for (int i = 0; i < 4; i++) {
        int cid = tid + i * 128;
        int r   = cid >> 2;
        int ch  = cid & 3;
        int row = m0 + r;
        int sz  = (row < M) ? 16 : 0;
        if (row >= M) row = M - 1;
        const __half* gp = Ahi + (size_t)row * K + kt * 32 + ch * 8;
        uint32_t sa = stg + r * LDB + ch * 16;
        asm volatile("cp.async.cg.shared.global [%0], [%1], 16, %2;"
                     :: "r"(sa), "l"(gp), "r"(sz));
    }
    // Bhi: 512 chunks
#pragma unroll
    for (int i = 0; i < 4; i++) {
        int cid = tid + i * 128;
        int r   = cid >> 2;
        int ch  = cid & 3;
        const __half* gp = Bhi + (size_t)(n0 + r) * K + kt * 32 + ch * 8;
        uint32_t sa = stg + OFF_B + r * LDB + ch * 16;
        asm volatile("cp.async.ca.shared.global [%0], [%1], 16;"
                     :: "r"(sa), "l"(gp));
    }
    if (TP) {
        // Blo: 512 chunks
#pragma unroll
        for (int i = 0; i < 4; i++) {
            int cid = tid + i * 128;
            int r   = cid >> 2;
            int ch  = cid & 3;
            const __half* gp = Blo + (size_t)(n0 + r) * K + kt * 32 + ch * 8;
            uint32_t sa = stg + OFF_B + MAT_BYTES + r * LDB + ch * 16;
            asm volatile("cp.async.ca.shared.global [%0], [%1], 16;"
                         :: "r"(sa), "l"(gp));
        }
    }
}

template <bool RELU, int SLOT, bool TP>
__global__ __launch_bounds__(128)
void k_bgemm(const __half* __restrict__ Ahi, const __half* __restrict__ Bhi,
             const __half* __restrict__ Blo,
             const float* __restrict__ bias, float* __restrict__ C,
             int M, int N, int K)
{
    extern __shared__ char smem[];
    const uint32_t sbase = s2u(smem);
    const int tid  = threadIdx.x;
    const int wid  = tid >> 5;
    const int lane = tid & 31;
    const int m0 = blockIdx.y * 128;
    const int n0 = blockIdx.x * 128;
    const int wm = wid & 1;
    const int wn = wid >> 1;

    float acc[4][8][4];
#pragma unroll
    for (int a = 0; a < 4; a++)
#pragma unroll
        for (int b = 0; b < 8; b++)
#pragma unroll
            for (int c = 0; c < 4; c++) acc[a][b][c] = 0.f;

    const int NKT = K >> 5;

    g_issue<TP>(sbase, 0, Ahi, Bhi, Blo, m0, n0, M, K, 0, tid);
    asm volatile("cp.async.commit_group;" ::: "memory");
    g_issue<TP>(sbase, 1, Ahi, Bhi, Blo, m0, n0, M, K, 1, tid);
    asm volatile("cp.async.commit_group;" ::: "memory");

    const uint32_t a_lane = (uint32_t)((wm * 64 + (lane & 15)) * LDB + (lane >> 4) * 16);
    const uint32_t b_lane = (uint32_t)(OFF_B + (wn * 64 + (lane >> 4) * 8 + (lane & 7)) * LDB
                                       + ((lane >> 3) & 1) * 16);

    for (int kt = 0; kt < NKT; kt++) {
        asm volatile("cp.async.wait_group 1;" ::: "memory");
        __syncthreads();
        if (kt + 2 < NKT)
            g_issue<TP>(sbase, (kt + 2) % NSTAGE, Ahi, Bhi, Blo, m0, n0, M, K, kt + 2, tid);
        asm volatile("cp.async.commit_group;" ::: "memory");

        const uint32_t sb = sbase + (kt % NSTAGE) * STAGE_BYTES;
#pragma unroll
        for (int k16 = 0; k16 < 2; k16++) {
            uint32_t ah[4][4];
#pragma unroll
            for (int mt = 0; mt < 4; mt++) {
                uint32_t aadr = sb + a_lane + mt * (16 * LDB) + k16 * 32;
                LDSM4(ah[mt], aadr);
            }
            uint32_t bh[8][2], bl[8][2];
#pragma unroll
            for (int ntb = 0; ntb < 8; ntb += 2) {
                uint32_t badr = sb + b_lane + ntb * (8 * LDB) + k16 * 32;
                LDSM4P(bh[ntb], bh[ntb + 1], badr);
                if (TP) LDSM4P(bl[ntb], bl[ntb + 1], badr + MAT_BYTES);
            }
#pragma unroll
            for (int mt = 0; mt < 4; mt++)
#pragma unroll
                for (int nt = 0; nt < 8; nt++) {
                    MMA(acc[mt][nt], ah[mt], bh[nt]);            // A * Bhi
                    if (TP) MMA(acc[mt][nt], ah[mt], bl[nt]);    // A * Blo
                }
        }
    }

    // ---------------- epilogue ----------------
    double lsum = 0.0, lsq = 0.0;
    const int rb = m0 + wm * 64 + (lane >> 2);
    const int cb = n0 + wn * 64 + (lane & 3) * 2;
#pragma unroll
    for (int mt = 0; mt < 4; mt++) {
#pragma unroll
        for (int half = 0; half < 2; half++) {
            int r = rb + mt * 16 + half * 8;
            if (r < M) {
                float* crow = C + (size_t)r * N;
#pragma unroll
                for (int nt = 0; nt < 8; nt++) {
                    int c = cb + nt * 8;
                    float v0 = acc[mt][nt][half * 2]     + bias[c];
                    float v1 = acc[mt][nt][half * 2 + 1] + bias[c + 1];
                    if (RELU) { v0 = fmaxf(v0, 0.f); v1 = fmaxf(v1, 0.f); }
                    *(float2*)(crow + c) = make_float2(v0, v1);
                    if (SLOT >= 0) {
                        lsum += (double)v0 + (double)v1;
                        lsq  += (double)v0 * v0 + (double)v1 * v1;
                    }
                }
            }
        }
    }
    if (SLOT >= 0) {
#pragma unroll
        for (int off = 16; off; off >>= 1) {
            lsum += __shfl_down_sync(0xffffffffu, lsum, off);
            lsq  += __shfl_down_sync(0xffffffffu, lsq,  off);
        }
        if (lane == 0) {
            atomicAdd(&g_acc[SLOT * 2],     lsum);
            atomicAdd(&g_acc[SLOT * 2 + 1], lsq);
        }
    }
}

// ---------------- f32 SGEMM (small; GEMM1 only) ----------------
template <bool RELU, int SLOT>
__global__ __launch_bounds__(256)
void k_gemm(const float* __restrict__ A, const float* __restrict__ B,
            const float* __restrict__ bias, float* __restrict__ C,
            int M, int N, int K)
{
    __shared__ float As[16][132];
    __shared__ float Bs[16][132];
    const int tid = threadIdx.x;
    const int tx  = tid & 15;
    const int ty  = tid >> 4;
    const int m0  = blockIdx.y * 128;
    const int n0  = blockIdx.x * 128;

    unsigned long long acc[8][4];
#pragma unroll
    for (int i = 0; i < 8; i++)
#pragma unroll
        for (int j = 0; j < 4; j++) acc[i][j] = 0ULL;

    for (int kt = 0; kt < K; kt += 16) {
        __syncthreads();
#pragma unroll
        for (int q = 0; q < 2; q++) {
            int fi  = tid + q * 256;
            int row = fi >> 2;
            int kq  = fi & 3;
            float4 av = make_float4(0.f, 0.f, 0.f, 0.f);
            int gr = m0 + row;
            if (gr < M)
                av = *(const float4*)(A + (size_t)gr * K + kt + kq * 4);
            As[kq * 4 + 0][row] = av.x;
            As[kq * 4 + 1][row] = av.y;
            As[kq * 4 + 2][row] = av.z;
            As[kq * 4 + 3][row] = av.w;
            float4 bv = *(const float4*)(B + (size_t)(n0 + row) * K + kt + kq * 4);
            Bs[kq * 4 + 0][row] = bv.x;
            Bs[kq * 4 + 1][row] = bv.y;
            Bs[kq * 4 + 2][row] = bv.z;
            Bs[kq * 4 + 3][row] = bv.w;
        }
        __syncthreads();
#pragma unroll
        for (int kk = 0; kk < 16; kk++) {
            float4 a0 = *(const float4*)&As[kk][ty * 8];
            float4 a1 = *(const float4*)&As[kk][ty * 8 + 4];
            float4 b0 = *(const float4*)&Bs[kk][tx * 8];
            float4 b1 = *(const float4*)&Bs[kk][tx * 8 + 4];
            unsigned long long bp0 = pk2(b0.x, b0.y);
            unsigned long long bp1 = pk2(b0.z, b0.w);
            unsigned long long bp2 = pk2(b1.x, b1.y);
            unsigned long long bp3 = pk2(b1.z, b1.w);
            float av[8] = {a0.x, a0.y, a0.z, a0.w, a1.x, a1.y, a1.z, a1.w};
#pragma unroll
            for (int i = 0; i < 8; i++) {
                unsigned long long ap = pk2(av[i], av[i]);
                fma2(acc[i][0], ap, bp0);
                fma2(acc[i][1], ap, bp1);
                fma2(acc[i][2], ap, bp2);
                fma2(acc[i][3], ap, bp3);
            }
        }
    }
#pragma unroll
    for (int i = 0; i < 8; i++) {
        int r = m0 + ty * 8 + i;
        if (r < M) {
            float* crow = C + (size_t)r * N + n0 + tx * 8;
            const float* brow = bias + n0 + tx * 8;
#pragma unroll
            for (int j2 = 0; j2 < 4; j2++) {
                float2 v = unpk2(acc[i][j2]);
                float c0 = v.x + brow[j2 * 2];
                float c1 = v.y + brow[j2 * 2 + 1];
                if (RELU) { c0 = fmaxf(c0, 0.f); c1 = fmaxf(c1, 0.f); }
                crow[j2 * 2]     = c0;
                crow[j2 * 2 + 1] = c1;
            }
        }
    }
}

// ---------------- GRU elementwise combine, vectorized (4 elems/thread) ----------------
template <int STEP, bool WF32>
__global__ void k_gru(const float* __restrict__ hin, float* __restrict__ hout,
                      __half2* __restrict__ ohi)
{
    int idx = blockIdx.x * blockDim.x + threadIdx.x;
    if (idx >= PP * (HSZ / 4)) return;
    int p  = idx >> 9;
    int j4 = idx & 511;
    int j  = j4 * 4;
    int node = (STEP == 0) ? g_iu[p] : g_ju[p];
    const float* gi = g_gi + (size_t)node * G3H;
    const float* gh = g_gh + (size_t)p * G3H;

    float4 gir = *(const float4*)(gi + j);
    float4 giz = *(const float4*)(gi + j + HSZ);
    float4 gin = *(const float4*)(gi + j + 2 * HSZ);
    float4 ghr = *(const float4*)(gh + j);
    float4 ghz = *(const float4*)(gh + j + HSZ);
    float4 ghn = *(const float4*)(gh + j + 2 * HSZ);
    float4 hv  = *(const float4*)(hin + (size_t)p * HSZ + j);

    float o[4];
    {
        float r0 = sigm_f(gir.x + ghr.x), z0 = sigm_f(giz.x + ghz.x);
        o[0] = (1.f - z0) * tanh_f(gin.x + r0 * ghn.x) + z0 * hv.x;
        float r1 = sigm_f(gir.y + ghr.y), z1 = sigm_f(giz.y + ghz.y);
        o[1] = (1.f - z1) * tanh_f(gin.y + r1 * ghn.y) + z1 * hv.y;
        float r2 = sigm_f(gir.z + ghr.z), z2 = sigm_f(giz.z + ghz.z);
        o[2] = (1.f - z2) * tanh_f(gin.z + r2 * ghn.z) + z2 * hv.z;
        float r3 = sigm_f(gir.w + ghr.w), z3 = sigm_f(giz.w + ghz.w);
        o[3] = (1.f - z3) * tanh_f(gin.w + r3 * ghn.w) + z3 * hv.w;
    }
    if (WF32)
        *(float4*)(hout + (size_t)p * HSZ + j) = make_float4(o[0], o[1], o[2], o[3]);
    ohi[idx * 2]     = __halves2half2(__float2half_rn(o[0]), __float2half_rn(o[1]));
    ohi[idx * 2 + 1] = __halves2half2(__float2half_rn(o[2]), __float2half_rn(o[3]));
}

// ---------------- full-tensor LayerNorm apply, vectorized ----------------
template <bool CONV>
__global__ void k_norm(float* __restrict__ buf, const float* __restrict__ w,
                       const float* __restrict__ b, int count4, int slot,
                       __half2* __restrict__ ohi)
{
    double sum = g_acc[slot * 2];
    double sq  = g_acc[slot * 2 + 1];
    double cnt = (double)count4 * 4.0;
    double mu  = sum / cnt;
    double var = sq / cnt - mu * mu;
    float rs  = rsqrtf((float)var + 1e-5f);
    float fmu = (float)mu;
    for (int i = blockIdx.x * blockDim.x + threadIdx.x; i < count4;
         i += gridDim.x * blockDim.x) {
        float4 v = *(const float4*)(buf + i * 4);
        float4 ww = *(const float4*)(w + i * 4);
        float4 bb = *(const float4*)(b + i * 4);
        float o0 = (v.x - fmu) * rs * ww.x + bb.x;
        float o1 = (v.y - fmu) * rs * ww.y + bb.y;
        float o2 = (v.z - fmu) * rs * ww.z + bb.z;
        float o3 = (v.w - fmu) * rs * ww.w + bb.w;
        if (CONV) {
            ohi[i * 2]     = __halves2half2(__float2half_rn(o0), __float2half_rn(o1));
            ohi[i * 2 + 1] = __halves2half2(__float2half_rn(o2), __float2half_rn(o3));
        } else {
            *(float4*)(buf + i * 4) = make_float4(o0, o1, o2, o3);
        }
    }
}

// ---------------- final dot + sigmoid + symmetric scatter ----------------
__global__ void k_out(const float* __restrict__ h3, const float* __restrict__ w4,
                      const float* __restrict__ b4, float* __restrict__ out)
{
    int w    = (blockIdx.x * blockDim.x + threadIdx.x) >> 5;
    int lane = threadIdx.x & 31;
    if (w >= NN * NN) return;
    int i = w / NN, j = w % NN;
    if (i == j) { if (lane == 0) out[w] = 0.f; return; }
    int i0 = min(i, j), j0 = max(i, j);
    int p = i0 * (NN - 1) - i0 * (i0 - 1) / 2 + (j0 - i0 - 1);
    const float* hr = h3 + (size_t)p * H2;
    float s = 0.f;
#pragma unroll
    for (int t = 0; t < H2 / 128; t++) {
        float4 a = *(const float4*)(hr + (t * 32 + lane) * 4);
        float4 b = *(const float4*)(w4 + (t * 32 + lane) * 4);
        s += a.x * b.x + a.y * b.y + a.z * b.z + a.w * b.w;
    }
#pragma unroll
    for (int off = 16; off; off >>= 1) s += __shfl_down_sync(0xffffffffu, s, off);
    if (lane == 0) out[w] = 1.0f / (1.0f + __expf(-(s + b4[0])));
}

// ---------------- host launch ----------------
extern "C" void kernel_launch(void* const* d_in, const int* in_sizes, int n_in,
                              void* d_out, int out_size)
{
    const float* x    = (const float*)d_in[0];
    const float* hid  = (const float*)d_in[1];
    const float* Wih  = (const float*)d_in[2];
    const float* Whh  = (const float*)d_in[3];
    const float* bih  = (const float*)d_in[4];
    const float* bhh  = (const float*)d_in[5];
    const float* W1   = (const float*)d_in[6];
    const float* b1   = (const float*)d_in[7];
    const float* ln1w = (const float*)d_in[8];
    const float* ln1b = (const float*)d_in[9];
    const float* W2   = (const float*)d_in[10];
    const float* b2   = (const float*)d_in[11];
    const float* ln2w = (const float*)d_in[12];
    const float* ln2b = (const float*)d_in[13];
    const float* W3   = (const float*)d_in[14];
    const float* b3   = (const float*)d_in[15];
    const float* ln3w = (const float*)d_in[16];
    const float* ln3b = (const float*)d_in[17];
    const float* W4   = (const float*)d_in[18];
    const float* b4   = (const float*)d_in[19];
    float* out = (float*)d_out;

    float *p_gi, *p_gh, *p_h, *p_y;
    __half *p_ahi, *p_bhi, *p_blo;
    cudaGetSymbolAddress((void**)&p_gi,  g_gi);
    cudaGetSymbolAddress((void**)&p_gh,  g_gh);
    cudaGetSymbolAddress((void**)&p_h,   g_h);
    cudaGetSymbolAddress((void**)&p_y,   g_y);
    cudaGetSymbolAddress((void**)&p_ahi, g_ahi);
    cudaGetSymbolAddress((void**)&p_bhi, g_bhi);
    cudaGetSymbolAddress((void**)&p_blo, g_blo);
    float* p_t  = p_gh;                    // [PP, H2]
    float* p_t2 = p_gh + (size_t)PP * H2;  // [PP, H2]

    cudaFuncSetAttribute(k_bgemm<false, -1, false>, cudaFuncAttributeMaxDynamicSharedMemorySize, GSMEM);
    cudaFuncSetAttribute(k_bgemm<true, 0, true>,    cudaFuncAttributeMaxDynamicSharedMemorySize, GSMEM);
    cudaFuncSetAttribute(k_bgemm<true, 1, true>,    cudaFuncAttributeMaxDynamicSharedMemorySize, GSMEM);
    cudaFuncSetAttribute(k_bgemm<true, 2, true>,    cudaFuncAttributeMaxDynamicSharedMemorySize, GSMEM);

    const int MB = (PP + 127) / 128;  // 28
    const int GRU_G = (PP * (HSZ / 4) + 255) / 256;

    // 0) init
    k_init<<<(NN * NN + 255) / 256, 256>>>();

    // 1) gi_node = x @ Wih^T + bih  [84, 6144], K=64 (tiny, f32 path)
    k_gemm<false, -1><<<dim3(G3H / 128, 1), 256>>>(x, Wih, bih, p_gi, NN, G3H, 64);

    // 2) GRU step 1 (single-pass fp16 weights: sigmoid/tanh damp the rounding)
    k_conva<<<(PP * HSZ / 4 + 255) / 256, 256>>>((const float4*)hid, (__half2*)p_ahi, PP * HSZ / 4);
    k_conva<<<(G3H * HSZ / 4 + 255) / 256, 256>>>((const float4*)Whh, (__half2*)p_bhi, G3H * HSZ / 4);
    k_bgemm<false, -1, false><<<dim3(G3H / 128, MB), 128, GSMEM>>>(
        p_ahi, p_bhi, p_blo, bhh, p_gh, PP, G3H, HSZ);
    k_gru<0, true><<<GRU_G, 256>>>(hid, p_h, (__half2*)p_ahi);

    // 3) GRU step 2 (single-pass)
    k_bgemm<false, -1, false><<<dim3(G3H / 128, MB), 128, GSMEM>>>(
        p_ahi, p_bhi, p_blo, bhh, p_gh, PP, G3H, HSZ);
    k_gru<1, false><<<GRU_G, 256>>>(p_h, p_h, (__half2*)p_ahi);

    // 4) layer 1 + LN (2-pass weights)
    k_convw<<<(HSZ * HSZ / 4 + 255) / 256, 256>>>((const float4*)W1, (__half2*)p_bhi,
                                                  (__half2*)p_blo, HSZ * HSZ / 4);
    k_bgemm<true, 0, true><<<dim3(HSZ / 128, MB), 128, GSMEM>>>(
        p_ahi, p_bhi, p_blo, b1, p_y, PP, HSZ, HSZ);
    k_norm<true><<<2048, 256>>>(p_y, ln1w, ln1b, PP * HSZ / 4, 0, (__half2*)p_ahi);

    // 5) layer 2 + LN (2-pass)
    k_convw<<<(H2 * HSZ / 4 + 255) / 256, 256>>>((const float4*)W2, (__half2*)p_bhi,
                                                 (__half2*)p_blo, H2 * HSZ / 4);
    k_bgemm<true, 1, true><<<dim3(H2 / 128, MB), 128, GSMEM>>>(
        p_ahi, p_bhi, p_blo, b2, p_t, PP, H2, HSZ);
    k_norm<true><<<2048, 256>>>(p_t, ln2w, ln2b, PP * H2 / 4, 1, (__half2*)p_ahi);

    // 6) layer 3 + LN (2-pass; in place f32 for k_out)
    k_convw<<<(H2 * H2 / 4 + 255) / 256, 256>>>((const float4*)W3, (__half2*)p_bhi,
                                                (__half2*)p_blo, H2 * H2 / 4);
    k_bgemm<true, 2, true><<<dim3(H2 / 128, MB), 128, GSMEM>>>(
        p_ahi, p_bhi, p_blo, b3, p_t2, PP, H2, H2);
    k_norm<false><<<2048, 256>>>(p_t2, ln3w, ln3b, PP * H2 / 4, 2, 0);

    // 7) output
    k_out<<<(NN * NN * 32 + 255) / 256, 256>>>(p_t2, W4, b4, out);
}

// round 11
// speedup vs baseline: 2.6297x; 1.1866x over previous
#include <cuda_runtime.h>
#include <cuda_fp16.h>
#include <stdint.h>

// ---------------- problem constants ----------------
#define NN   84
#define PP   3486
#define HSZ  2048
#define H2   1024
#define G3H  6144

// ---------------- device scratch ----------------
__device__ float g_gi[NN * G3H];
__device__ float g_gh[PP * G3H];      // GEMM outputs; reused as t / t2 later
__device__ float g_h [PP * HSZ];
__device__ float g_y [PP * HSZ];
__device__ double g_acc[6];
__device__ int   g_iu[PP];
__device__ int   g_ju[PP];
__device__ __half g_ahi[PP * HSZ];    // activation fp16
__device__ __half g_bhi[G3H * HSZ];   // weight fp16

// fast, overflow-safe activations
__device__ __forceinline__ float sigm_f(float x) {
    return 1.0f / (1.0f + __expf(-x));
}
__device__ __forceinline__ float tanh_f(float x) {
    float e = __expf(-2.0f * fabsf(x));
    float t = (1.0f - e) / (1.0f + e);
    return copysignf(t, x);
}

__device__ __forceinline__ uint32_t s2u(const void* p) {
    uint32_t a;
    asm("{ .reg .u64 t; cvta.to.shared.u64 t, %1; cvt.u32.u64 %0, t; }" : "=r"(a) : "l"(p));
    return a;
}

// ---------------- packed f32x2 helpers (for small f32 GEMM) ----------------
__device__ __forceinline__ unsigned long long pk2(float lo, float hi) {
    unsigned long long r;
    asm("mov.b64 %0, {%1, %2};" : "=l"(r) : "f"(lo), "f"(hi));
    return r;
}
__device__ __forceinline__ void fma2(unsigned long long& d,
                                     unsigned long long a, unsigned long long b) {
    asm("fma.rn.f32x2 %0, %1, %2, %0;" : "+l"(d) : "l"(a), "l"(b));
}
__device__ __forceinline__ float2 unpk2(unsigned long long v) {
    float lo, hi;
    asm("mov.b64 {%0, %1}, %2;" : "=f"(lo), "=f"(hi) : "l"(v));
    return make_float2(lo, hi);
}

// ---------------- init ----------------
__global__ void k_init() {
    int t = blockIdx.x * blockDim.x + threadIdx.x;
    if (t < 6) g_acc[t] = 0.0;
    if (t < NN * NN) {
        int i = t / NN, j = t % NN;
        if (j > i) {
            int p = i * (NN - 1) - i * (i - 1) / 2 + (j - i - 1);
            g_iu[p] = i;
            g_ju[p] = j;
        }
    }
}

// ---------------- vectorized f32 -> fp16 convert (4 elems/thread) ----------------
__global__ void k_conva(const float4* __restrict__ in, __half2* __restrict__ hi, int n4) {
    int i = blockIdx.x * blockDim.x + threadIdx.x;
    if (i >= n4) return;
    float4 v = in[i];
    hi[i * 2]     = __halves2half2(__float2half_rn(v.x), __float2half_rn(v.y));
    hi[i * 2 + 1] = __halves2half2(__float2half_rn(v.z), __float2half_rn(v.w));
}

// ================= fp16 single-pass mma.sync GEMM =================
// C[M,N] = A[M,K] @ B[N,K]^T + bias.
// CTA 128(M)x128(N), BK=32, 128 threads, warp grid 2(M) x 2(N), warp tile 64x64.
// 3-stage cp.async ring, ONE __syncthreads per K-tile iteration.
// Per-stage SMEM: A(128x80) B(128x80) = 20480 B -> 3 CTAs/SM.
#define LDB          80
#define MAT_BYTES    (128 * LDB)      // 10240
#define OFF_B        MAT_BYTES        // 10240
#define STAGE_BYTES  (2 * MAT_BYTES)  // 20480
#define NSTAGE       3
#define GSMEM        (NSTAGE * STAGE_BYTES)   // 61440

#define LDSM4(R, A) \
    asm volatile("ldmatrix.sync.aligned.m8n8.x4.shared.b16 {%0,%1,%2,%3}, [%4];" \
        : "=r"((R)[0]), "=r"((R)[1]), "=r"((R)[2]), "=r"((R)[3]) : "r"(A))
#define LDSM4P(R0, R1, A) \
    asm volatile("ldmatrix.sync.aligned.m8n8.x4.shared.b16 {%0,%1,%2,%3}, [%4];" \
        : "=r"((R0)[0]), "=r"((R0)[1]), "=r"((R1)[0]), "=r"((R1)[1]) : "r"(A))
#define MMA(D, Aa, Bb) \
    asm volatile("mma.sync.aligned.m16n8k16.row.col.f32.f16.f16.f32 " \
        "{%0,%1,%2,%3},{%4,%5,%6,%7},{%8,%9},{%0,%1,%2,%3};" \
        : "+f"((D)[0]), "+f"((D)[1]), "+f"((D)[2]), "+f"((D)[3]) \
        : "r"((Aa)[0]), "r"((Aa)[1]), "r"((Aa)[2]), "r"((Aa)[3]), \
          "r"((Bb)[0]), "r"((Bb)[1]))

__device__ __forceinline__ void g_issue(
    uint32_t sbase, int s,
    const __half* Ahi, const __half* Bhi,
    int m0, int n0, int M, int K, int kt, int tid)
{
    const uint32_t stg = sbase + s * STAGE_BYTES;
    // A: 128 rows x 4 chunks = 512 chunks
#pragma unroll
    for (int i = 0; i < 4; i++) {
        int cid = tid + i * 128;
        int r   = cid >> 2;
        int ch  = cid & 3;
        int row = m0 + r;
        int sz  = (row < M) ? 16 : 0;
        if (row >= M) row = M - 1;
        const __half* gp = Ahi + (size_t)row * K + kt * 32 + ch * 8;
        uint32_t sa = stg + r * LDB + ch * 16;
        asm volatile("cp.async.cg.shared.global [%0], [%1], 16, %2;"
                     :: "r"(sa), "l"(gp), "r"(sz));
    }
    // B: 512 chunks
#pragma unroll
    for (int i = 0; i < 4; i++) {
        int cid = tid + i * 128;
        int r   = cid >> 2;
        int ch  = cid & 3;
        const __half* gp = Bhi + (size_t)(n0 + r) * K + kt * 32 + ch * 8;
        uint32_t sa = stg + OFF_B + r * LDB + ch * 16;
        asm volatile("cp.async.ca.shared.global [%0], [%1], 16;"
                     :: "r"(sa), "l"(gp));
    }
}

template <bool RELU, int SLOT>
__global__ __launch_bounds__(128)
void k_bgemm(const __half* __restrict__ Ahi, const __half* __restrict__ Bhi,
             const float* __restrict__ bias, float* __restrict__ C,
             int M, int N, int K)
{
    extern __shared__ char smem[];
    const uint32_t sbase = s2u(smem);
    const int tid  = threadIdx.x;
    const int wid  = tid >> 5;
    const int lane = tid & 31;
    const int m0 = blockIdx.y * 128;
    const int n0 = blockIdx.x * 128;
    const int wm = wid & 1;
    const int wn = wid >> 1;

    float acc[4][8][4];
#pragma unroll
    for (int a = 0; a < 4; a++)
#pragma unroll
        for (int b = 0; b < 8; b++)
#pragma unroll
            for (int c = 0; c < 4; c++) acc[a][b][c] = 0.f;

    const int NKT = K >> 5;

    g_issue(sbase, 0, Ahi, Bhi, m0, n0, M, K, 0, tid);
    asm volatile("cp.async.commit_group;" ::: "memory");
    g_issue(sbase, 1, Ahi, Bhi, m0, n0, M, K, 1, tid);
    asm volatile("cp.async.commit_group;" ::: "memory");

    const uint32_t a_lane = (uint32_t)((wm * 64 + (lane & 15)) * LDB + (lane >> 4) * 16);
    const uint32_t b_lane = (uint32_t)(OFF_B + (wn * 64 + (lane >> 4) * 8 + (lane & 7)) * LDB
                                       + ((lane >> 3) & 1) * 16);

    for (int kt = 0; kt < NKT; kt++) {
        asm volatile("cp.async.wait_group 1;" ::: "memory");
        __syncthreads();
        if (kt + 2 < NKT)
            g_issue(sbase, (kt + 2) % NSTAGE, Ahi, Bhi, m0, n0, M, K, kt + 2, tid);
        asm volatile("cp.async.commit_group;" ::: "memory");

        const uint32_t sb = sbase + (kt % NSTAGE) * STAGE_BYTES;
#pragma unroll
        for (int k16 = 0; k16 < 2; k16++) {
            uint32_t ah[4][4];
#pragma unroll
            for (int mt = 0; mt < 4; mt++) {
                uint32_t aadr = sb + a_lane + mt * (16 * LDB) + k16 * 32;
                LDSM4(ah[mt], aadr);
            }
            uint32_t bh[8][2];
#pragma unroll
            for (int ntb = 0; ntb < 8; ntb += 2) {
                uint32_t badr = sb + b_lane + ntb * (8 * LDB) + k16 * 32;
                LDSM4P(bh[ntb], bh[ntb + 1], badr);
            }
#pragma unroll
            for (int mt = 0; mt < 4; mt++)
#pragma unroll
                for (int nt = 0; nt < 8; nt++)
                    MMA(acc[mt][nt], ah[mt], bh[nt]);
        }
    }

    // ---------------- epilogue ----------------
    double lsum = 0.0, lsq = 0.0;
    const int rb = m0 + wm * 64 + (lane >> 2);
    const int cb = n0 + wn * 64 + (lane & 3) * 2;
#pragma unroll
    for (int mt = 0; mt < 4; mt++) {
#pragma unroll
        for (int half = 0; half < 2; half++) {
            int r = rb + mt * 16 + half * 8;
            if (r < M) {
                float* crow = C + (size_t)r * N;
#pragma unroll
                for (int nt = 0; nt < 8; nt++) {
                    int c = cb + nt * 8;
                    float v0 = acc[mt][nt][half * 2]     + bias[c];
                    float v1 = acc[mt][nt][half * 2 + 1] + bias[c + 1];
                    if (RELU) { v0 = fmaxf(v0, 0.f); v1 = fmaxf(v1, 0.f); }
                    *(float2*)(crow + c) = make_float2(v0, v1);
                    if (SLOT >= 0) {
                        lsum += (double)v0 + (double)v1;
                        lsq  += (double)v0 * v0 + (double)v1 * v1;
                    }
                }
            }
        }
    }
    if (SLOT >= 0) {
#pragma unroll
        for (int off = 16; off; off >>= 1) {
            lsum += __shfl_down_sync(0xffffffffu, lsum, off);
            lsq  += __shfl_down_sync(0xffffffffu, lsq,  off);
        }
        if (lane == 0) {
            atomicAdd(&g_acc[SLOT * 2],     lsum);
            atomicAdd(&g_acc[SLOT * 2 + 1], lsq);
        }
    }
}

// ---------------- f32 SGEMM (small; GEMM1 only) ----------------
template <bool RELU, int SLOT>
__global__ __launch_bounds__(256)
void k_gemm(const float* __restrict__ A, const float* __restrict__ B,
            const float* __restrict__ bias, float* __restrict__ C,
            int M, int N, int K)
{
    __shared__ float As[16][132];
    __shared__ float Bs[16][132];
    const int tid = threadIdx.x;
    const int tx  = tid & 15;
    const int ty  = tid >> 4;
    const int m0  = blockIdx.y * 128;
    const int n0  = blockIdx.x * 128;

    unsigned long long acc[8][4];
#pragma unroll
    for (int i = 0; i < 8; i++)
#pragma unroll
        for (int j = 0; j < 4; j++) acc[i][j] = 0ULL;

    for (int kt = 0; kt < K; kt += 16) {
        __syncthreads();
#pragma unroll
        for (int q = 0; q < 2; q++) {
            int fi  = tid + q * 256;
            int row = fi >> 2;
            int kq  = fi & 3;
            float4 av = make_float4(0.f, 0.f, 0.f, 0.f);
            int gr = m0 + row;
            if (gr < M)
                av = *(const float4*)(A + (size_t)gr * K + kt + kq * 4);
            As[kq * 4 + 0][row] = av.x;
            As[kq * 4 + 1][row] = av.y;
            As[kq * 4 + 2][row] = av.z;
            As[kq * 4 + 3][row] = av.w;
            float4 bv = *(const float4*)(B + (size_t)(n0 + row) * K + kt + kq * 4);
            Bs[kq * 4 + 0][row] = bv.x;
            Bs[kq * 4 + 1][row] = bv.y;
            Bs[kq * 4 + 2][row] = bv.z;
            Bs[kq * 4 + 3][row] = bv.w;
        }
        __syncthreads();
#pragma unroll
        for (int kk = 0; kk < 16; kk++) {
            float4 a0 = *(const float4*)&As[kk][ty * 8];
            float4 a1 = *(const float4*)&As[kk][ty * 8 + 4];
            float4 b0 = *(const float4*)&Bs[kk][tx * 8];
            float4 b1 = *(const float4*)&Bs[kk][tx * 8 + 4];
            unsigned long long bp0 = pk2(b0.x, b0.y);
            unsigned long long bp1 = pk2(b0.z, b0.w);
            unsigned long long bp2 = pk2(b1.x, b1.y);
            unsigned long long bp3 = pk2(b1.z, b1.w);
            float av[8] = {a0.x, a0.y, a0.z, a0.w, a1.x, a1.y, a1.z, a1.w};
#pragma unroll
            for (int i = 0; i < 8; i++) {
                unsigned long long ap = pk2(av[i], av[i]);
                fma2(acc[i][0], ap, bp0);
                fma2(acc[i][1], ap, bp1);
                fma2(acc[i][2], ap, bp2);
                fma2(acc[i][3], ap, bp3);
            }
        }
    }
#pragma unroll
    for (int i = 0; i < 8; i++) {
        int r = m0 + ty * 8 + i;
        if (r < M) {
            float* crow = C + (size_t)r * N + n0 + tx * 8;
            const float* brow = bias + n0 + tx * 8;
#pragma unroll
            for (int j2 = 0; j2 < 4; j2++) {
                float2 v = unpk2(acc[i][j2]);
                float c0 = v.x + brow[j2 * 2];
                float c1 = v.y + brow[j2 * 2 + 1];
                if (RELU) { c0 = fmaxf(c0, 0.f); c1 = fmaxf(c1, 0.f); }
                crow[j2 * 2]     = c0;
                crow[j2 * 2 + 1] = c1;
            }
        }
    }
}

// ---------------- GRU elementwise combine, vectorized (4 elems/thread) ----------------
template <int STEP, bool WF32>
__global__ void k_gru(const float* __restrict__ hin, float* __restrict__ hout,
                      __half2* __restrict__ ohi)
{
    int idx = blockIdx.x * blockDim.x + threadIdx.x;
    if (idx >= PP * (HSZ / 4)) return;
    int p  = idx >> 9;
    int j4 = idx & 511;
    int j  = j4 * 4;
    int node = (STEP == 0) ? g_iu[p] : g_ju[p];
    const float* gi = g_gi + (size_t)node * G3H;
    const float* gh = g_gh + (size_t)p * G3H;

    float4 gir = *(const float4*)(gi + j);
    float4 giz = *(const float4*)(gi + j + HSZ);
    float4 gin = *(const float4*)(gi + j + 2 * HSZ);
    float4 ghr = *(const float4*)(gh + j);
    float4 ghz = *(const float4*)(gh + j + HSZ);
    float4 ghn = *(const float4*)(gh + j + 2 * HSZ);
    float4 hv  = *(const float4*)(hin + (size_t)p * HSZ + j);

    float o[4];
    {
        float r0 = sigm_f(gir.x + ghr.x), z0 = sigm_f(giz.x + ghz.x);
        o[0] = (1.f - z0) * tanh_f(gin.x + r0 * ghn.x) + z0 * hv.x;
        float r1 = sigm_f(gir.y + ghr.y), z1 = sigm_f(giz.y + ghz.y);
        o[1] = (1.f - z1) * tanh_f(gin.y + r1 * ghn.y) + z1 * hv.y;
        float r2 = sigm_f(gir.z + ghr.z), z2 = sigm_f(giz.z + ghz.z);
        o[2] = (1.f - z2) * tanh_f(gin.z + r2 * ghn.z) + z2 * hv.z;
        float r3 = sigm_f(gir.w + ghr.w), z3 = sigm_f(giz.w + ghz.w);
        o[3] = (1.f - z3) * tanh_f(gin.w + r3 * ghn.w) + z3 * hv.w;
    }
    if (WF32)
        *(float4*)(hout + (size_t)p * HSZ + j) = make_float4(o[0], o[1], o[2], o[3]);
    ohi[idx * 2]     = __halves2half2(__float2half_rn(o[0]), __float2half_rn(o[1]));
    ohi[idx * 2 + 1] = __halves2half2(__float2half_rn(o[2]), __float2half_rn(o[3]));
}

// ---------------- full-tensor LayerNorm apply, vectorized ----------------
template <bool CONV>
__global__ void k_norm(float* __restrict__ buf, const float* __restrict__ w,
                       const float* __restrict__ b, int count4, int slot,
                       __half2* __restrict__ ohi)
{
    double sum = g_acc[slot * 2];
    double sq  = g_acc[slot * 2 + 1];
    double cnt = (double)count4 * 4.0;
    double mu  = sum / cnt;
    double var = sq / cnt - mu * mu;
    float rs  = rsqrtf((float)var + 1e-5f);
    float fmu = (float)mu;
    for (int i = blockIdx.x * blockDim.x + threadIdx.x; i < count4;
         i += gridDim.x * blockDim.x) {
        float4 v = *(const float4*)(buf + i * 4);
        float4 ww = *(const float4*)(w + i * 4);
        float4 bb = *(const float4*)(b + i * 4);
        float o0 = (v.x - fmu) * rs * ww.x + bb.x;
        float o1 = (v.y - fmu) * rs * ww.y + bb.y;
        float o2 = (v.z - fmu) * rs * ww.z + bb.z;
        float o3 = (v.w - fmu) * rs * ww.w + bb.w;
        if (CONV) {
            ohi[i * 2]     = __halves2half2(__float2half_rn(o0), __float2half_rn(o1));
            ohi[i * 2 + 1] = __halves2half2(__float2half_rn(o2), __float2half_rn(o3));
        } else {
            *(float4*)(buf + i * 4) = make_float4(o0, o1, o2, o3);
        }
    }
}

// ---------------- final dot + sigmoid + symmetric scatter ----------------
__global__ void k_out(const float* __restrict__ h3, const float* __restrict__ w4,
                      const float* __restrict__ b4, float* __restrict__ out)
{
    int w    = (blockIdx.x * blockDim.x + threadIdx.x) >> 5;
    int lane = threadIdx.x & 31;
    if (w >= NN * NN) return;
    int i = w / NN, j = w % NN;
    if (i == j) { if (lane == 0) out[w] = 0.f; return; }
    int i0 = min(i, j), j0 = max(i, j);
    int p = i0 * (NN - 1) - i0 * (i0 - 1) / 2 + (j0 - i0 - 1);
    const float* hr = h3 + (size_t)p * H2;
    float s = 0.f;
#pragma unroll
    for (int t = 0; t < H2 / 128; t++) {
        float4 a = *(const float4*)(hr + (t * 32 + lane) * 4);
        float4 b = *(const float4*)(w4 + (t * 32 + lane) * 4);
        s += a.x * b.x + a.y * b.y + a.z * b.z + a.w * b.w;
    }
#pragma unroll
    for (int off = 16; off; off >>= 1) s += __shfl_down_sync(0xffffffffu, s, off);
    if (lane == 0) out[w] = 1.0f / (1.0f + __expf(-(s + b4[0])));
}

// ---------------- host launch ----------------
extern "C" void kernel_launch(void* const* d_in, const int* in_sizes, int n_in,
                              void* d_out, int out_size)
{
    const float* x    = (const float*)d_in[0];
    const float* hid  = (const float*)d_in[1];
    const float* Wih  = (const float*)d_in[2];
    const float* Whh  = (const float*)d_in[3];
    const float* bih  = (const float*)d_in[4];
    const float* bhh  = (const float*)d_in[5];
    const float* W1   = (const float*)d_in[6];
    const float* b1   = (const float*)d_in[7];
    const float* ln1w = (const float*)d_in[8];
    const float* ln1b = (const float*)d_in[9];
    const float* W2   = (const float*)d_in[10];
    const float* b2   = (const float*)d_in[11];
    const float* ln2w = (const float*)d_in[12];
    const float* ln2b = (const float*)d_in[13];
    const float* W3   = (const float*)d_in[14];
    const float* b3   = (const float*)d_in[15];
    const float* ln3w = (const float*)d_in[16];
    const float* ln3b = (const float*)d_in[17];
    const float* W4   = (const float*)d_in[18];
    const float* b4   = (const float*)d_in[19];
    float* out = (float*)d_out;

    float *p_gi, *p_gh, *p_h, *p_y;
    __half *p_ahi, *p_bhi;
    cudaGetSymbolAddress((void**)&p_gi,  g_gi);
    cudaGetSymbolAddress((void**)&p_gh,  g_gh);
    cudaGetSymbolAddress((void**)&p_h,   g_h);
    cudaGetSymbolAddress((void**)&p_y,   g_y);
    cudaGetSymbolAddress((void**)&p_ahi, g_ahi);
    cudaGetSymbolAddress((void**)&p_bhi, g_bhi);
    float* p_t  = p_gh;                    // [PP, H2]
    float* p_t2 = p_gh + (size_t)PP * H2;  // [PP, H2]

    cudaFuncSetAttribute(k_bgemm<false, -1>, cudaFuncAttributeMaxDynamicSharedMemorySize, GSMEM);
    cudaFuncSetAttribute(k_bgemm<true, 0>,   cudaFuncAttributeMaxDynamicSharedMemorySize, GSMEM);
    cudaFuncSetAttribute(k_bgemm<true, 1>,   cudaFuncAttributeMaxDynamicSharedMemorySize, GSMEM);
    cudaFuncSetAttribute(k_bgemm<true, 2>,   cudaFuncAttributeMaxDynamicSharedMemorySize, GSMEM);

    const int MB = (PP + 127) / 128;  // 28
    const int GRU_G = (PP * (HSZ / 4) + 255) / 256;

    // 0) init
    k_init<<<(NN * NN + 255) / 256, 256>>>();

    // 1) gi_node = x @ Wih^T + bih  [84, 6144], K=64 (tiny, f32 path)
    k_gemm<false, -1><<<dim3(G3H / 128, 1), 256>>>(x, Wih, bih, p_gi, NN, G3H, 64);

    // 2) GRU step 1 (single-pass fp16)
    k_conva<<<(PP * HSZ / 4 + 255) / 256, 256>>>((const float4*)hid, (__half2*)p_ahi, PP * HSZ / 4);
    k_conva<<<(G3H * HSZ / 4 + 255) / 256, 256>>>((const float4*)Whh, (__half2*)p_bhi, G3H * HSZ / 4);
    k_bgemm<false, -1><<<dim3(G3H / 128, MB), 128, GSMEM>>>(
        p_ahi, p_bhi, bhh, p_gh, PP, G3H, HSZ);
    k_gru<0, true><<<GRU_G, 256>>>(hid, p_h, (__half2*)p_ahi);

    // 3) GRU step 2 (single-pass)
    k_bgemm<false, -1><<<dim3(G3H / 128, MB), 128, GSMEM>>>(
        p_ahi, p_bhi, bhh, p_gh, PP, G3H, HSZ);
    k_gru<1, false><<<GRU_G, 256>>>(p_h, p_h, (__half2*)p_ahi);

    // 4) layer 1 + LN (single-pass fp16)
    k_conva<<<(HSZ * HSZ / 4 + 255) / 256, 256>>>((const float4*)W1, (__half2*)p_bhi, HSZ * HSZ / 4);
    k_bgemm<true, 0><<<dim3(HSZ / 128, MB), 128, GSMEM>>>(
        p_ahi, p_bhi, b1, p_y, PP, HSZ, HSZ);
    k_norm<true><<<2048, 256>>>(p_y, ln1w, ln1b, PP * HSZ / 4, 0, (__half2*)p_ahi);

    // 5) layer 2 + LN (single-pass)
    k_conva<<<(H2 * HSZ / 4 + 255) / 256, 256>>>((const float4*)W2, (__half2*)p_bhi, H2 * HSZ / 4);
    k_bgemm<true, 1><<<dim3(H2 / 128, MB), 128, GSMEM>>>(
        p_ahi, p_bhi, b2, p_t, PP, H2, HSZ);
    k_norm<true><<<2048, 256>>>(p_t, ln2w, ln2b, PP * H2 / 4, 1, (__half2*)p_ahi);

    // 6) layer 3 + LN (single-pass; in place f32 for k_out)
    k_conva<<<(H2 * H2 / 4 + 255) / 256, 256>>>((const float4*)W3, (__half2*)p_bhi, H2 * H2 / 4);
    k_bgemm<true, 2><<<dim3(H2 / 128, MB), 128, GSMEM>>>(
        p_ahi, p_bhi, b3, p_t2, PP, H2, H2);
    k_norm<false><<<2048, 256>>>(p_t2, ln3w, ln3b, PP * H2 / 4, 2, 0);

    // 7) output
    k_out<<<(NN * NN * 32 + 255) / 256, 256>>>(p_t2, W4, b4, out);
}

// round 12
// speedup vs baseline: 2.6931x; 1.0241x over previous
#include <cuda_runtime.h>
#include <cuda_fp16.h>
#include <stdint.h>

// ---------------- problem constants ----------------
#define NN   84
#define PP   3486
#define HSZ  2048
#define H2   1024
#define G3H  6144

// ---------------- device scratch ----------------
__device__ float g_gi[NN * G3H];
__device__ float g_gh[PP * G3H];      // GRU: fp16 view [PP,3H]; later f32 t/t2
__device__ float g_y [PP * HSZ];
__device__ double g_acc[6];
__device__ int   g_iu[PP];
__device__ int   g_ju[PP];
__device__ __half g_ahi[PP * HSZ];    // activation fp16 (doubles as hidden-state carry)
__device__ __half g_bhi[G3H * HSZ];   // weight fp16

// fast, overflow-safe activations
__device__ __forceinline__ float sigm_f(float x) {
    return 1.0f / (1.0f + __expf(-x));
}
__device__ __forceinline__ float tanh_f(float x) {
    float e = __expf(-2.0f * fabsf(x));
    float t = (1.0f - e) / (1.0f + e);
    return copysignf(t, x);
}

__device__ __forceinline__ uint32_t s2u(const void* p) {
    uint32_t a;
    asm("{ .reg .u64 t; cvta.to.shared.u64 t, %1; cvt.u32.u64 %0, t; }" : "=r"(a) : "l"(p));
    return a;
}

// load 4 halves -> float4
__device__ __forceinline__ float4 ld_h4(const __half* p) {
    uint2 u = *(const uint2*)p;
    __half2 a = *(__half2*)&u.x;
    __half2 b = *(__half2*)&u.y;
    float2 fa = __half22float2(a), fb = __half22float2(b);
    return make_float4(fa.x, fa.y, fb.x, fb.y);
}

// ---------------- packed f32x2 helpers (for small f32 GEMM) ----------------
__device__ __forceinline__ unsigned long long pk2(float lo, float hi) {
    unsigned long long r;
    asm("mov.b64 %0, {%1, %2};" : "=l"(r) : "f"(lo), "f"(hi));
    return r;
}
__device__ __forceinline__ void fma2(unsigned long long& d,
                                     unsigned long long a, unsigned long long b) {
    asm("fma.rn.f32x2 %0, %1, %2, %0;" : "+l"(d) : "l"(a), "l"(b));
}
__device__ __forceinline__ float2 unpk2(unsigned long long v) {
    float lo, hi;
    asm("mov.b64 {%0, %1}, %2;" : "=f"(lo), "=f"(hi) : "l"(v));
    return make_float2(lo, hi);
}

// ---------------- init ----------------
__global__ void k_init() {
    int t = blockIdx.x * blockDim.x + threadIdx.x;
    if (t < 6) g_acc[t] = 0.0;
    if (t < NN * NN) {
        int i = t / NN, j = t % NN;
        if (j > i) {
            int p = i * (NN - 1) - i * (i - 1) / 2 + (j - i - 1);
            g_iu[p] = i;
            g_ju[p] = j;
        }
    }
}

// ---------------- vectorized f32 -> fp16 convert (4 elems/thread) ----------------
__global__ void k_conva(const float4* __restrict__ in, __half2* __restrict__ hi, int n4) {
    int i = blockIdx.x * blockDim.x + threadIdx.x;
    if (i >= n4) return;
    float4 v = in[i];
    hi[i * 2]     = __halves2half2(__float2half_rn(v.x), __float2half_rn(v.y));
    hi[i * 2 + 1] = __halves2half2(__float2half_rn(v.z), __float2half_rn(v.w));
}

// ================= fp16 single-pass mma.sync GEMM =================
// C[M,N] = A[M,K] @ B[N,K]^T + bias.  OUTH: store fp16 output (GRU gates).
// CTA 128(M)x128(N), BK=32, 128 threads, warp grid 2(M) x 2(N), warp tile 64x64.
// 3-stage cp.async ring, ONE __syncthreads per K-tile iteration. 3 CTAs/SM.
#define LDB          80
#define MAT_BYTES    (128 * LDB)      // 10240
#define OFF_B        MAT_BYTES        // 10240
#define STAGE_BYTES  (2 * MAT_BYTES)  // 20480
#define NSTAGE       3
#define GSMEM        (NSTAGE * STAGE_BYTES)   // 61440

#define LDSM4(R, A) \
    asm volatile("ldmatrix.sync.aligned.m8n8.x4.shared.b16 {%0,%1,%2,%3}, [%4];" \
        : "=r"((R)[0]), "=r"((R)[1]), "=r"((R)[2]), "=r"((R)[3]) : "r"(A))
#define LDSM4P(R0, R1, A) \
    asm volatile("ldmatrix.sync.aligned.m8n8.x4.shared.b16 {%0,%1,%2,%3}, [%4];" \
        : "=r"((R0)[0]), "=r"((R0)[1]), "=r"((R1)[0]), "=r"((R1)[1]) : "r"(A))
#define MMA(D, Aa, Bb) \
    asm volatile("mma.sync.aligned.m16n8k16.row.col.f32.f16.f16.f32 " \
        "{%0,%1,%2,%3},{%4,%5,%6,%7},{%8,%9},{%0,%1,%2,%3};" \
        : "+f"((D)[0]), "+f"((D)[1]), "+f"((D)[2]), "+f"((D)[3]) \
        : "r"((Aa)[0]), "r"((Aa)[1]), "r"((Aa)[2]), "r"((Aa)[3]), \
          "r"((Bb)[0]), "r"((Bb)[1]))

__device__ __forceinline__ void g_issue(
    uint32_t sbase, int s,
    const __half* Ahi, const __half* Bhi,
    int m0, int n0, int M, int K, int kt, int tid)
{
    const uint32_t stg = sbase + s * STAGE_BYTES;
#pragma unroll
    for (int i = 0; i < 4; i++) {
        int cid = tid + i * 128;
        int r   = cid >> 2;
        int ch  = cid & 3;
        int row = m0 + r;
        int sz  = (row < M) ? 16 : 0;
        if (row >= M) row = M - 1;
        const __half* gp = Ahi + (size_t)row * K + kt * 32 + ch * 8;
        uint32_t sa = stg + r * LDB + ch * 16;
        asm volatile("cp.async.cg.shared.global [%0], [%1], 16, %2;"
                     :: "r"(sa), "l"(gp), "r"(sz));
    }
#pragma unroll
    for (int i = 0; i < 4; i++) {
        int cid = tid + i * 128;
        int r   = cid >> 2;
        int ch  = cid & 3;
        const __half* gp = Bhi + (size_t)(n0 + r) * K + kt * 32 + ch * 8;
        uint32_t sa = stg + OFF_B + r * LDB + ch * 16;
        asm volatile("cp.async.ca.shared.global [%0], [%1], 16;"
                     :: "r"(sa), "l"(gp));
    }
}

template <bool RELU, int SLOT, bool OUTH>
__global__ __launch_bounds__(128)
void k_bgemm(const __half* __restrict__ Ahi, const __half* __restrict__ Bhi,
             const float* __restrict__ bias, void* __restrict__ Cv,
             int M, int N, int K)
{
    extern __shared__ char smem[];
    const uint32_t sbase = s2u(smem);
    const int tid  = threadIdx.x;
    const int wid  = tid >> 5;
    const int lane = tid & 31;
    const int m0 = blockIdx.y * 128;
    const int n0 = blockIdx.x * 128;
    const int wm = wid & 1;
    const int wn = wid >> 1;

    float acc[4][8][4];
#pragma unroll
    for (int a = 0; a < 4; a++)
#pragma unroll
        for (int b = 0; b < 8; b++)
#pragma unroll
            for (int c = 0; c < 4; c++) acc[a][b][c] = 0.f;

    const int NKT = K >> 5;

    g_issue(sbase, 0, Ahi, Bhi, m0, n0, M, K, 0, tid);
    asm volatile("cp.async.commit_group;" ::: "memory");
    g_issue(sbase, 1, Ahi, Bhi, m0, n0, M, K, 1, tid);
    asm volatile("cp.async.commit_group;" ::: "memory");

    const uint32_t a_lane = (uint32_t)((wm * 64 + (lane & 15)) * LDB + (lane >> 4) * 16);
    const uint32_t b_lane = (uint32_t)(OFF_B + (wn * 64 + (lane >> 4) * 8 + (lane & 7)) * LDB
                                       + ((lane >> 3) & 1) * 16);

    for (int kt = 0; kt < NKT; kt++) {
        asm volatile("cp.async.wait_group 1;" ::: "memory");
        __syncthreads();
        if (kt + 2 < NKT)
            g_issue(sbase, (kt + 2) % NSTAGE, Ahi, Bhi, m0, n0, M, K, kt + 2, tid);
        asm volatile("cp.async.commit_group;" ::: "memory");

        const uint32_t sb = sbase + (kt % NSTAGE) * STAGE_BYTES;
#pragma unroll
        for (int k16 = 0; k16 < 2; k16++) {
            uint32_t ah[4][4];
#pragma unroll
            for (int mt = 0; mt < 4; mt++) {
                uint32_t aadr = sb + a_lane + mt * (16 * LDB) + k16 * 32;
                LDSM4(ah[mt], aadr);
            }
            uint32_t bh[8][2];
#pragma unroll
            for (int ntb = 0; ntb < 8; ntb += 2) {
                uint32_t badr = sb + b_lane + ntb * (8 * LDB) + k16 * 32;
                LDSM4P(bh[ntb], bh[ntb + 1], badr);
            }
#pragma unroll
            for (int mt = 0; mt < 4; mt++)
#pragma unroll
                for (int nt = 0; nt < 8; nt++)
                    MMA(acc[mt][nt], ah[mt], bh[nt]);
        }
    }

    // ---------------- epilogue ----------------
    double lsum = 0.0, lsq = 0.0;
    const int rb = m0 + wm * 64 + (lane >> 2);
    const int cb = n0 + wn * 64 + (lane & 3) * 2;
#pragma unroll
    for (int mt = 0; mt < 4; mt++) {
#pragma unroll
        for (int half = 0; half < 2; half++) {
            int r = rb + mt * 16 + half * 8;
            if (r < M) {
#pragma unroll
                for (int nt = 0; nt < 8; nt++) {
                    int c = cb + nt * 8;
                    float v0 = acc[mt][nt][half * 2]     + bias[c];
                    float v1 = acc[mt][nt][half * 2 + 1] + bias[c + 1];
                    if (RELU) { v0 = fmaxf(v0, 0.f); v1 = fmaxf(v1, 0.f); }
                    if (OUTH) {
                        __half* crow = (__half*)Cv + (size_t)r * N;
                        *(__half2*)(crow + c) = __floats2half2_rn(v0, v1);
                    } else {
                        float* crow = (float*)Cv + (size_t)r * N;
                        *(float2*)(crow + c) = make_float2(v0, v1);
                    }
                    if (SLOT >= 0) {
                        lsum += (double)v0 + (double)v1;
                        lsq  += (double)v0 * v0 + (double)v1 * v1;
                    }
                }
            }
        }
    }
    if (SLOT >= 0) {
#pragma unroll
        for (int off = 16; off; off >>= 1) {
            lsum += __shfl_down_sync(0xffffffffu, lsum, off);
            lsq  += __shfl_down_sync(0xffffffffu, lsq,  off);
        }
        if (lane == 0) {
            atomicAdd(&g_acc[SLOT * 2],     lsum);
            atomicAdd(&g_acc[SLOT * 2 + 1], lsq);
        }
    }
}

// ---------------- f32 SGEMM (small; GEMM1 only) ----------------
template <bool RELU, int SLOT>
__global__ __launch_bounds__(256)
void k_gemm(const float* __restrict__ A, const float* __restrict__ B,
            const float* __restrict__ bias, float* __restrict__ C,
            int M, int N, int K)
{
    __shared__ float As[16][132];
    __shared__ float Bs[16][132];
    const int tid = threadIdx.x;
    const int tx  = tid & 15;
    const int ty  = tid >> 4;
    const int m0  = blockIdx.y * 128;
    const int n0  = blockIdx.x * 128;

    unsigned long long acc[8][4];
#pragma unroll
    for (int i = 0; i < 8; i++)
#pragma unroll
        for (int j = 0; j < 4; j++) acc[i][j] = 0ULL;

    for (int kt = 0; kt < K; kt += 16) {
        __syncthreads();
#pragma unroll
        for (int q = 0; q < 2; q++) {
            int fi  = tid + q * 256;
            int row = fi >> 2;
            int kq  = fi & 3;
            float4 av = make_float4(0.f, 0.f, 0.f, 0.f);
            int gr = m0 + row;
            if (gr < M)
                av = *(const float4*)(A + (size_t)gr * K + kt + kq * 4);
            As[kq * 4 + 0][row] = av.x;
            As[kq * 4 + 1][row] = av.y;
            As[kq * 4 + 2][row] = av.z;
            As[kq * 4 + 3][row] = av.w;
            float4 bv = *(const float4*)(B + (size_t)(n0 + row) * K + kt + kq * 4);
            Bs[kq * 4 + 0][row] = bv.x;
            Bs[kq * 4 + 1][row] = bv.y;
            Bs[kq * 4 + 2][row] = bv.z;
            Bs[kq * 4 + 3][row] = bv.w;
        }
        __syncthreads();
#pragma unroll
        for (int kk = 0; kk < 16; kk++) {
            float4 a0 = *(const float4*)&As[kk][ty * 8];
            float4 a1 = *(const float4*)&As[kk][ty * 8 + 4];
            float4 b0 = *(const float4*)&Bs[kk][tx * 8];
            float4 b1 = *(const float4*)&Bs[kk][tx * 8 + 4];
            unsigned long long bp0 = pk2(b0.x, b0.y);
            unsigned long long bp1 = pk2(b0.z, b0.w);
            unsigned long long bp2 = pk2(b1.x, b1.y);
            unsigned long long bp3 = pk2(b1.z, b1.w);
            float av[8] = {a0.x, a0.y, a0.z, a0.w, a1.x, a1.y, a1.z, a1.w};
#pragma unroll
            for (int i = 0; i < 8; i++) {
                unsigned long long ap = pk2(av[i], av[i]);
                fma2(acc[i][0], ap, bp0);
                fma2(acc[i][1], ap, bp1);
                fma2(acc[i][2], ap, bp2);
                fma2(acc[i][3], ap, bp3);
            }
        }
    }
#pragma unroll
    for (int i = 0; i < 8; i++) {
        int r = m0 + ty * 8 + i;
        if (r < M) {
            float* crow = C + (size_t)r * N + n0 + tx * 8;
            const float* brow = bias + n0 + tx * 8;
#pragma unroll
            for (int j2 = 0; j2 < 4; j2++) {
                float2 v = unpk2(acc[i][j2]);
                float c0 = v.x + brow[j2 * 2];
                float c1 = v.y + brow[j2 * 2 + 1];
                if (RELU) { c0 = fmaxf(c0, 0.f); c1 = fmaxf(c1, 0.f); }
                crow[j2 * 2]     = c0;
                crow[j2 * 2 + 1] = c1;
            }
        }
    }
}

// ---------------- GRU elementwise combine, fp16 gates + fp16 state ----------------
// STEP 0: hin from f32 `hid` input.  STEP 1: hin from fp16 g_ahi (in-place).
template <int STEP>
__global__ void k_gru(const float* __restrict__ hin32, const __half* __restrict__ ghh,
                      __half2* __restrict__ ohi)
{
    int idx = blockIdx.x * blockDim.x + threadIdx.x;
    if (idx >= PP * (HSZ / 4)) return;
    int p  = idx >> 9;
    int j4 = idx & 511;
    int j  = j4 * 4;
    int node = (STEP == 0) ? g_iu[p] : g_ju[p];
    const float* gi = g_gi + (size_t)node * G3H;
    const __half* gh = ghh + (size_t)p * G3H;

    float4 gir = *(const float4*)(gi + j);
    float4 giz = *(const float4*)(gi + j + HSZ);
    float4 gin = *(const float4*)(gi + j + 2 * HSZ);
    float4 ghr = ld_h4(gh + j);
    float4 ghz = ld_h4(gh + j + HSZ);
    float4 ghn = ld_h4(gh + j + 2 * HSZ);
    float4 hv;
    if (STEP == 0) {
        hv = *(const float4*)(hin32 + (size_t)p * HSZ + j);
    } else {
        float2 a = __half22float2(ohi[idx * 2]);
        float2 b = __half22float2(ohi[idx * 2 + 1]);
        hv = make_float4(a.x, a.y, b.x, b.y);
    }

    float o[4];
    {
        float r0 = sigm_f(gir.x + ghr.x), z0 = sigm_f(giz.x + ghz.x);
        o[0] = (1.f - z0) * tanh_f(gin.x + r0 * ghn.x) + z0 * hv.x;
        float r1 = sigm_f(gir.y + ghr.y), z1 = sigm_f(giz.y + ghz.y);
        o[1] = (1.f - z1) * tanh_f(gin.y + r1 * ghn.y) + z1 * hv.y;
        float r2 = sigm_f(gir.z + ghr.z), z2 = sigm_f(giz.z + ghz.z);
        o[2] = (1.f - z2) * tanh_f(gin.z + r2 * ghn.z) + z2 * hv.z;
        float r3 = sigm_f(gir.w + ghr.w), z3 = sigm_f(giz.w + ghz.w);
        o[3] = (1.f - z3) * tanh_f(gin.w + r3 * ghn.w) + z3 * hv.w;
    }
    ohi[idx * 2]     = __floats2half2_rn(o[0], o[1]);
    ohi[idx * 2 + 1] = __floats2half2_rn(o[2], o[3]);
}

// ---------------- full-tensor LayerNorm apply, vectorized ----------------
template <bool CONV>
__global__ void k_norm(float* __restrict__ buf, const float* __restrict__ w,
                       const float* __restrict__ b, int count4, int slot,
                       __half2* __restrict__ ohi)
{
    double sum = g_acc[slot * 2];
    double sq  = g_acc[slot * 2 + 1];
    double cnt = (double)count4 * 4.0;
    double mu  = sum / cnt;
    double var = sq / cnt - mu * mu;
    float rs  = rsqrtf((float)var + 1e-5f);
    float fmu = (float)mu;
    for (int i = blockIdx.x * blockDim.x + threadIdx.x; i < count4;
         i += gridDim.x * blockDim.x) {
        float4 v = *(const float4*)(buf + i * 4);
        float4 ww = *(const float4*)(w + i * 4);
        float4 bb = *(const float4*)(b + i * 4);
        float o0 = (v.x - fmu) * rs * ww.x + bb.x;
        float o1 = (v.y - fmu) * rs * ww.y + bb.y;
        float o2 = (v.z - fmu) * rs * ww.z + bb.z;
        float o3 = (v.w - fmu) * rs * ww.w + bb.w;
        if (CONV) {
            ohi[i * 2]     = __floats2half2_rn(o0, o1);
            ohi[i * 2 + 1] = __floats2half2_rn(o2, o3);
        } else {
            *(float4*)(buf + i * 4) = make_float4(o0, o1, o2, o3);
        }
    }
}

// ---------------- final dot + sigmoid + symmetric scatter ----------------
__global__ void k_out(const float* __restrict__ h3, const float* __restrict__ w4,
                      const float* __restrict__ b4, float* __restrict__ out)
{
    int w    = (blockIdx.x * blockDim.x + threadIdx.x) >> 5;
    int lane = threadIdx.x & 31;
    if (w >= NN * NN) return;
    int i = w / NN, j = w % NN;
    if (i == j) { if (lane == 0) out[w] = 0.f; return; }
    int i0 = min(i, j), j0 = max(i, j);
    int p = i0 * (NN - 1) - i0 * (i0 - 1) / 2 + (j0 - i0 - 1);
    const float* hr = h3 + (size_t)p * H2;
    float s = 0.f;
#pragma unroll
    for (int t = 0; t < H2 / 128; t++) {
        float4 a = *(const float4*)(hr + (t * 32 + lane) * 4);
        float4 b = *(const float4*)(w4 + (t * 32 + lane) * 4);
        s += a.x * b.x + a.y * b.y + a.z * b.z + a.w * b.w;
    }
#pragma unroll
    for (int off = 16; off; off >>= 1) s += __shfl_down_sync(0xffffffffu, s, off);
    if (lane == 0) out[w] = 1.0f / (1.0f + __expf(-(s + b4[0])));
}

// ---------------- host launch ----------------
extern "C" void kernel_launch(void* const* d_in, const int* in_sizes, int n_in,
                              void* d_out, int out_size)
{
    const float* x    = (const float*)d_in[0];
    const float* hid  = (const float*)d_in[1];
    const float* Wih  = (const float*)d_in[2];
    const float* Whh  = (const float*)d_in[3];
    const float* bih  = (const float*)d_in[4];
    const float* bhh  = (const float*)d_in[5];
    const float* W1   = (const float*)d_in[6];
    const float* b1   = (const float*)d_in[7];
    const float* ln1w = (const float*)d_in[8];
    const float* ln1b = (const float*)d_in[9];
    const float* W2   = (const float*)d_in[10];
    const float* b2   = (const float*)d_in[11];
    const float* ln2w = (const float*)d_in[12];
    const float* ln2b = (const float*)d_in[13];
    const float* W3   = (const float*)d_in[14];
    const float* b3   = (const float*)d_in[15];
    const float* ln3w = (const float*)d_in[16];
    const float* ln3b = (const float*)d_in[17];
    const float* W4   = (const float*)d_in[18];
    const float* b4   = (const float*)d_in[19];
    float* out = (float*)d_out;

    float *p_gi, *p_gh, *p_y;
    __half *p_ahi, *p_bhi;
    cudaGetSymbolAddress((void**)&p_gi,  g_gi);
    cudaGetSymbolAddress((void**)&p_gh,  g_gh);
    cudaGetSymbolAddress((void**)&p_y,   g_y);
    cudaGetSymbolAddress((void**)&p_ahi, g_ahi);
    cudaGetSymbolAddress((void**)&p_bhi, g_bhi);
    __half* p_ghh = (__half*)p_gh;         // fp16 view of gate buffer
    float* p_t  = p_gh;                    // [PP, H2]  (gates dead after GRU)
    float* p_t2 = p_gh + (size_t)PP * H2;  // [PP, H2]

    cudaFuncSetAttribute(k_bgemm<false, -1, true>, cudaFuncAttributeMaxDynamicSharedMemorySize, GSMEM);
    cudaFuncSetAttribute(k_bgemm<true, 0, false>,  cudaFuncAttributeMaxDynamicSharedMemorySize, GSMEM);
    cudaFuncSetAttribute(k_bgemm<true, 1, false>,  cudaFuncAttributeMaxDynamicSharedMemorySize, GSMEM);
    cudaFuncSetAttribute(k_bgemm<true, 2, false>,  cudaFuncAttributeMaxDynamicSharedMemorySize, GSMEM);

    const int MB = (PP + 127) / 128;  // 28
    const int GRU_G = (PP * (HSZ / 4) + 255) / 256;

    // 0) init
    k_init<<<(NN * NN + 255) / 256, 256>>>();

    // 1) gi_node = x @ Wih^T + bih  [84, 6144], K=64 (tiny, f32 path)
    k_gemm<false, -1><<<dim3(G3H / 128, 1), 256>>>(x, Wih, bih, p_gi, NN, G3H, 64);

    // 2) GRU step 1 (fp16 gates out; h1 kept only in fp16 g_ahi)
    k_conva<<<(PP * HSZ / 4 + 255) / 256, 256>>>((const float4*)hid, (__half2*)p_ahi, PP * HSZ / 4);
    k_conva<<<(G3H * HSZ / 4 + 255) / 256, 256>>>((const float4*)Whh, (__half2*)p_bhi, G3H * HSZ / 4);
    k_bgemm<false, -1, true><<<dim3(G3H / 128, MB), 128, GSMEM>>>(
        p_ahi, p_bhi, bhh, p_ghh, PP, G3H, HSZ);
    k_gru<0><<<GRU_G, 256>>>(hid, p_ghh, (__half2*)p_ahi);

    // 3) GRU step 2 (reads h1 fp16 from g_ahi in place)
    k_bgemm<false, -1, true><<<dim3(G3H / 128, MB), 128, GSMEM>>>(
        p_ahi, p_bhi, bhh, p_ghh, PP, G3H, HSZ);
    k_gru<1><<<GRU_G, 256>>>(hid, p_ghh, (__half2*)p_ahi);

    // 4) layer 1 + LN
    k_conva<<<(HSZ * HSZ / 4 + 255) / 256, 256>>>((const float4*)W1, (__half2*)p_bhi, HSZ * HSZ / 4);
    k_bgemm<true, 0, false><<<dim3(HSZ / 128, MB), 128, GSMEM>>>(
        p_ahi, p_bhi, b1, p_y, PP, HSZ, HSZ);
    k_norm<true><<<2048, 256>>>(p_y, ln1w, ln1b, PP * HSZ / 4, 0, (__half2*)p_ahi);

    // 5) layer 2 + LN
    k_conva<<<(H2 * HSZ / 4 + 255) / 256, 256>>>((const float4*)W2, (__half2*)p_bhi, H2 * HSZ / 4);
    k_bgemm<true, 1, false><<<dim3(H2 / 128, MB), 128, GSMEM>>>(
        p_ahi, p_bhi, b2, p_t, PP, H2, HSZ);
    k_norm<true><<<2048, 256>>>(p_t, ln2w, ln2b, PP * H2 / 4, 1, (__half2*)p_ahi);

    // 6) layer 3 + LN (in place f32 for k_out)
    k_conva<<<(H2 * H2 / 4 + 255) / 256, 256>>>((const float4*)W3, (__half2*)p_bhi, H2 * H2 / 4);
    k_bgemm<true, 2, false><<<dim3(H2 / 128, MB), 128, GSMEM>>>(
        p_ahi, p_bhi, b3, p_t2, PP, H2, H2);
    k_norm<false><<<2048, 256>>>(p_t2, ln3w, ln3b, PP * H2 / 4, 2, 0);

    // 7) output
    k_out<<<(NN * NN * 32 + 255) / 256, 256>>>(p_t2, W4, b4, out);
}

// round 13
// speedup vs baseline: 2.7304x; 1.0139x over previous
#include <cuda_runtime.h>
#include <cuda_fp16.h>
#include <stdint.h>

// ---------------- problem constants ----------------
#define NN   84
#define PP   3486
#define HSZ  2048
#define H2   1024
#define G3H  6144

// ---------------- device scratch ----------------
__device__ float g_gi[NN * G3H];
__device__ float g_gh[PP * G3H];      // GRU: fp16 view [PP,3H]; later f32 t/t2
__device__ float g_y [PP * HSZ];
__device__ double g_acc[6];
__device__ int   g_iu[PP];
__device__ int   g_ju[PP];
__device__ __half g_ahi[PP * HSZ];    // activation fp16 (doubles as hidden-state carry)
__device__ __half g_bWhh[G3H * HSZ];  // weight fp16 buffers (converted once upfront)
__device__ __half g_bW1[HSZ * HSZ];
__device__ __half g_bW2[H2 * HSZ];
__device__ __half g_bW3[H2 * H2];

// fast, overflow-safe activations
__device__ __forceinline__ float sigm_f(float x) {
    return 1.0f / (1.0f + __expf(-x));
}
__device__ __forceinline__ float tanh_f(float x) {
    float e = __expf(-2.0f * fabsf(x));
    float t = (1.0f - e) / (1.0f + e);
    return copysignf(t, x);
}

__device__ __forceinline__ uint32_t s2u(const void* p) {
    uint32_t a;
    asm("{ .reg .u64 t; cvta.to.shared.u64 t, %1; cvt.u32.u64 %0, t; }" : "=r"(a) : "l"(p));
    return a;
}

// 8 halves (uint4) -> 8 floats
__device__ __forceinline__ void h8_to_f(uint4 v, float* o) {
    float2 f;
    f = __half22float2(*(__half2*)&v.x); o[0] = f.x; o[1] = f.y;
    f = __half22float2(*(__half2*)&v.y); o[2] = f.x; o[3] = f.y;
    f = __half22float2(*(__half2*)&v.z); o[4] = f.x; o[5] = f.y;
    f = __half22float2(*(__half2*)&v.w); o[6] = f.x; o[7] = f.y;
}
// 8 floats -> uint4 of halves
__device__ __forceinline__ uint4 f_to_h8(const float* o) {
    union { __half2 h[4]; uint4 u; } r;
    r.h[0] = __floats2half2_rn(o[0], o[1]);
    r.h[1] = __floats2half2_rn(o[2], o[3]);
    r.h[2] = __floats2half2_rn(o[4], o[5]);
    r.h[3] = __floats2half2_rn(o[6], o[7]);
    return r.u;
}
__device__ __forceinline__ void conv8(const float4* __restrict__ in,
                                      uint4* __restrict__ out, int i8) {
    float4 a = in[i8 * 2], b = in[i8 * 2 + 1];
    float o[8] = {a.x, a.y, a.z, a.w, b.x, b.y, b.z, b.w};
    out[i8] = f_to_h8(o);
}

// ---------------- packed f32x2 helpers (for small f32 GEMM) ----------------
__device__ __forceinline__ unsigned long long pk2(float lo, float hi) {
    unsigned long long r;
    asm("mov.b64 %0, {%1, %2};" : "=l"(r) : "f"(lo), "f"(hi));
    return r;
}
__device__ __forceinline__ void fma2(unsigned long long& d,
                                     unsigned long long a, unsigned long long b) {
    asm("fma.rn.f32x2 %0, %1, %2, %0;" : "+l"(d) : "l"(a), "l"(b));
}
__device__ __forceinline__ float2 unpk2(unsigned long long v) {
    float lo, hi;
    asm("mov.b64 {%0, %1}, %2;" : "=f"(lo), "=f"(hi) : "l"(v));
    return make_float2(lo, hi);
}

// ---------------- init ----------------
__global__ void k_init() {
    int t = blockIdx.x * blockDim.x + threadIdx.x;
    if (t < 6) g_acc[t] = 0.0;
    if (t < NN * NN) {
        int i = t / NN, j = t % NN;
        if (j > i) {
            int p = i * (NN - 1) - i * (i - 1) / 2 + (j - i - 1);
            g_iu[p] = i;
            g_ju[p] = j;
        }
    }
}

// ---------------- one-shot weight converts (all 4 weights, 8 elems/thread) ----------------
#define N8_WHH  (G3H * HSZ / 8)             // 1572864
#define N8_W1   (HSZ * HSZ / 8)             // 524288
#define N8_W2   (H2 * HSZ / 8)              // 262144
#define N8_W3   (H2 * H2 / 8)               // 131072
#define N8_ALL  (N8_WHH + N8_W1 + N8_W2 + N8_W3)

__global__ void k_convall(const float4* __restrict__ Whh, const float4* __restrict__ W1,
                          const float4* __restrict__ W2, const float4* __restrict__ W3)
{
    int i = blockIdx.x * blockDim.x + threadIdx.x;
    if (i < N8_WHH) {
        conv8(Whh, (uint4*)g_bWhh, i);
    } else if (i < N8_WHH + N8_W1) {
        conv8(W1, (uint4*)g_bW1, i - N8_WHH);
    } else if (i < N8_WHH + N8_W1 + N8_W2) {
        conv8(W2, (uint4*)g_bW2, i - N8_WHH - N8_W1);
    } else if (i < N8_ALL) {
        conv8(W3, (uint4*)g_bW3, i - N8_WHH - N8_W1 - N8_W2);
    }
}

// ---------------- activation convert (8 elems/thread) ----------------
__global__ void k_conva8(const float4* __restrict__ in, uint4* __restrict__ hi, int n8) {
    int i = blockIdx.x * blockDim.x + threadIdx.x;
    if (i < n8) conv8(in, hi, i);
}

// ================= fp16 single-pass mma.sync GEMM =================
// C[M,N] = A[M,K] @ B[N,K]^T + bias.  OUTH: store fp16 output (GRU gates).
// CTA 128(M)x128(N), BK=32, 128 threads, warp grid 2(M) x 2(N), warp tile 64x64.
// 3-stage cp.async ring, ONE __syncthreads per K-tile iteration. 3 CTAs/SM.
#define LDB          80
#define MAT_BYTES    (128 * LDB)      // 10240
#define OFF_B        MAT_BYTES        // 10240
#define STAGE_BYTES  (2 * MAT_BYTES)  // 20480
#define NSTAGE       3
#define GSMEM        (NSTAGE * STAGE_BYTES)   // 61440

#define LDSM4(R, A) \
    asm volatile("ldmatrix.sync.aligned.m8n8.x4.shared.b16 {%0,%1,%2,%3}, [%4];" \
        : "=r"((R)[0]), "=r"((R)[1]), "=r"((R)[2]), "=r"((R)[3]) : "r"(A))
#define LDSM4P(R0, R1, A) \
    asm volatile("ldmatrix.sync.aligned.m8n8.x4.shared.b16 {%0,%1,%2,%3}, [%4];" \
        : "=r"((R0)[0]), "=r"((R0)[1]), "=r"((R1)[0]), "=r"((R1)[1]) : "r"(A))
#define MMA(D, Aa, Bb) \
    asm volatile("mma.sync.aligned.m16n8k16.row.col.f32.f16.f16.f32 " \
        "{%0,%1,%2,%3},{%4,%5,%6,%7},{%8,%9},{%0,%1,%2,%3};" \
        : "+f"((D)[0]), "+f"((D)[1]), "+f"((D)[2]), "+f"((D)[3]) \
        : "r"((Aa)[0]), "r"((Aa)[1]), "r"((Aa)[2]), "r"((Aa)[3]), \
          "r"((Bb)[0]), "r"((Bb)[1]))

__device__ __forceinline__ void g_issue(
    uint32_t sbase, int s,
    const __half* Ahi, const __half* Bhi,
    int m0, int n0, int M, int K, int kt, int tid)
{
    const uint32_t stg = sbase + s * STAGE_BYTES;
#pragma unroll
    for (int i = 0; i < 4; i++) {
        int cid = tid + i * 128;
        int r   = cid >> 2;
        int ch  = cid & 3;
        int row = m0 + r;
        int sz  = (row < M) ? 16 : 0;
        if (row >= M) row = M - 1;
        const __half* gp = Ahi + (size_t)row * K + kt * 32 + ch * 8;
        uint32_t sa = stg + r * LDB + ch * 16;
        asm volatile("cp.async.cg.shared.global [%0], [%1], 16, %2;"
                     :: "r"(sa), "l"(gp), "r"(sz));
    }
#pragma unroll
    for (int i = 0; i < 4; i++) {
        int cid = tid + i * 128;
        int r   = cid >> 2;
        int ch  = cid & 3;
        const __half* gp = Bhi + (size_t)(n0 + r) * K + kt * 32 + ch * 8;
        uint32_t sa = stg + OFF_B + r * LDB + ch * 16;
        asm volatile("cp.async.ca.shared.global [%0], [%1], 16;"
                     :: "r"(sa), "l"(gp));
    }
}

template <bool RELU, int SLOT, bool OUTH>
__global__ __launch_bounds__(128)
void k_bgemm(const __half* __restrict__ Ahi, const __half* __restrict__ Bhi,
             const float* __restrict__ bias, void* __restrict__ Cv,
             int M, int N, int K)
{
    extern __shared__ char smem[];
    const uint32_t sbase = s2u(smem);
    const int tid  = threadIdx.x;
    const int wid  = tid >> 5;
    const int lane = tid & 31;
    const int m0 = blockIdx.y * 128;
    const int n0 = blockIdx.x * 128;
    const int wm = wid & 1;
    const int wn = wid >> 1;

    float acc[4][8][4];
#pragma unroll
    for (int a = 0; a < 4; a++)
#pragma unroll
        for (int b = 0; b < 8; b++)
#pragma unroll
            for (int c = 0; c < 4; c++) acc[a][b][c] = 0.f;

    const int NKT = K >> 5;

    g_issue(sbase, 0, Ahi, Bhi, m0, n0, M, K, 0, tid);
    asm volatile("cp.async.commit_group;" ::: "memory");
    g_issue(sbase, 1, Ahi, Bhi, m0, n0, M, K, 1, tid);
    asm volatile("cp.async.commit_group;" ::: "memory");

    const uint32_t a_lane = (uint32_t)((wm * 64 + (lane & 15)) * LDB + (lane >> 4) * 16);
    const uint32_t b_lane = (uint32_t)(OFF_B + (wn * 64 + (lane >> 4) * 8 + (lane & 7)) * LDB
                                       + ((lane >> 3) & 1) * 16);

    for (int kt = 0; kt < NKT; kt++) {
        asm volatile("cp.async.wait_group 1;" ::: "memory");
        __syncthreads();
        if (kt + 2 < NKT)
            g_issue(sbase, (kt + 2) % NSTAGE, Ahi, Bhi, m0, n0, M, K, kt + 2, tid);
        asm volatile("cp.async.commit_group;" ::: "memory");

        const uint32_t sb = sbase + (kt % NSTAGE) * STAGE_BYTES;
#pragma unroll
        for (int k16 = 0; k16 < 2; k16++) {
            uint32_t ah[4][4];
#pragma unroll
            for (int mt = 0; mt < 4; mt++) {
                uint32_t aadr = sb + a_lane + mt * (16 * LDB) + k16 * 32;
                LDSM4(ah[mt], aadr);
            }
            uint32_t bh[8][2];
#pragma unroll
            for (int ntb = 0; ntb < 8; ntb += 2) {
                uint32_t badr = sb + b_lane + ntb * (8 * LDB) + k16 * 32;
                LDSM4P(bh[ntb], bh[ntb + 1], badr);
            }
#pragma unroll
            for (int mt = 0; mt < 4; mt++)
#pragma unroll
                for (int nt = 0; nt < 8; nt++)
                    MMA(acc[mt][nt], ah[mt], bh[nt]);
        }
    }

    // ---------------- epilogue ----------------
    double lsum = 0.0, lsq = 0.0;
    const int rb = m0 + wm * 64 + (lane >> 2);
    const int cb = n0 + wn * 64 + (lane & 3) * 2;
#pragma unroll
    for (int mt = 0; mt < 4; mt++) {
#pragma unroll
        for (int half = 0; half < 2; half++) {
            int r = rb + mt * 16 + half * 8;
            if (r < M) {
#pragma unroll
                for (int nt = 0; nt < 8; nt++) {
                    int c = cb + nt * 8;
                    float v0 = acc[mt][nt][half * 2]     + bias[c];
                    float v1 = acc[mt][nt][half * 2 + 1] + bias[c + 1];
                    if (RELU) { v0 = fmaxf(v0, 0.f); v1 = fmaxf(v1, 0.f); }
                    if (OUTH) {
                        __half* crow = (__half*)Cv + (size_t)r * N;
                        *(__half2*)(crow + c) = __floats2half2_rn(v0, v1);
                    } else {
                        float* crow = (float*)Cv + (size_t)r * N;
                        *(float2*)(crow + c) = make_float2(v0, v1);
                    }
                    if (SLOT >= 0) {
                        lsum += (double)v0 + (double)v1;
                        lsq  += (double)v0 * v0 + (double)v1 * v1;
                    }
                }
            }
        }
    }
    if (SLOT >= 0) {
#pragma unroll
        for (int off = 16; off; off >>= 1) {
            lsum += __shfl_down_sync(0xffffffffu, lsum, off);
            lsq  += __shfl_down_sync(0xffffffffu, lsq,  off);
        }
        if (lane == 0) {
            atomicAdd(&g_acc[SLOT * 2],     lsum);
            atomicAdd(&g_acc[SLOT * 2 + 1], lsq);
        }
    }
}

// ---------------- f32 SGEMM (small; GEMM1 only) ----------------
template <bool RELU, int SLOT>
__global__ __launch_bounds__(256)
void k_gemm(const float* __restrict__ A, const float* __restrict__ B,
            const float* __restrict__ bias, float* __restrict__ C,
            int M, int N, int K)
{
    __shared__ float As[16][132];
    __shared__ float Bs[16][132];
    const int tid = threadIdx.x;
    const int tx  = tid & 15;
    const int ty  = tid >> 4;
    const int m0  = blockIdx.y * 128;
    const int n0  = blockIdx.x * 128;

    unsigned long long acc[8][4];
#pragma unroll
    for (int i = 0; i < 8; i++)
#pragma unroll
        for (int j = 0; j < 4; j++) acc[i][j] = 0ULL;

    for (int kt = 0; kt < K; kt += 16) {
        __syncthreads();
#pragma unroll
        for (int q = 0; q < 2; q++) {
            int fi  = tid + q * 256;
            int row = fi >> 2;
            int kq  = fi & 3;
            float4 av = make_float4(0.f, 0.f, 0.f, 0.f);
            int gr = m0 + row;
            if (gr < M)
                av = *(const float4*)(A + (size_t)gr * K + kt + kq * 4);
            As[kq * 4 + 0][row] = av.x;
            As[kq * 4 + 1][row] = av.y;
            As[kq * 4 + 2][row] = av.z;
            As[kq * 4 + 3][row] = av.w;
            float4 bv = *(const float4*)(B + (size_t)(n0 + row) * K + kt + kq * 4);
            Bs[kq * 4 + 0][row] = bv.x;
            Bs[kq * 4 + 1][row] = bv.y;
            Bs[kq * 4 + 2][row] = bv.z;
            Bs[kq * 4 + 3][row] = bv.w;
        }
        __syncthreads();
#pragma unroll
        for (int kk = 0; kk < 16; kk++) {
            float4 a0 = *(const float4*)&As[kk][ty * 8];
            float4 a1 = *(const float4*)&As[kk][ty * 8 + 4];
            float4 b0 = *(const float4*)&Bs[kk][tx * 8];
            float4 b1 = *(const float4*)&Bs[kk][tx * 8 + 4];
            unsigned long long bp0 = pk2(b0.x, b0.y);
            unsigned long long bp1 = pk2(b0.z, b0.w);
            unsigned long long bp2 = pk2(b1.x, b1.y);
            unsigned long long bp3 = pk2(b1.z, b1.w);
            float av[8] = {a0.x, a0.y, a0.z, a0.w, a1.x, a1.y, a1.z, a1.w};
#pragma unroll
            for (int i = 0; i < 8; i++) {
                unsigned long long ap = pk2(av[i], av[i]);
                fma2(acc[i][0], ap, bp0);
                fma2(acc[i][1], ap, bp1);
                fma2(acc[i][2], ap, bp2);
                fma2(acc[i][3], ap, bp3);
            }
        }
    }
#pragma unroll
    for (int i = 0; i < 8; i++) {
        int r = m0 + ty * 8 + i;
        if (r < M) {
            float* crow = C + (size_t)r * N + n0 + tx * 8;
            const float* brow = bias + n0 + tx * 8;
#pragma unroll
            for (int j2 = 0; j2 < 4; j2++) {
                float2 v = unpk2(acc[i][j2]);
                float c0 = v.x + brow[j2 * 2];
                float c1 = v.y + brow[j2 * 2 + 1];
                if (RELU) { c0 = fmaxf(c0, 0.f); c1 = fmaxf(c1, 0.f); }
                crow[j2 * 2]     = c0;
                crow[j2 * 2 + 1] = c1;
            }
        }
    }
}

// ---------------- GRU elementwise combine, 8 elems/thread ----------------
// STEP 0: hin from f32 `hid` input.  STEP 1: hin from fp16 g_ahi (in-place).
template <int STEP>
__global__ void k_gru(const float* __restrict__ hin32, const __half* __restrict__ ghh,
                      uint4* __restrict__ ohi)
{
    int idx = blockIdx.x * blockDim.x + threadIdx.x;    // over PP * (HSZ/8)
    if (idx >= PP * (HSZ / 8)) return;
    int p = idx >> 8;              // /(HSZ/8)=256
    int j = (idx & 255) * 8;
    int node = (STEP == 0) ? g_iu[p] : g_ju[p];
    const float* gi = g_gi + (size_t)node * G3H;
    const __half* gh = ghh + (size_t)p * G3H;

    float gr[8], gz[8], gn[8], hr[8], hz[8], hn[8], hv[8], o[8];
    {
        float4 a, b;
        a = *(const float4*)(gi + j);           b = *(const float4*)(gi + j + 4);
        gr[0]=a.x; gr[1]=a.y; gr[2]=a.z; gr[3]=a.w; gr[4]=b.x; gr[5]=b.y; gr[6]=b.z; gr[7]=b.w;
        a = *(const float4*)(gi + j + HSZ);     b = *(const float4*)(gi + j + HSZ + 4);
        gz[0]=a.x; gz[1]=a.y; gz[2]=a.z; gz[3]=a.w; gz[4]=b.x; gz[5]=b.y; gz[6]=b.z; gz[7]=b.w;
        a = *(const float4*)(gi + j + 2*HSZ);   b = *(const float4*)(gi + j + 2*HSZ + 4);
        gn[0]=a.x; gn[1]=a.y; gn[2]=a.z; gn[3]=a.w; gn[4]=b.x; gn[5]=b.y; gn[6]=b.z; gn[7]=b.w;
    }
    h8_to_f(*(const uint4*)(gh + j),           hr);
    h8_to_f(*(const uint4*)(gh + j + HSZ),     hz);
    h8_to_f(*(const uint4*)(gh + j + 2 * HSZ), hn);
    if (STEP == 0) {
        float4 a = *(const float4*)(hin32 + (size_t)p * HSZ + j);
        float4 b = *(const float4*)(hin32 + (size_t)p * HSZ + j + 4);
        hv[0]=a.x; hv[1]=a.y; hv[2]=a.z; hv[3]=a.w; hv[4]=b.x; hv[5]=b.y; hv[6]=b.z; hv[7]=b.w;
    } else {
        h8_to_f(ohi[idx], hv);
    }
#pragma unroll
    for (int e = 0; e < 8; e++) {
        float r = sigm_f(gr[e] + hr[e]);
        float z = sigm_f(gz[e] + hz[e]);
        float n = tanh_f(gn[e] + r * hn[e]);
        o[e] = (1.f - z) * n + z * hv[e];
    }
    ohi[idx] = f_to_h8(o);
}

// ---------------- full-tensor LayerNorm apply, 8 elems/thread ----------------
__global__ void k_norm(const float* __restrict__ buf, const float* __restrict__ w,
                       const float* __restrict__ b, int count8, int slot,
                       uint4* __restrict__ ohi)
{
    double sum = g_acc[slot * 2];
    double sq  = g_acc[slot * 2 + 1];
    double cnt = (double)count8 * 8.0;
    double mu  = sum / cnt;
    double var = sq / cnt - mu * mu;
    float rs  = rsqrtf((float)var + 1e-5f);
    float fmu = (float)mu;
    for (int i = blockIdx.x * blockDim.x + threadIdx.x; i < count8;
         i += gridDim.x * blockDim.x) {
        float o[8];
#pragma unroll
        for (int q = 0; q < 2; q++) {
            float4 v  = *(const float4*)(buf + i * 8 + q * 4);
            float4 ww = *(const float4*)(w   + i * 8 + q * 4);
            float4 bb = *(const float4*)(b   + i * 8 + q * 4);
            o[q*4+0] = (v.x - fmu) * rs * ww.x + bb.x;
            o[q*4+1] = (v.y - fmu) * rs * ww.y + bb.y;
            o[q*4+2] = (v.z - fmu) * rs * ww.z + bb.z;
            o[q*4+3] = (v.w - fmu) * rs * ww.w + bb.w;
        }
        ohi[i] = f_to_h8(o);
    }
}

// ---------------- final: fused LN3 + dot + sigmoid + symmetric write ----------------
// Warp per pair p (writes out[i,j] AND out[j,i]); extra warps zero the diagonal.
__global__ void k_out(const float* __restrict__ h3, const float* __restrict__ lnw,
                      const float* __restrict__ lnb, const float* __restrict__ w4,
                      const float* __restrict__ b4, float* __restrict__ out)
{
    int gw   = (blockIdx.x * blockDim.x + threadIdx.x) >> 5;
    int lane = threadIdx.x & 31;
    if (gw >= PP) {
        int d = gw - PP;
        if (d < NN && lane == 0) out[d * NN + d] = 0.f;
        return;
    }
    double sum = g_acc[4];
    double sq  = g_acc[5];
    double cnt = (double)PP * (double)H2;
    double mu  = sum / cnt;
    double var = sq / cnt - mu * mu;
    float rs  = rsqrtf((float)var + 1e-5f);
    float fmu = (float)mu;

    const float* hr = h3  + (size_t)gw * H2;
    const float* wr = lnw + (size_t)gw * H2;
    const float* br = lnb + (size_t)gw * H2;
    float s = 0.f;
#pragma unroll
    for (int t = 0; t < H2 / 128; t++) {
        int off = (t * 32 + lane) * 4;
        float4 v  = *(const float4*)(hr + off);
        float4 ww = *(const float4*)(wr + off);
        float4 bb = *(const float4*)(br + off);
        float4 q  = *(const float4*)(w4 + off);
        s += ((v.x - fmu) * rs * ww.x + bb.x) * q.x;
        s += ((v.y - fmu) * rs * ww.y + bb.y) * q.y;
        s += ((v.z - fmu) * rs * ww.z + bb.z) * q.z;
        s += ((v.w - fmu) * rs * ww.w + bb.w) * q.w;
    }
#pragma unroll
    for (int off = 16; off; off >>= 1) s += __shfl_down_sync(0xffffffffu, s, off);
    if (lane == 0) {
        float val = 1.0f / (1.0f + __expf(-(s + b4[0])));
        int i = g_iu[gw], j = g_ju[gw];
        out[i * NN + j] = val;
        out[j * NN + i] = val;
    }
}

// ---------------- host launch ----------------
extern "C" void kernel_launch(void* const* d_in, const int* in_sizes, int n_in,
                              void* d_out, int out_size)
{
    const float* x    = (const float*)d_in[0];
    const float* hid  = (const float*)d_in[1];
    const float* Wih  = (const float*)d_in[2];
    const float* Whh  = (const float*)d_in[3];
    const float* bih  = (const float*)d_in[4];
    const float* bhh  = (const float*)d_in[5];
    const float* W1   = (const float*)d_in[6];
    const float* b1   = (const float*)d_in[7];
    const float* ln1w = (const float*)d_in[8];
    const float* ln1b = (const float*)d_in[9];
    const float* W2   = (const float*)d_in[10];
    const float* b2   = (const float*)d_in[11];
    const float* ln2w = (const float*)d_in[12];
    const float* ln2b = (const float*)d_in[13];
    const float* W3   = (const float*)d_in[14];
    const float* b3   = (const float*)d_in[15];
    const float* ln3w = (const float*)d_in[16];
    const float* ln3b = (const float*)d_in[17];
    const float* W4   = (const float*)d_in[18];
    const float* b4   = (const float*)d_in[19];
    float* out = (float*)d_out;

    float *p_gi, *p_gh, *p_y;
    __half *p_ahi, *p_bWhh, *p_bW1, *p_bW2, *p_bW3;
    cudaGetSymbolAddress((void**)&p_gi,   g_gi);
    cudaGetSymbolAddress((void**)&p_gh,   g_gh);
    cudaGetSymbolAddress((void**)&p_y,    g_y);
    cudaGetSymbolAddress((void**)&p_ahi,  g_ahi);
    cudaGetSymbolAddress((void**)&p_bWhh, g_bWhh);
    cudaGetSymbolAddress((void**)&p_bW1,  g_bW1);
    cudaGetSymbolAddress((void**)&p_bW2,  g_bW2);
    cudaGetSymbolAddress((void**)&p_bW3,  g_bW3);
    __half* p_ghh = (__half*)p_gh;         // fp16 view of gate buffer
    float* p_t  = p_gh;                    // [PP, H2]  (gates dead after GRU)
    float* p_t2 = p_gh + (size_t)PP * H2;  // [PP, H2]

    cudaFuncSetAttribute(k_bgemm<false, -1, true>, cudaFuncAttributeMaxDynamicSharedMemorySize, GSMEM);
    cudaFuncSetAttribute(k_bgemm<true, 0, false>,  cudaFuncAttributeMaxDynamicSharedMemorySize, GSMEM);
    cudaFuncSetAttribute(k_bgemm<true, 1, false>,  cudaFuncAttributeMaxDynamicSharedMemorySize, GSMEM);
    cudaFuncSetAttribute(k_bgemm<true, 2, false>,  cudaFuncAttributeMaxDynamicSharedMemorySize, GSMEM);

    const int MB = (PP + 127) / 128;  // 28
    const int GRU_G = (PP * (HSZ / 8) + 255) / 256;

    // 0) init + all weight converts (one node each)
    k_init<<<(NN * NN + 255) / 256, 256>>>();
    k_convall<<<(N8_ALL + 255) / 256, 256>>>((const float4*)Whh, (const float4*)W1,
                                             (const float4*)W2, (const float4*)W3);

    // 1) gi_node = x @ Wih^T + bih  [84, 6144], K=64 (tiny, f32 path)
    k_gemm<false, -1><<<dim3(G3H / 128, 1), 256>>>(x, Wih, bih, p_gi, NN, G3H, 64);

    // 2) GRU step 1 (fp16 gates out; h1 kept only in fp16 g_ahi)
    k_conva8<<<(PP * HSZ / 8 + 255) / 256, 256>>>((const float4*)hid, (uint4*)p_ahi, PP * HSZ / 8);
    k_bgemm<false, -1, true><<<dim3(G3H / 128, MB), 128, GSMEM>>>(
        p_ahi, p_bWhh, bhh, p_ghh, PP, G3H, HSZ);
    k_gru<0><<<GRU_G, 256>>>(hid, p_ghh, (uint4*)p_ahi);

    // 3) GRU step 2 (reads h1 fp16 from g_ahi in place)
    k_bgemm<false, -1, true><<<dim3(G3H / 128, MB), 128, GSMEM>>>(
        p_ahi, p_bWhh, bhh, p_ghh, PP, G3H, HSZ);
    k_gru<1><<<GRU_G, 256>>>(hid, p_ghh, (uint4*)p_ahi);

    // 4) layer 1 + LN
    k_bgemm<true, 0, false><<<dim3(HSZ / 128, MB), 128, GSMEM>>>(
        p_ahi, p_bW1, b1, p_y, PP, HSZ, HSZ);
    k_norm<<<2048, 256>>>(p_y, ln1w, ln1b, PP * HSZ / 8, 0, (uint4*)p_ahi);

    // 5) layer 2 + LN
    k_bgemm<true, 1, false><<<dim3(H2 / 128, MB), 128, GSMEM>>>(
        p_ahi, p_bW2, b2, p_t, PP, H2, HSZ);
    k_norm<<<2048, 256>>>(p_t, ln2w, ln2b, PP * H2 / 8, 1, (uint4*)p_ahi);

    // 6) layer 3 (raw f32 out; LN fused into k_out)
    k_bgemm<true, 2, false><<<dim3(H2 / 128, MB), 128, GSMEM>>>(
        p_ahi, p_bW3, b3, p_t2, PP, H2, H2);

    // 7) output: fused LN3 + dot + sigmoid + symmetric scatter
    k_out<<<((PP + NN) * 32 + 255) / 256, 256>>>(p_t2, ln3w, ln3b, W4, b4, out);
}

// round 15
// speedup vs baseline: 2.7414x; 1.0040x over previous
#include <cuda_runtime.h>
#include <cuda_fp16.h>
#include <stdint.h>

// ---------------- problem constants ----------------
#define NN   84
#define PP   3486
#define HSZ  2048
#define H2   1024
#define G3H  6144

// ---------------- device scratch ----------------
__device__ float g_gi[NN * G3H];
__device__ float g_gh[PP * G3H];      // GRU: fp16 view [PP,3H]; later f32 t/t2
__device__ float g_y [PP * HSZ];
__device__ double g_acc[6];
__device__ int   g_iu[PP];
__device__ int   g_ju[PP];
__device__ __half g_ahi[PP * HSZ];    // activation fp16 (doubles as hidden-state carry)
__device__ __half g_bWhh[G3H * HSZ];  // weight fp16 buffers (converted once upfront)
__device__ __half g_bW1[HSZ * HSZ];
__device__ __half g_bW2[H2 * HSZ];
__device__ __half g_bW3[H2 * H2];

// fast, overflow-safe activations
__device__ __forceinline__ float sigm_f(float x) {
    return 1.0f / (1.0f + __expf(-x));
}
__device__ __forceinline__ float tanh_f(float x) {
    float e = __expf(-2.0f * fabsf(x));
    float t = (1.0f - e) / (1.0f + e);
    return copysignf(t, x);
}

__device__ __forceinline__ uint32_t s2u(const void* p) {
    uint32_t a;
    asm("{ .reg .u64 t; cvta.to.shared.u64 t, %1; cvt.u32.u64 %0, t; }" : "=r"(a) : "l"(p));
    return a;
}

// 8 halves (uint4) -> 8 floats
__device__ __forceinline__ void h8_to_f(uint4 v, float* o) {
    float2 f;
    f = __half22float2(*(__half2*)&v.x); o[0] = f.x; o[1] = f.y;
    f = __half22float2(*(__half2*)&v.y); o[2] = f.x; o[3] = f.y;
    f = __half22float2(*(__half2*)&v.z); o[4] = f.x; o[5] = f.y;
    f = __half22float2(*(__half2*)&v.w); o[6] = f.x; o[7] = f.y;
}
// 8 floats -> uint4 of halves
__device__ __forceinline__ uint4 f_to_h8(const float* o) {
    union { __half2 h[4]; uint4 u; } r;
    r.h[0] = __floats2half2_rn(o[0], o[1]);
    r.h[1] = __floats2half2_rn(o[2], o[3]);
    r.h[2] = __floats2half2_rn(o[4], o[5]);
    r.h[3] = __floats2half2_rn(o[6], o[7]);
    return r.u;
}
__device__ __forceinline__ void conv8(const float4* __restrict__ in,
                                      uint4* __restrict__ out, int i8) {
    float4 a = in[i8 * 2], b = in[i8 * 2 + 1];
    float o[8] = {a.x, a.y, a.z, a.w, b.x, b.y, b.z, b.w};
    out[i8] = f_to_h8(o);
}

// ---------------- packed f32x2 helpers (for small f32 GEMM) ----------------
__device__ __forceinline__ unsigned long long pk2(float lo, float hi) {
    unsigned long long r;
    asm("mov.b64 %0, {%1, %2};" : "=l"(r) : "f"(lo), "f"(hi));
    return r;
}
__device__ __forceinline__ void fma2(unsigned long long& d,
                                     unsigned long long a, unsigned long long b) {
    asm("fma.rn.f32x2 %0, %1, %2, %0;" : "+l"(d) : "l"(a), "l"(b));
}
__device__ __forceinline__ float2 unpk2(unsigned long long v) {
    float lo, hi;
    asm("mov.b64 {%0, %1}, %2;" : "=f"(lo), "=f"(hi) : "l"(v));
    return make_float2(lo, hi);
}

// ---------------- one-shot init + weight converts (fused) ----------------
#define N8_WHH  (G3H * HSZ / 8)             // 1572864
#define N8_W1   (HSZ * HSZ / 8)             // 524288
#define N8_W2   (H2 * HSZ / 8)              // 262144
#define N8_W3   (H2 * H2 / 8)               // 131072
#define N8_ALL  (N8_WHH + N8_W1 + N8_W2 + N8_W3)

__global__ void k_convall(const float4* __restrict__ Whh, const float4* __restrict__ W1,
                          const float4* __restrict__ W2, const float4* __restrict__ W3)
{
    int i = blockIdx.x * blockDim.x + threadIdx.x;
    // fused init (indices < NN*NN = 7056 << N8_ALL)
    if (i < 6) g_acc[i] = 0.0;
    if (i < NN * NN) {
        int r = i / NN, c = i % NN;
        if (c > r) {
            int p = r * (NN - 1) - r * (r - 1) / 2 + (c - r - 1);
            g_iu[p] = r;
            g_ju[p] = c;
        }
    }
    if (i < N8_WHH) {
        conv8(Whh, (uint4*)g_bWhh, i);
    } else if (i < N8_WHH + N8_W1) {
        conv8(W1, (uint4*)g_bW1, i - N8_WHH);
    } else if (i < N8_WHH + N8_W1 + N8_W2) {
        conv8(W2, (uint4*)g_bW2, i - N8_WHH - N8_W1);
    } else if (i < N8_ALL) {
        conv8(W3, (uint4*)g_bW3, i - N8_WHH - N8_W1 - N8_W2);
    }
}

// ---------------- activation convert (8 elems/thread) ----------------
__global__ void k_conva8(const float4* __restrict__ in, uint4* __restrict__ hi, int n8) {
    int i = blockIdx.x * blockDim.x + threadIdx.x;
    if (i < n8) conv8(in, hi, i);
}

// ================= fp16 single-pass mma.sync GEMM =================
// C[M,N] = A[M,K] @ B[N,K]^T + bias.  OUTH: store fp16 output (GRU gates).
// CTA 128(M)x128(N), BK=32, 128 threads, warp grid 2(M) x 2(N), warp tile 64x64.
// 3-stage cp.async ring, ONE __syncthreads per K-tile iteration. 3 CTAs/SM.
#define LDB          80
#define MAT_BYTES    (128 * LDB)      // 10240
#define OFF_B        MAT_BYTES        // 10240
#define STAGE_BYTES  (2 * MAT_BYTES)  // 20480
#define NSTAGE       3
#define GSMEM        (NSTAGE * STAGE_BYTES)   // 61440

#define LDSM4(R, A) \
    asm volatile("ldmatrix.sync.aligned.m8n8.x4.shared.b16 {%0,%1,%2,%3}, [%4];" \
        : "=r"((R)[0]), "=r"((R)[1]), "=r"((R)[2]), "=r"((R)[3]) : "r"(A))
#define LDSM4P(R0, R1, A) \
    asm volatile("ldmatrix.sync.aligned.m8n8.x4.shared.b16 {%0,%1,%2,%3}, [%4];" \
        : "=r"((R0)[0]), "=r"((R0)[1]), "=r"((R1)[0]), "=r"((R1)[1]) : "r"(A))
#define MMA(D, Aa, Bb) \
    asm volatile("mma.sync.aligned.m16n8k16.row.col.f32.f16.f16.f32 " \
        "{%0,%1,%2,%3},{%4,%5,%6,%7},{%8,%9},{%0,%1,%2,%3};" \
        : "+f"((D)[0]), "+f"((D)[1]), "+f"((D)[2]), "+f"((D)[3]) \
        : "r"((Aa)[0]), "r"((Aa)[1]), "r"((Aa)[2]), "r"((Aa)[3]), \
          "r"((Bb)[0]), "r"((Bb)[1]))

__device__ __forceinline__ void g_issue(
    uint32_t sbase, int s,
    const __half* Ahi, const __half* Bhi,
    int m0, int n0, int M, int K, int kt, int tid)
{
    const uint32_t stg = sbase + s * STAGE_BYTES;
#pragma unroll
    for (int i = 0; i < 4; i++) {
        int cid = tid + i * 128;
        int r   = cid >> 2;
        int ch  = cid & 3;
        int row = m0 + r;
        int sz  = (row < M) ? 16 : 0;
        if (row >= M) row = M - 1;
        const __half* gp = Ahi + (size_t)row * K + kt * 32 + ch * 8;
        uint32_t sa = stg + r * LDB + ch * 16;
        asm volatile("cp.async.cg.shared.global [%0], [%1], 16, %2;"
                     :: "r"(sa), "l"(gp), "r"(sz));
    }
#pragma unroll
    for (int i = 0; i < 4; i++) {
        int cid = tid + i * 128;
        int r   = cid >> 2;
        int ch  = cid & 3;
        const __half* gp = Bhi + (size_t)(n0 + r) * K + kt * 32 + ch * 8;
        uint32_t sa = stg + OFF_B + r * LDB + ch * 16;
        asm volatile("cp.async.ca.shared.global [%0], [%1], 16;"
                     :: "r"(sa), "l"(gp));
    }
}

template <bool RELU, int SLOT, bool OUTH>
__global__ __launch_bounds__(128)
void k_bgemm(const __half* __restrict__ Ahi, const __half* __restrict__ Bhi,
             const float* __restrict__ bias, void* __restrict__ Cv,
             int M, int N, int K)
{
    extern __shared__ char smem[];
    const uint32_t sbase = s2u(smem);
    const int tid  = threadIdx.x;
    const int wid  = tid >> 5;
    const int lane = tid & 31;
    const int m0 = blockIdx.y * 128;
    const int n0 = blockIdx.x * 128;
    const int wm = wid & 1;
    const int wn = wid >> 1;

    float acc[4][8][4];
#pragma unroll
    for (int a = 0; a < 4; a++)
#pragma unroll
        for (int b = 0; b < 8; b++)
#pragma unroll
            for (int c = 0; c < 4; c++) acc[a][b][c] = 0.f;

    const int NKT = K >> 5;

    g_issue(sbase, 0, Ahi, Bhi, m0, n0, M, K, 0, tid);
    asm volatile("cp.async.commit_group;" ::: "memory");
    g_issue(sbase, 1, Ahi, Bhi, m0, n0, M, K, 1, tid);
    asm volatile("cp.async.commit_group;" ::: "memory");

    const uint32_t a_lane = (uint32_t)((wm * 64 + (lane & 15)) * LDB + (lane >> 4) * 16);
    const uint32_t b_lane = (uint32_t)(OFF_B + (wn * 64 + (lane >> 4) * 8 + (lane & 7)) * LDB
                                       + ((lane >> 3) & 1) * 16);

    for (int kt = 0; kt < NKT; kt++) {
        asm volatile("cp.async.wait_group 1;" ::: "memory");
        __syncthreads();
        if (kt + 2 < NKT)
            g_issue(sbase, (kt + 2) % NSTAGE, Ahi, Bhi, m0, n0, M, K, kt + 2, tid);
        asm volatile("cp.async.commit_group;" ::: "memory");

        const uint32_t sb = sbase + (kt % NSTAGE) * STAGE_BYTES;
#pragma unroll
        for (int k16 = 0; k16 < 2; k16++) {
            uint32_t ah[4][4];
#pragma unroll
            for (int mt = 0; mt < 4; mt++) {
                uint32_t aadr = sb + a_lane + mt * (16 * LDB) + k16 * 32;
                LDSM4(ah[mt], aadr);
            }
            uint32_t bh[8][2];
#pragma unroll
            for (int ntb = 0; ntb < 8; ntb += 2) {
                uint32_t badr = sb + b_lane + ntb * (8 * LDB) + k16 * 32;
                LDSM4P(bh[ntb], bh[ntb + 1], badr);
            }
#pragma unroll
            for (int mt = 0; mt < 4; mt++)
#pragma unroll
                for (int nt = 0; nt < 8; nt++)
                    MMA(acc[mt][nt], ah[mt], bh[nt]);
        }
    }

    // ---------------- epilogue ----------------
    double lsum = 0.0, lsq = 0.0;
    const int rb = m0 + wm * 64 + (lane >> 2);
    const int cb = n0 + wn * 64 + (lane & 3) * 2;
#pragma unroll
    for (int mt = 0; mt < 4; mt++) {
#pragma unroll
        for (int half = 0; half < 2; half++) {
            int r = rb + mt * 16 + half * 8;
            if (r < M) {
#pragma unroll
                for (int nt = 0; nt < 8; nt++) {
                    int c = cb + nt * 8;
                    float v0 = acc[mt][nt][half * 2]     + bias[c];
                    float v1 = acc[mt][nt][half * 2 + 1] + bias[c + 1];
                    if (RELU) { v0 = fmaxf(v0, 0.f); v1 = fmaxf(v1, 0.f); }
                    if (OUTH) {
                        __half* crow = (__half*)Cv + (size_t)r * N;
                        *(__half2*)(crow + c) = __floats2half2_rn(v0, v1);
                    } else {
                        float* crow = (float*)Cv + (size_t)r * N;
                        *(float2*)(crow + c) = make_float2(v0, v1);
                    }
                    if (SLOT >= 0) {
                        lsum += (double)v0 + (double)v1;
                        lsq  += (double)v0 * v0 + (double)v1 * v1;
                    }
                }
            }
        }
    }
    if (SLOT >= 0) {
#pragma unroll
        for (int off = 16; off; off >>= 1) {
            lsum += __shfl_down_sync(0xffffffffu, lsum, off);
            lsq  += __shfl_down_sync(0xffffffffu, lsq,  off);
        }
        if (lane == 0) {
            atomicAdd(&g_acc[SLOT * 2],     lsum);
            atomicAdd(&g_acc[SLOT * 2 + 1], lsq);
        }
    }
}

// ---------------- f32 SGEMM (small; GEMM1 only) ----------------
template <bool RELU, int SLOT>
__global__ __launch_bounds__(256)
void k_gemm(const float* __restrict__ A, const float* __restrict__ B,
            const float* __restrict__ bias, float* __restrict__ C,
            int M, int N, int K)
{
    __shared__ float As[16][132];
    __shared__ float Bs[16][132];
    const int tid = threadIdx.x;
    const int tx  = tid & 15;
    const int ty  = tid >> 4;
    const int m0  = blockIdx.y * 128;
    const int n0  = blockIdx.x * 128;

    unsigned long long acc[8][4];
#pragma unroll
    for (int i = 0; i < 8; i++)
#pragma unroll
        for (int j = 0; j < 4; j++) acc[i][j] = 0ULL;

    for (int kt = 0; kt < K; kt += 16) {
        __syncthreads();
#pragma unroll
        for (int q = 0; q < 2; q++) {
            int fi  = tid + q * 256;
            int row = fi >> 2;
            int kq  = fi & 3;
            float4 av = make_float4(0.f, 0.f, 0.f, 0.f);
            int gr = m0 + row;
            if (gr < M)
                av = *(const float4*)(A + (size_t)gr * K + kt + kq * 4);
            As[kq * 4 + 0][row] = av.x;
            As[kq * 4 + 1][row] = av.y;
            As[kq * 4 + 2][row] = av.z;
            As[kq * 4 + 3][row] = av.w;
            float4 bv = *(const float4*)(B + (size_t)(n0 + row) * K + kt + kq * 4);
            Bs[kq * 4 + 0][row] = bv.x;
            Bs[kq * 4 + 1][row] = bv.y;
            Bs[kq * 4 + 2][row] = bv.z;
            Bs[kq * 4 + 3][row] = bv.w;
        }
        __syncthreads();
#pragma unroll
        for (int kk = 0; kk < 16; kk++) {
            float4 a0 = *(const float4*)&As[kk][ty * 8];
            float4 a1 = *(const float4*)&As[kk][ty * 8 + 4];
            float4 b0 = *(const float4*)&Bs[kk][tx * 8];
            float4 b1 = *(const float4*)&Bs[kk][tx * 8 + 4];
            unsigned long long bp0 = pk2(b0.x, b0.y);
            unsigned long long bp1 = pk2(b0.z, b0.w);
            unsigned long long bp2 = pk2(b1.x, b1.y);
            unsigned long long bp3 = pk2(b1.z, b1.w);
            float av[8] = {a0.x, a0.y, a0.z, a0.w, a1.x, a1.y, a1.z, a1.w};
#pragma unroll
            for (int i = 0; i < 8; i++) {
                unsigned long long ap = pk2(av[i], av[i]);
                fma2(acc[i][0], ap, bp0);
                fma2(acc[i][1], ap, bp1);
                fma2(acc[i][2], ap, bp2);
                fma2(acc[i][3], ap, bp3);
            }
        }
    }
#pragma unroll
    for (int i = 0; i < 8; i++) {
        int r = m0 + ty * 8 + i;
        if (r < M) {
            float* crow = C + (size_t)r * N + n0 + tx * 8;
            const float* brow = bias + n0 + tx * 8;
#pragma unroll
            for (int j2 = 0; j2 < 4; j2++) {
                float2 v = unpk2(acc[i][j2]);
                float c0 = v.x + brow[j2 * 2];
                float c1 = v.y + brow[j2 * 2 + 1];
                if (RELU) { c0 = fmaxf(c0, 0.f); c1 = fmaxf(c1, 0.f); }
                crow[j2 * 2]     = c0;
                crow[j2 * 2 + 1] = c1;
            }
        }
    }
}

// ---------------- GRU elementwise combine, 8 elems/thread ----------------
// STEP 0: hin from f32 `hid` input.  STEP 1: hin from fp16 g_ahi (in-place).
template <int STEP>
__global__ void k_gru(const float* __restrict__ hin32, const __half* __restrict__ ghh,
                      uint4* __restrict__ ohi)
{
    int idx = blockIdx.x * blockDim.x + threadIdx.x;    // over PP * (HSZ/8)
    if (idx >= PP * (HSZ / 8)) return;
    int p = idx >> 8;              // /(HSZ/8)=256
    int j = (idx & 255) * 8;
    int node = (STEP == 0) ? g_iu[p] : g_ju[p];
    const float* gi = g_gi + (size_t)node * G3H;
    const __half* gh = ghh + (size_t)p * G3H;

    float gr[8], gz[8], gn[8], hr[8], hz[8], hn[8], hv[8], o[8];
    {
        float4 a, b;
        a = *(const float4*)(gi + j);           b = *(const float4*)(gi + j + 4);
        gr[0]=a.x; gr[1]=a.y; gr[2]=a.z; gr[3]=a.w; gr[4]=b.x; gr[5]=b.y; gr[6]=b.z; gr[7]=b.w;
        a = *(const float4*)(gi + j + HSZ);     b = *(const float4*)(gi + j + HSZ + 4);
        gz[0]=a.x; gz[1]=a.y; gz[2]=a.z; gz[3]=a.w; gz[4]=b.x; gz[5]=b.y; gz[6]=b.z; gz[7]=b.w;
        a = *(const float4*)(gi + j + 2*HSZ);   b = *(const float4*)(gi + j + 2*HSZ + 4);
        gn[0]=a.x; gn[1]=a.y; gn[2]=a.z; gn[3]=a.w; gn[4]=b.x; gn[5]=b.y; gn[6]=b.z; gn[7]=b.w;
    }
    h8_to_f(*(const uint4*)(gh + j),           hr);
    h8_to_f(*(const uint4*)(gh + j + HSZ),     hz);
    h8_to_f(*(const uint4*)(gh + j + 2 * HSZ), hn);
    if (STEP == 0) {
        float4 a = *(const float4*)(hin32 + (size_t)p * HSZ + j);
        float4 b = *(const float4*)(hin32 + (size_t)p * HSZ + j + 4);
        hv[0]=a.x; hv[1]=a.y; hv[2]=a.z; hv[3]=a.w; hv[4]=b.x; hv[5]=b.y; hv[6]=b.z; hv[7]=b.w;
    } else {
        h8_to_f(ohi[idx], hv);
    }
#pragma unroll
    for (int e = 0; e < 8; e++) {
        float r = sigm_f(gr[e] + hr[e]);
        float z = sigm_f(gz[e] + hz[e]);
        float n = tanh_f(gn[e] + r * hn[e]);
        o[e] = (1.f - z) * n + z * hv[e];
    }
    ohi[idx] = f_to_h8(o);
}

// ---------------- full-tensor LayerNorm apply, 8 elems/thread ----------------
__global__ void k_norm(const float* __restrict__ buf, const float* __restrict__ w,
                       const float* __restrict__ b, int count8, int slot,
                       uint4* __restrict__ ohi)
{
    double sum = g_acc[slot * 2];
    double sq  = g_acc[slot * 2 + 1];
    double cnt = (double)count8 * 8.0;
    double mu  = sum / cnt;
    double var = sq / cnt - mu * mu;
    float rs  = rsqrtf((float)var + 1e-5f);
    float fmu = (float)mu;
    for (int i = blockIdx.x * blockDim.x + threadIdx.x; i < count8;
         i += gridDim.x * blockDim.x) {
        float o[8];
#pragma unroll
        for (int q = 0; q < 2; q++) {
            float4 v  = *(const float4*)(buf + i * 8 + q * 4);
            float4 ww = *(const float4*)(w   + i * 8 + q * 4);
            float4 bb = *(const float4*)(b   + i * 8 + q * 4);
            o[q*4+0] = (v.x - fmu) * rs * ww.x + bb.x;
            o[q*4+1] = (v.y - fmu) * rs * ww.y + bb.y;
            o[q*4+2] = (v.z - fmu) * rs * ww.z + bb.z;
            o[q*4+3] = (v.w - fmu) * rs * ww.w + bb.w;
        }
        ohi[i] = f_to_h8(o);
    }
}

// ---------------- final: fused LN3 + dot + sigmoid + symmetric write ----------------
// Warp per pair p (writes out[i,j] AND out[j,i]); extra warps zero the diagonal.
__global__ void k_out(const float* __restrict__ h3, const float* __restrict__ lnw,
                      const float* __restrict__ lnb, const float* __restrict__ w4,
                      const float* __restrict__ b4, float* __restrict__ out)
{
    int gw   = (blockIdx.x * blockDim.x + threadIdx.x) >> 5;
    int lane = threadIdx.x & 31;
    if (gw >= PP) {
        int d = gw - PP;
        if (d < NN && lane == 0) out[d * NN + d] = 0.f;
        return;
    }
    double sum = g_acc[4];
    double sq  = g_acc[5];
    double cnt = (double)PP * (double)H2;
    double mu  = sum / cnt;
    double var = sq / cnt - mu * mu;
    float rs  = rsqrtf((float)var + 1e-5f);
    float fmu = (float)mu;

    const float* hr = h3  + (size_t)gw * H2;
    const float* wr = lnw + (size_t)gw * H2;
    const float* br = lnb + (size_t)gw * H2;
    float s = 0.f;
#pragma unroll
    for (int t = 0; t < H2 / 128; t++) {
        int off = (t * 32 + lane) * 4;
        float4 v  = *(const float4*)(hr + off);
        float4 ww = *(const float4*)(wr + off);
        float4 bb = *(const float4*)(br + off);
        float4 q  = *(const float4*)(w4 + off);
        s += ((v.x - fmu) * rs * ww.x + bb.x) * q.x;
        s += ((v.y - fmu) * rs * ww.y + bb.y) * q.y;
        s += ((v.z - fmu) * rs * ww.z + bb.z) * q.z;
        s += ((v.w - fmu) * rs * ww.w + bb.w) * q.w;
    }
#pragma unroll
    for (int off = 16; off; off >>= 1) s += __shfl_down_sync(0xffffffffu, s, off);
    if (lane == 0) {
        float val = 1.0f / (1.0f + __expf(-(s + b4[0])));
        int i = g_iu[gw], j = g_ju[gw];
        out[i * NN + j] = val;
        out[j * NN + i] = val;
    }
}

// ---------------- host launch ----------------
extern "C" void kernel_launch(void* const* d_in, const int* in_sizes, int n_in,
                              void* d_out, int out_size)
{
    const float* x    = (const float*)d_in[0];
    const float* hid  = (const float*)d_in[1];
    const float* Wih  = (const float*)d_in[2];
    const float* Whh  = (const float*)d_in[3];
    const float* bih  = (const float*)d_in[4];
    const float* bhh  = (const float*)d_in[5];
    const float* W1   = (const float*)d_in[6];
    const float* b1   = (const float*)d_in[7];
    const float* ln1w = (const float*)d_in[8];
    const float* ln1b = (const float*)d_in[9];
    const float* W2   = (const float*)d_in[10];
    const float* b2   = (const float*)d_in[11];
    const float* ln2w = (const float*)d_in[12];
    const float* ln2b = (const float*)d_in[13];
    const float* W3   = (const float*)d_in[14];
    const float* b3   = (const float*)d_in[15];
    const float* ln3w = (const float*)d_in[16];
    const float* ln3b = (const float*)d_in[17];
    const float* W4   = (const float*)d_in[18];
    const float* b4   = (const float*)d_in[19];
    float* out = (float*)d_out;

    float *p_gi, *p_gh, *p_y;
    __half *p_ahi, *p_bWhh, *p_bW1, *p_bW2, *p_bW3;
    cudaGetSymbolAddress((void**)&p_gi,   g_gi);
    cudaGetSymbolAddress((void**)&p_gh,   g_gh);
    cudaGetSymbolAddress((void**)&p_y,    g_y);
    cudaGetSymbolAddress((void**)&p_ahi,  g_ahi);
    cudaGetSymbolAddress((void**)&p_bWhh, g_bWhh);
    cudaGetSymbolAddress((void**)&p_bW1,  g_bW1);
    cudaGetSymbolAddress((void**)&p_bW2,  g_bW2);
    cudaGetSymbolAddress((void**)&p_bW3,  g_bW3);
    __half* p_ghh = (__half*)p_gh;         // fp16 view of gate buffer
    float* p_t  = p_gh;                    // [PP, H2]  (gates dead after GRU)
    float* p_t2 = p_gh + (size_t)PP * H2;  // [PP, H2]

    cudaFuncSetAttribute(k_bgemm<false, -1, true>, cudaFuncAttributeMaxDynamicSharedMemorySize, GSMEM);
    cudaFuncSetAttribute(k_bgemm<true, 0, false>,  cudaFuncAttributeMaxDynamicSharedMemorySize, GSMEM);
    cudaFuncSetAttribute(k_bgemm<true, 1, false>,  cudaFuncAttributeMaxDynamicSharedMemorySize, GSMEM);
    cudaFuncSetAttribute(k_bgemm<true, 2, false>,  cudaFuncAttributeMaxDynamicSharedMemorySize, GSMEM);

    const int MB = (PP + 127) / 128;  // 28
    const int GRU_G = (PP * (HSZ / 8) + 255) / 256;

    // 0) fused init + all weight converts (single node)
    k_convall<<<(N8_ALL + 255) / 256, 256>>>((const float4*)Whh, (const float4*)W1,
                                             (const float4*)W2, (const float4*)W3);

    // 1) gi_node = x @ Wih^T + bih  [84, 6144], K=64 (tiny, f32 path)
    k_gemm<false, -1><<<dim3(G3H / 128, 1), 256>>>(x, Wih, bih, p_gi, NN, G3H, 64);

    // 2) GRU step 1 (fp16 gates out; h1 kept only in fp16 g_ahi)
    k_conva8<<<(PP * HSZ / 8 + 255) / 256, 256>>>((const float4*)hid, (uint4*)p_ahi, PP * HSZ / 8);
    k_bgemm<false, -1, true><<<dim3(G3H / 128, MB), 128, GSMEM>>>(
        p_ahi, p_bWhh, bhh, p_ghh, PP, G3H, HSZ);
    k_gru<0><<<GRU_G, 256>>>(hid, p_ghh, (uint4*)p_ahi);

    // 3) GRU step 2 (reads h1 fp16 from g_ahi in place)
    k_bgemm<false, -1, true><<<dim3(G3H / 128, MB), 128, GSMEM>>>(
        p_ahi, p_bWhh, bhh, p_ghh, PP, G3H, HSZ);
    k_gru<1><<<GRU_G, 256>>>(hid, p_ghh, (uint4*)p_ahi);

    // 4) layer 1 + LN
    k_bgemm<true, 0, false><<<dim3(HSZ / 128, MB), 128, GSMEM>>>(
        p_ahi, p_bW1, b1, p_y, PP, HSZ, HSZ);
    k_norm<<<2048, 256>>>(p_y, ln1w, ln1b, PP * HSZ / 8, 0, (uint4*)p_ahi);

    // 5) layer 2 + LN
    k_bgemm<true, 1, false><<<dim3(H2 / 128, MB), 128, GSMEM>>>(
        p_ahi, p_bW2, b2, p_t, PP, H2, HSZ);
    k_norm<<<2048, 256>>>(p_t, ln2w, ln2b, PP * H2 / 8, 1, (uint4*)p_ahi);

    // 6) layer 3 (raw f32 out; LN fused into k_out)
    k_bgemm<true, 2, false><<<dim3(H2 / 128, MB), 128, GSMEM>>>(
        p_ahi, p_bW3, b3, p_t2, PP, H2, H2);

    // 7) output: fused LN3 + dot + sigmoid + symmetric scatter
    k_out<<<((PP + NN) * 32 + 255) / 256, 256>>>(p_t2, ln3w, ln3b, W4, b4, out);
}

// round 16
// speedup vs baseline: 2.7594x; 1.0066x over previous
#include <cuda_runtime.h>
#include <cuda_fp16.h>
#include <stdint.h>

// ---------------- problem constants ----------------
#define NN   84
#define PP   3486
#define HSZ  2048
#define H2   1024
#define G3H  6144

// ---------------- device scratch ----------------
__device__ float g_gi[NN * G3H];
__device__ float g_gh[PP * G3H];      // GRU: fp16 view [PP,3H]; later f32 t/t2
__device__ float g_y [PP * HSZ];
__device__ double g_acc[6];
__device__ int   g_iu[PP];
__device__ int   g_ju[PP];
__device__ __half g_ahi[PP * HSZ];    // activation fp16 (doubles as hidden-state carry)
__device__ __half g_bWhh[G3H * HSZ];  // weight fp16 buffers (converted once upfront)
__device__ __half g_bW1[HSZ * HSZ];
__device__ __half g_bW2[H2 * HSZ];
__device__ __half g_bW3[H2 * H2];

// fast, overflow-safe activations
__device__ __forceinline__ float sigm_f(float x) {
    return 1.0f / (1.0f + __expf(-x));
}
__device__ __forceinline__ float tanh_f(float x) {
    float e = __expf(-2.0f * fabsf(x));
    float t = (1.0f - e) / (1.0f + e);
    return copysignf(t, x);
}

__device__ __forceinline__ uint32_t s2u(const void* p) {
    uint32_t a;
    asm("{ .reg .u64 t; cvta.to.shared.u64 t, %1; cvt.u32.u64 %0, t; }" : "=r"(a) : "l"(p));
    return a;
}

// 8 halves (uint4) -> 8 floats
__device__ __forceinline__ void h8_to_f(uint4 v, float* o) {
    float2 f;
    f = __half22float2(*(__half2*)&v.x); o[0] = f.x; o[1] = f.y;
    f = __half22float2(*(__half2*)&v.y); o[2] = f.x; o[3] = f.y;
    f = __half22float2(*(__half2*)&v.z); o[4] = f.x; o[5] = f.y;
    f = __half22float2(*(__half2*)&v.w); o[6] = f.x; o[7] = f.y;
}
// 8 floats -> uint4 of halves
__device__ __forceinline__ uint4 f_to_h8(const float* o) {
    union { __half2 h[4]; uint4 u; } r;
    r.h[0] = __floats2half2_rn(o[0], o[1]);
    r.h[1] = __floats2half2_rn(o[2], o[3]);
    r.h[2] = __floats2half2_rn(o[4], o[5]);
    r.h[3] = __floats2half2_rn(o[6], o[7]);
    return r.u;
}
__device__ __forceinline__ void conv8(const float4* __restrict__ in,
                                      uint4* __restrict__ out, int i8) {
    float4 a = in[i8 * 2], b = in[i8 * 2 + 1];
    float o[8] = {a.x, a.y, a.z, a.w, b.x, b.y, b.z, b.w};
    out[i8] = f_to_h8(o);
}

// ---------------- packed f32x2 helpers (for small f32 GEMM) ----------------
__device__ __forceinline__ unsigned long long pk2(float lo, float hi) {
    unsigned long long r;
    asm("mov.b64 %0, {%1, %2};" : "=l"(r) : "f"(lo), "f"(hi));
    return r;
}
__device__ __forceinline__ void fma2(unsigned long long& d,
                                     unsigned long long a, unsigned long long b) {
    asm("fma.rn.f32x2 %0, %1, %2, %0;" : "+l"(d) : "l"(a), "l"(b));
}
__device__ __forceinline__ float2 unpk2(unsigned long long v) {
    float lo, hi;
    asm("mov.b64 {%0, %1}, %2;" : "=f"(lo), "=f"(hi) : "l"(v));
    return make_float2(lo, hi);
}

// ---------------- one-shot init + weight converts (fused) ----------------
#define N8_WHH  (G3H * HSZ / 8)             // 1572864
#define N8_W1   (HSZ * HSZ / 8)             // 524288
#define N8_W2   (H2 * HSZ / 8)              // 262144
#define N8_W3   (H2 * H2 / 8)               // 131072
#define N8_ALL  (N8_WHH + N8_W1 + N8_W2 + N8_W3)

__global__ void k_convall(const float4* __restrict__ Whh, const float4* __restrict__ W1,
                          const float4* __restrict__ W2, const float4* __restrict__ W3)
{
    int i = blockIdx.x * blockDim.x + threadIdx.x;
    // fused init (indices < NN*NN = 7056 << N8_ALL)
    if (i < 6) g_acc[i] = 0.0;
    if (i < NN * NN) {
        int r = i / NN, c = i % NN;
        if (c > r) {
            int p = r * (NN - 1) - r * (r - 1) / 2 + (c - r - 1);
            g_iu[p] = r;
            g_ju[p] = c;
        }
    }
    if (i < N8_WHH) {
        conv8(Whh, (uint4*)g_bWhh, i);
    } else if (i < N8_WHH + N8_W1) {
        conv8(W1, (uint4*)g_bW1, i - N8_WHH);
    } else if (i < N8_WHH + N8_W1 + N8_W2) {
        conv8(W2, (uint4*)g_bW2, i - N8_WHH - N8_W1);
    } else if (i < N8_ALL) {
        conv8(W3, (uint4*)g_bW3, i - N8_WHH - N8_W1 - N8_W2);
    }
}

// ---------------- activation convert (8 elems/thread) ----------------
__global__ void k_conva8(const float4* __restrict__ in, uint4* __restrict__ hi, int n8) {
    int i = blockIdx.x * blockDim.x + threadIdx.x;
    if (i < n8) conv8(in, hi, i);
}

// ================= fp16 single-pass mma.sync GEMM =================
// C[M,N] = A[M,K] @ B[N,K]^T + bias.  OUTH: store fp16 output (GRU gates).
// CTA 128(M)x128(N), BK=32, 128 threads, warp grid 2(M) x 2(N), warp tile 64x64.
// 3-stage cp.async ring, ONE __syncthreads per K-tile iteration.
// __launch_bounds__(128, 3): cap regs at 170 so 3 CTAs/SM fit the register file.
#define LDB          80
#define MAT_BYTES    (128 * LDB)      // 10240
#define OFF_B        MAT_BYTES        // 10240
#define STAGE_BYTES  (2 * MAT_BYTES)  // 20480
#define NSTAGE       3
#define GSMEM        (NSTAGE * STAGE_BYTES)   // 61440

#define LDSM4(R, A) \
    asm volatile("ldmatrix.sync.aligned.m8n8.x4.shared.b16 {%0,%1,%2,%3}, [%4];" \
        : "=r"((R)[0]), "=r"((R)[1]), "=r"((R)[2]), "=r"((R)[3]) : "r"(A))
#define LDSM4P(R0, R1, A) \
    asm volatile("ldmatrix.sync.aligned.m8n8.x4.shared.b16 {%0,%1,%2,%3}, [%4];" \
        : "=r"((R0)[0]), "=r"((R0)[1]), "=r"((R1)[0]), "=r"((R1)[1]) : "r"(A))
#define MMA(D, Aa, Bb) \
    asm volatile("mma.sync.aligned.m16n8k16.row.col.f32.f16.f16.f32 " \
        "{%0,%1,%2,%3},{%4,%5,%6,%7},{%8,%9},{%0,%1,%2,%3};" \
        : "+f"((D)[0]), "+f"((D)[1]), "+f"((D)[2]), "+f"((D)[3]) \
        : "r"((Aa)[0]), "r"((Aa)[1]), "r"((Aa)[2]), "r"((Aa)[3]), \
          "r"((Bb)[0]), "r"((Bb)[1]))

__device__ __forceinline__ void g_issue(
    uint32_t sbase, int s,
    const __half* Ahi, const __half* Bhi,
    int m0, int n0, int M, int K, int kt, int tid)
{
    const uint32_t stg = sbase + s * STAGE_BYTES;
#pragma unroll
    for (int i = 0; i < 4; i++) {
        int cid = tid + i * 128;
        int r   = cid >> 2;
        int ch  = cid & 3;
        int row = m0 + r;
        int sz  = (row < M) ? 16 : 0;
        if (row >= M) row = M - 1;
        const __half* gp = Ahi + (size_t)row * K + kt * 32 + ch * 8;
        uint32_t sa = stg + r * LDB + ch * 16;
        asm volatile("cp.async.cg.shared.global [%0], [%1], 16, %2;"
                     :: "r"(sa), "l"(gp), "r"(sz));
    }
#pragma unroll
    for (int i = 0; i < 4; i++) {
        int cid = tid + i * 128;
        int r   = cid >> 2;
        int ch  = cid & 3;
        const __half* gp = Bhi + (size_t)(n0 + r) * K + kt * 32 + ch * 8;
        uint32_t sa = stg + OFF_B + r * LDB + ch * 16;
        asm volatile("cp.async.ca.shared.global [%0], [%1], 16;"
                     :: "r"(sa), "l"(gp));
    }
}

template <bool RELU, int SLOT, bool OUTH>
__global__ __launch_bounds__(128, 3)
void k_bgemm(const __half* __restrict__ Ahi, const __half* __restrict__ Bhi,
             const float* __restrict__ bias, void* __restrict__ Cv,
             int M, int N, int K)
{
    extern __shared__ char smem[];
    const uint32_t sbase = s2u(smem);
    const int tid  = threadIdx.x;
    const int wid  = tid >> 5;
    const int lane = tid & 31;
    const int m0 = blockIdx.y * 128;
    const int n0 = blockIdx.x * 128;
    const int wm = wid & 1;
    const int wn = wid >> 1;

    float acc[4][8][4];
#pragma unroll
    for (int a = 0; a < 4; a++)
#pragma unroll
        for (int b = 0; b < 8; b++)
#pragma unroll
            for (int c = 0; c < 4; c++) acc[a][b][c] = 0.f;

    const int NKT = K >> 5;

    g_issue(sbase, 0, Ahi, Bhi, m0, n0, M, K, 0, tid);
    asm volatile("cp.async.commit_group;" ::: "memory");
    g_issue(sbase, 1, Ahi, Bhi, m0, n0, M, K, 1, tid);
    asm volatile("cp.async.commit_group;" ::: "memory");

    const uint32_t a_lane = (uint32_t)((wm * 64 + (lane & 15)) * LDB + (lane >> 4) * 16);
    const uint32_t b_lane = (uint32_t)(OFF_B + (wn * 64 + (lane >> 4) * 8 + (lane & 7)) * LDB
                                       + ((lane >> 3) & 1) * 16);

    for (int kt = 0; kt < NKT; kt++) {
        asm volatile("cp.async.wait_group 1;" ::: "memory");
        __syncthreads();
        if (kt + 2 < NKT)
            g_issue(sbase, (kt + 2) % NSTAGE, Ahi, Bhi, m0, n0, M, K, kt + 2, tid);
        asm volatile("cp.async.commit_group;" ::: "memory");

        const uint32_t sb = sbase + (kt % NSTAGE) * STAGE_BYTES;
#pragma unroll
        for (int k16 = 0; k16 < 2; k16++) {
            uint32_t ah[4][4];
#pragma unroll
            for (int mt = 0; mt < 4; mt++) {
                uint32_t aadr = sb + a_lane + mt * (16 * LDB) + k16 * 32;
                LDSM4(ah[mt], aadr);
            }
            uint32_t bh[8][2];
#pragma unroll
            for (int ntb = 0; ntb < 8; ntb += 2) {
                uint32_t badr = sb + b_lane + ntb * (8 * LDB) + k16 * 32;
                LDSM4P(bh[ntb], bh[ntb + 1], badr);
            }
#pragma unroll
            for (int mt = 0; mt < 4; mt++)
#pragma unroll
                for (int nt = 0; nt < 8; nt++)
                    MMA(acc[mt][nt], ah[mt], bh[nt]);
        }
    }

    // ---------------- epilogue ----------------
    double lsum = 0.0, lsq = 0.0;
    const int rb = m0 + wm * 64 + (lane >> 2);
    const int cb = n0 + wn * 64 + (lane & 3) * 2;
#pragma unroll
    for (int mt = 0; mt < 4; mt++) {
#pragma unroll
        for (int half = 0; half < 2; half++) {
            int r = rb + mt * 16 + half * 8;
            if (r < M) {
#pragma unroll
                for (int nt = 0; nt < 8; nt++) {
                    int c = cb + nt * 8;
                    float v0 = acc[mt][nt][half * 2]     + bias[c];
                    float v1 = acc[mt][nt][half * 2 + 1] + bias[c + 1];
                    if (RELU) { v0 = fmaxf(v0, 0.f); v1 = fmaxf(v1, 0.f); }
                    if (OUTH) {
                        __half* crow = (__half*)Cv + (size_t)r * N;
                        *(__half2*)(crow + c) = __floats2half2_rn(v0, v1);
                    } else {
                        float* crow = (float*)Cv + (size_t)r * N;
                        *(float2*)(crow + c) = make_float2(v0, v1);
                    }
                    if (SLOT >= 0) {
                        lsum += (double)v0 + (double)v1;
                        lsq  += (double)v0 * v0 + (double)v1 * v1;
                    }
                }
            }
        }
    }
    if (SLOT >= 0) {
#pragma unroll
        for (int off = 16; off; off >>= 1) {
            lsum += __shfl_down_sync(0xffffffffu, lsum, off);
            lsq  += __shfl_down_sync(0xffffffffu, lsq,  off);
        }
        if (lane == 0) {
            atomicAdd(&g_acc[SLOT * 2],     lsum);
            atomicAdd(&g_acc[SLOT * 2 + 1], lsq);
        }
    }
}

// ---------------- f32 SGEMM (small; GEMM1 only) ----------------
template <bool RELU, int SLOT>
__global__ __launch_bounds__(256)
void k_gemm(const float* __restrict__ A, const float* __restrict__ B,
            const float* __restrict__ bias, float* __restrict__ C,
            int M, int N, int K)
{
    __shared__ float As[16][132];
    __shared__ float Bs[16][132];
    const int tid = threadIdx.x;
    const int tx  = tid & 15;
    const int ty  = tid >> 4;
    const int m0  = blockIdx.y * 128;
    const int n0  = blockIdx.x * 128;

    unsigned long long acc[8][4];
#pragma unroll
    for (int i = 0; i < 8; i++)
#pragma unroll
        for (int j = 0; j < 4; j++) acc[i][j] = 0ULL;

    for (int kt = 0; kt < K; kt += 16) {
        __syncthreads();
#pragma unroll
        for (int q = 0; q < 2; q++) {
            int fi  = tid + q * 256;
            int row = fi >> 2;
            int kq  = fi & 3;
            float4 av = make_float4(0.f, 0.f, 0.f, 0.f);
            int gr = m0 + row;
            if (gr < M)
                av = *(const float4*)(A + (size_t)gr * K + kt + kq * 4);
            As[kq * 4 + 0][row] = av.x;
            As[kq * 4 + 1][row] = av.y;
            As[kq * 4 + 2][row] = av.z;
            As[kq * 4 + 3][row] = av.w;
            float4 bv = *(const float4*)(B + (size_t)(n0 + row) * K + kt + kq * 4);
            Bs[kq * 4 + 0][row] = bv.x;
            Bs[kq * 4 + 1][row] = bv.y;
            Bs[kq * 4 + 2][row] = bv.z;
            Bs[kq * 4 + 3][row] = bv.w;
        }
        __syncthreads();
#pragma unroll
        for (int kk = 0; kk < 16; kk++) {
            float4 a0 = *(const float4*)&As[kk][ty * 8];
            float4 a1 = *(const float4*)&As[kk][ty * 8 + 4];
            float4 b0 = *(const float4*)&Bs[kk][tx * 8];
            float4 b1 = *(const float4*)&Bs[kk][tx * 8 + 4];
            unsigned long long bp0 = pk2(b0.x, b0.y);
            unsigned long long bp1 = pk2(b0.z, b0.w);
            unsigned long long bp2 = pk2(b1.x, b1.y);
            unsigned long long bp3 = pk2(b1.z, b1.w);
            float av[8] = {a0.x, a0.y, a0.z, a0.w, a1.x, a1.y, a1.z, a1.w};
#pragma unroll
            for (int i = 0; i < 8; i++) {
                unsigned long long ap = pk2(av[i], av[i]);
                fma2(acc[i][0], ap, bp0);
                fma2(acc[i][1], ap, bp1);
                fma2(acc[i][2], ap, bp2);
                fma2(acc[i][3], ap, bp3);
            }
        }
    }
#pragma unroll
    for (int i = 0; i < 8; i++) {
        int r = m0 + ty * 8 + i;
        if (r < M) {
            float* crow = C + (size_t)r * N + n0 + tx * 8;
            const float* brow = bias + n0 + tx * 8;
#pragma unroll
            for (int j2 = 0; j2 < 4; j2++) {
                float2 v = unpk2(acc[i][j2]);
                float c0 = v.x + brow[j2 * 2];
                float c1 = v.y + brow[j2 * 2 + 1];
                if (RELU) { c0 = fmaxf(c0, 0.f); c1 = fmaxf(c1, 0.f); }
                crow[j2 * 2]     = c0;
                crow[j2 * 2 + 1] = c1;
            }
        }
    }
}

// ---------------- GRU elementwise combine, 8 elems/thread ----------------
// STEP 0: hin from f32 `hid` input.  STEP 1: hin from fp16 g_ahi (in-place).
template <int STEP>
__global__ void k_gru(const float* __restrict__ hin32, const __half* __restrict__ ghh,
                      uint4* __restrict__ ohi)
{
    int idx = blockIdx.x * blockDim.x + threadIdx.x;    // over PP * (HSZ/8)
    if (idx >= PP * (HSZ / 8)) return;
    int p = idx >> 8;              // /(HSZ/8)=256
    int j = (idx & 255) * 8;
    int node = (STEP == 0) ? g_iu[p] : g_ju[p];
    const float* gi = g_gi + (size_t)node * G3H;
    const __half* gh = ghh + (size_t)p * G3H;

    float gr[8], gz[8], gn[8], hr[8], hz[8], hn[8], hv[8], o[8];
    {
        float4 a, b;
        a = *(const float4*)(gi + j);           b = *(const float4*)(gi + j + 4);
        gr[0]=a.x; gr[1]=a.y; gr[2]=a.z; gr[3]=a.w; gr[4]=b.x; gr[5]=b.y; gr[6]=b.z; gr[7]=b.w;
        a = *(const float4*)(gi + j + HSZ);     b = *(const float4*)(gi + j + HSZ + 4);
        gz[0]=a.x; gz[1]=a.y; gz[2]=a.z; gz[3]=a.w; gz[4]=b.x; gz[5]=b.y; gz[6]=b.z; gz[7]=b.w;
        a = *(const float4*)(gi + j + 2*HSZ);   b = *(const float4*)(gi + j + 2*HSZ + 4);
        gn[0]=a.x; gn[1]=a.y; gn[2]=a.z; gn[3]=a.w; gn[4]=b.x; gn[5]=b.y; gn[6]=b.z; gn[7]=b.w;
    }
    h8_to_f(*(const uint4*)(gh + j),           hr);
    h8_to_f(*(const uint4*)(gh + j + HSZ),     hz);
    h8_to_f(*(const uint4*)(gh + j + 2 * HSZ), hn);
    if (STEP == 0) {
        float4 a = *(const float4*)(hin32 + (size_t)p * HSZ + j);
        float4 b = *(const float4*)(hin32 + (size_t)p * HSZ + j + 4);
        hv[0]=a.x; hv[1]=a.y; hv[2]=a.z; hv[3]=a.w; hv[4]=b.x; hv[5]=b.y; hv[6]=b.z; hv[7]=b.w;
    } else {
        h8_to_f(ohi[idx], hv);
    }
#pragma unroll
    for (int e = 0; e < 8; e++) {
        float r = sigm_f(gr[e] + hr[e]);
        float z = sigm_f(gz[e] + hz[e]);
        float n = tanh_f(gn[e] + r * hn[e]);
        o[e] = (1.f - z) * n + z * hv[e];
    }
    ohi[idx] = f_to_h8(o);
}

// ---------------- full-tensor LayerNorm apply, 8 elems/thread ----------------
__global__ void k_norm(const float* __restrict__ buf, const float* __restrict__ w,
                       const float* __restrict__ b, int count8, int slot,
                       uint4* __restrict__ ohi)
{
    double sum = g_acc[slot * 2];
    double sq  = g_acc[slot * 2 + 1];
    double cnt = (double)count8 * 8.0;
    double mu  = sum / cnt;
    double var = sq / cnt - mu * mu;
    float rs  = rsqrtf((float)var + 1e-5f);
    float fmu = (float)mu;
    for (int i = blockIdx.x * blockDim.x + threadIdx.x; i < count8;
         i += gridDim.x * blockDim.x) {
        float o[8];
#pragma unroll
        for (int q = 0; q < 2; q++) {
            float4 v  = *(const float4*)(buf + i * 8 + q * 4);
            float4 ww = *(const float4*)(w   + i * 8 + q * 4);
            float4 bb = *(const float4*)(b   + i * 8 + q * 4);
            o[q*4+0] = (v.x - fmu) * rs * ww.x + bb.x;
            o[q*4+1] = (v.y - fmu) * rs * ww.y + bb.y;
            o[q*4+2] = (v.z - fmu) * rs * ww.z + bb.z;
            o[q*4+3] = (v.w - fmu) * rs * ww.w + bb.w;
        }
        ohi[i] = f_to_h8(o);
    }
}

// ---------------- final: fused LN3 + dot + sigmoid + symmetric write ----------------
__global__ void k_out(const float* __restrict__ h3, const float* __restrict__ lnw,
                      const float* __restrict__ lnb, const float* __restrict__ w4,
                      const float* __restrict__ b4, float* __restrict__ out)
{
    int gw   = (blockIdx.x * blockDim.x + threadIdx.x) >> 5;
    int lane = threadIdx.x & 31;
    if (gw >= PP) {
        int d = gw - PP;
        if (d < NN && lane == 0) out[d * NN + d] = 0.f;
        return;
    }
    double sum = g_acc[4];
    double sq  = g_acc[5];
    double cnt = (double)PP * (double)H2;
    double mu  = sum / cnt;
    double var = sq / cnt - mu * mu;
    float rs  = rsqrtf((float)var + 1e-5f);
    float fmu = (float)mu;

    const float* hr = h3  + (size_t)gw * H2;
    const float* wr = lnw + (size_t)gw * H2;
    const float* br = lnb + (size_t)gw * H2;
    float s = 0.f;
#pragma unroll
    for (int t = 0; t < H2 / 128; t++) {
        int off = (t * 32 + lane) * 4;
        float4 v  = *(const float4*)(hr + off);
        float4 ww = *(const float4*)(wr + off);
        float4 bb = *(const float4*)(br + off);
        float4 q  = *(const float4*)(w4 + off);
        s += ((v.x - fmu) * rs * ww.x + bb.x) * q.x;
        s += ((v.y - fmu) * rs * ww.y + bb.y) * q.y;
        s += ((v.z - fmu) * rs * ww.z + bb.z) * q.z;
        s += ((v.w - fmu) * rs * ww.w + bb.w) * q.w;
    }
#pragma unroll
    for (int off = 16; off; off >>= 1) s += __shfl_down_sync(0xffffffffu, s, off);
    if (lane == 0) {
        float val = 1.0f / (1.0f + __expf(-(s + b4[0])));
        int i = g_iu[gw], j = g_ju[gw];
        out[i * NN + j] = val;
        out[j * NN + i] = val;
    }
}

// ---------------- host launch ----------------
extern "C" void kernel_launch(void* const* d_in, const int* in_sizes, int n_in,
                              void* d_out, int out_size)
{
    const float* x    = (const float*)d_in[0];
    const float* hid  = (const float*)d_in[1];
    const float* Wih  = (const float*)d_in[2];
    const float* Whh  = (const float*)d_in[3];
    const float* bih  = (const float*)d_in[4];
    const float* bhh  = (const float*)d_in[5];
    const float* W1   = (const float*)d_in[6];
    const float* b1   = (const float*)d_in[7];
    const float* ln1w = (const float*)d_in[8];
    const float* ln1b = (const float*)d_in[9];
    const float* W2   = (const float*)d_in[10];
    const float* b2   = (const float*)d_in[11];
    const float* ln2w = (const float*)d_in[12];
    const float* ln2b = (const float*)d_in[13];
    const float* W3   = (const float*)d_in[14];
    const float* b3   = (const float*)d_in[15];
    const float* ln3w = (const float*)d_in[16];
    const float* ln3b = (const float*)d_in[17];
    const float* W4   = (const float*)d_in[18];
    const float* b4   = (const float*)d_in[19];
    float* out = (float*)d_out;

    float *p_gi, *p_gh, *p_y;
    __half *p_ahi, *p_bWhh, *p_bW1, *p_bW2, *p_bW3;
    cudaGetSymbolAddress((void**)&p_gi,   g_gi);
    cudaGetSymbolAddress((void**)&p_gh,   g_gh);
    cudaGetSymbolAddress((void**)&p_y,    g_y);
    cudaGetSymbolAddress((void**)&p_ahi,  g_ahi);
    cudaGetSymbolAddress((void**)&p_bWhh, g_bWhh);
    cudaGetSymbolAddress((void**)&p_bW1,  g_bW1);
    cudaGetSymbolAddress((void**)&p_bW2,  g_bW2);
    cudaGetSymbolAddress((void**)&p_bW3,  g_bW3);
    __half* p_ghh = (__half*)p_gh;         // fp16 view of gate buffer
    float* p_t  = p_gh;                    // [PP, H2]  (gates dead after GRU)
    float* p_t2 = p_gh + (size_t)PP * H2;  // [PP, H2]

    cudaFuncSetAttribute(k_bgemm<false, -1, true>, cudaFuncAttributeMaxDynamicSharedMemorySize, GSMEM);
    cudaFuncSetAttribute(k_bgemm<true, 0, false>,  cudaFuncAttributeMaxDynamicSharedMemorySize, GSMEM);
    cudaFuncSetAttribute(k_bgemm<true, 1, false>,  cudaFuncAttributeMaxDynamicSharedMemorySize, GSMEM);
    cudaFuncSetAttribute(k_bgemm<true, 2, false>,  cudaFuncAttributeMaxDynamicSharedMemorySize, GSMEM);

    const int MB = (PP + 127) / 128;  // 28
    const int GRU_G = (PP * (HSZ / 8) + 255) / 256;

    // 0) fused init + all weight converts (single node)
    k_convall<<<(N8_ALL + 255) / 256, 256>>>((const float4*)Whh, (const float4*)W1,
                                             (const float4*)W2, (const float4*)W3);

    // 1) gi_node = x @ Wih^T + bih  [84, 6144], K=64 (tiny, f32 path)
    k_gemm<false, -1><<<dim3(G3H / 128, 1), 256>>>(x, Wih, bih, p_gi, NN, G3H, 64);

    // 2) GRU step 1 (fp16 gates out; h1 kept only in fp16 g_ahi)
    k_conva8<<<(PP * HSZ / 8 + 255) / 256, 256>>>((const float4*)hid, (uint4*)p_ahi, PP * HSZ / 8);
    k_bgemm<false, -1, true><<<dim3(G3H / 128, MB), 128, GSMEM>>>(
        p_ahi, p_bWhh, bhh, p_ghh, PP, G3H, HSZ);
    k_gru<0><<<GRU_G, 256>>>(hid, p_ghh, (uint4*)p_ahi);

    // 3) GRU step 2 (reads h1 fp16 from g_ahi in place)
    k_bgemm<false, -1, true><<<dim3(G3H / 128, MB), 128, GSMEM>>>(
        p_ahi, p_bWhh, bhh, p_ghh, PP, G3H, HSZ);
    k_gru<1><<<GRU_G, 256>>>(hid, p_ghh, (uint4*)p_ahi);

    // 4) layer 1 + LN
    k_bgemm<true, 0, false><<<dim3(HSZ / 128, MB), 128, GSMEM>>>(
        p_ahi, p_bW1, b1, p_y, PP, HSZ, HSZ);
    k_norm<<<2048, 256>>>(p_y, ln1w, ln1b, PP * HSZ / 8, 0, (uint4*)p_ahi);

    // 5) layer 2 + LN
    k_bgemm<true, 1, false><<<dim3(H2 / 128, MB), 128, GSMEM>>>(
        p_ahi, p_bW2, b2, p_t, PP, H2, HSZ);
    k_norm<<<2048, 256>>>(p_t, ln2w, ln2b, PP * H2 / 8, 1, (uint4*)p_ahi);

    // 6) layer 3 (raw f32 out; LN fused into k_out)
    k_bgemm<true, 2, false><<<dim3(H2 / 128, MB), 128, GSMEM>>>(
        p_ahi, p_bW3, b3, p_t2, PP, H2, H2);

    // 7) output: fused LN3 + dot + sigmoid + symmetric scatter
    k_out<<<((PP + NN) * 32 + 255) / 256, 256>>>(p_t2, ln3w, ln3b, W4, b4, out);
}